// round 1
// baseline (speedup 1.0000x reference)
#include <cuda_runtime.h>
#include <cstdint>
#include <cstddef>

// Problem constants (fixed shapes from reference)
#define BB   8
#define CC   512
#define LL   4096
#define HID  512
#define NH   8
#define DH   64
#define EPSV 1e-5f
#define SCALEV 0.125f   // 64^-0.5

// ---------------- scratch (device globals; no allocations allowed) ----------
__device__ float g_xn  [(size_t)BB * CC * LL];        // 64 MB  normalized x
__device__ float g_qkv [(size_t)BB * 3 * HID * LL];   // 192 MB qkv
__device__ float g_ctx [(size_t)BB * NH * DH * DH];   // 1 MB   context
__device__ float g_attn[(size_t)BB * HID * LL];       // 64 MB  attention out

// ---------------- 1) LayerNorm over channel dim ----------------------------
__global__ void ln_kernel(const float* __restrict__ x,
                          const float* __restrict__ gamma,
                          const float* __restrict__ beta,
                          float* __restrict__ xn)
{
    int l = blockIdx.x * blockDim.x + threadIdx.x;   // 0..LL-1
    int b = blockIdx.y;
    const float* xp = x  + (size_t)b * CC * LL + l;
    float*       op = xn + (size_t)b * CC * LL + l;

    float s = 0.f, ss = 0.f;
    #pragma unroll 8
    for (int c = 0; c < CC; c++) {
        float v = xp[(size_t)c * LL];
        s += v; ss += v * v;
    }
    float mean = s * (1.0f / CC);
    float var  = ss * (1.0f / CC) - mean * mean;
    float rstd = rsqrtf(var + EPSV);

    #pragma unroll 8
    for (int c = 0; c < CC; c++) {
        float v = xp[(size_t)c * LL];
        op[(size_t)c * LL] = (v - mean) * rstd * gamma[c] + beta[c];
    }
}

// ---------------- 2,6) SGEMM: C[z] = A @ B[z] (+ bias + residual) ----------
// A: [M,K] row-major (shared across batch). B: [K,N] row-major, C: [M,N].
// BM=BN=128, BK=16, 256 threads, 8x8 microtile per thread.
template <bool EPI>
__global__ __launch_bounds__(256)
void sgemm_kernel(const float* __restrict__ A, const float* __restrict__ Bm,
                  float* __restrict__ Cm, int M, int N, int K,
                  size_t strideB, size_t strideC,
                  const float* __restrict__ bias,
                  const float* __restrict__ res, size_t strideR)
{
    __shared__ float As[16][132];   // padded: conflict-free transposed stores
    __shared__ float Bs[16][128];

    const int tid = threadIdx.x;
    const int bx = blockIdx.x, by = blockIdx.y, bz = blockIdx.z;

    const float* Ab = A  + (size_t)by * 128 * K;
    const float* Bb = Bm + (size_t)bz * strideB + (size_t)bx * 128;

    const int ty = tid >> 4;          // 0..15 -> row group (8 rows)
    const int tx = tid & 15;          // 0..15 -> col group (8 cols)

    float acc[8][8];
    #pragma unroll
    for (int i = 0; i < 8; i++)
        #pragma unroll
        for (int j = 0; j < 8; j++) acc[i][j] = 0.f;

    for (int k0 = 0; k0 < K; k0 += 16) {
        // load A tile (128x16, transposed into As) and B tile (16x128)
        #pragma unroll
        for (int it = 0; it < 2; it++) {
            int f = tid + it * 256;               // 0..511 (float4 index)
            int ar = f >> 2, ac = (f & 3) * 4;
            float4 av = *reinterpret_cast<const float4*>(Ab + (size_t)ar * K + k0 + ac);
            As[ac + 0][ar] = av.x; As[ac + 1][ar] = av.y;
            As[ac + 2][ar] = av.z; As[ac + 3][ar] = av.w;

            int br = f >> 5, bc = (f & 31) * 4;
            float4 bv = *reinterpret_cast<const float4*>(Bb + (size_t)(k0 + br) * N + bc);
            *reinterpret_cast<float4*>(&Bs[br][bc]) = bv;
        }
        __syncthreads();

        #pragma unroll
        for (int k = 0; k < 16; k++) {
            float af[8], bf[8];
            float4 a0 = *reinterpret_cast<const float4*>(&As[k][ty * 8]);
            float4 a1 = *reinterpret_cast<const float4*>(&As[k][ty * 8 + 4]);
            float4 b0 = *reinterpret_cast<const float4*>(&Bs[k][tx * 8]);
            float4 b1 = *reinterpret_cast<const float4*>(&Bs[k][tx * 8 + 4]);
            af[0]=a0.x; af[1]=a0.y; af[2]=a0.z; af[3]=a0.w;
            af[4]=a1.x; af[5]=a1.y; af[6]=a1.z; af[7]=a1.w;
            bf[0]=b0.x; bf[1]=b0.y; bf[2]=b0.z; bf[3]=b0.w;
            bf[4]=b1.x; bf[5]=b1.y; bf[6]=b1.z; bf[7]=b1.w;
            #pragma unroll
            for (int i = 0; i < 8; i++)
                #pragma unroll
                for (int j = 0; j < 8; j++)
                    acc[i][j] = fmaf(af[i], bf[j], acc[i][j]);
        }
        __syncthreads();
    }

    // write back (float4), optional bias + residual epilogue
    #pragma unroll
    for (int i = 0; i < 8; i++) {
        int row = by * 128 + ty * 8 + i;
        size_t off = (size_t)bz * strideC + (size_t)row * N + (size_t)bx * 128 + tx * 8;
        float bv = EPI ? bias[row] : 0.f;
        #pragma unroll
        for (int h = 0; h < 2; h++) {
            float4 v;
            v.x = acc[i][h*4+0]; v.y = acc[i][h*4+1];
            v.z = acc[i][h*4+2]; v.w = acc[i][h*4+3];
            if (EPI) {
                size_t roff = (size_t)bz * strideR + (size_t)row * N + (size_t)bx * 128 + tx * 8;
                float4 r = *reinterpret_cast<const float4*>(res + roff + h * 4);
                v.x += bv + r.x; v.y += bv + r.y; v.z += bv + r.z; v.w += bv + r.w;
            }
            *reinterpret_cast<float4*>(Cm + off + h * 4) = v;
        }
    }
}

// ---------------- 3) softmax over L on the K slice of qkv -------------------
__global__ void softmax_kernel(float* __restrict__ qkv)
{
    int row = blockIdx.x;            // 0..BB*HID-1
    int b = row >> 9, r = row & 511;
    float* p = qkv + ((size_t)b * 3 + 1) * ((size_t)HID * LL) + (size_t)r * LL;

    const int tid = threadIdx.x;
    __shared__ float shp[8];
    __shared__ float bcast;

    float m = -3.4e38f;
    for (int i = tid; i < LL; i += 256) m = fmaxf(m, p[i]);
    #pragma unroll
    for (int o = 16; o; o >>= 1) m = fmaxf(m, __shfl_xor_sync(0xffffffffu, m, o));
    if ((tid & 31) == 0) shp[tid >> 5] = m;
    __syncthreads();
    if (tid < 32) {
        float v = (tid < 8) ? shp[tid] : -3.4e38f;
        #pragma unroll
        for (int o = 4; o; o >>= 1) v = fmaxf(v, __shfl_xor_sync(0xffffffffu, v, o));
        if (tid == 0) bcast = v;
    }
    __syncthreads();
    float M = bcast;
    __syncthreads();

    float s = 0.f;
    for (int i = tid; i < LL; i += 256) s += __expf(p[i] - M);
    #pragma unroll
    for (int o = 16; o; o >>= 1) s += __shfl_xor_sync(0xffffffffu, s, o);
    if ((tid & 31) == 0) shp[tid >> 5] = s;
    __syncthreads();
    if (tid < 32) {
        float v = (tid < 8) ? shp[tid] : 0.f;
        #pragma unroll
        for (int o = 4; o; o >>= 1) v += __shfl_xor_sync(0xffffffffu, v, o);
        if (tid == 0) bcast = v;
    }
    __syncthreads();
    float inv = 1.0f / bcast;

    for (int i = tid; i < LL; i += 256) p[i] = __expf(p[i] - M) * inv;
}

// ---------------- 4) context = k @ v^T  (split-K with atomics) -------------
__global__ void zero_ctx_kernel(float* __restrict__ ctx)
{
    ctx[blockIdx.x * 256 + threadIdx.x] = 0.f;
}

__global__ __launch_bounds__(256)
void ctx_kernel(const float* __restrict__ qkv, float* __restrict__ ctx)
{
    const int chunk = blockIdx.x;    // 0..7, each covers 512 of L
    const int h = blockIdx.y, b = blockIdx.z;

    const float* kp = qkv + ((size_t)b * 3 + 1) * ((size_t)HID * LL) + (size_t)h * DH * LL;
    const float* vp = qkv + ((size_t)b * 3 + 2) * ((size_t)HID * LL) + (size_t)h * DH * LL;

    __shared__ float ksT[64][65];    // [n][d]
    __shared__ float vsT[64][65];    // [n][e]

    const int tid = threadIdx.x;
    const int ty = tid >> 4;         // d group (4 rows)
    const int tx = tid & 15;         // e group (4 cols)

    float acc[4][4];
    #pragma unroll
    for (int i = 0; i < 4; i++)
        #pragma unroll
        for (int j = 0; j < 4; j++) acc[i][j] = 0.f;

    for (int t = 0; t < 8; t++) {
        int n0 = chunk * 512 + t * 64;
        #pragma unroll
        for (int i = 0; i < 16; i++) {
            int f = tid + i * 256;            // 0..4095
            int d = f >> 6, nn = f & 63;
            ksT[nn][d] = kp[(size_t)d * LL + n0 + nn];
            vsT[nn][d] = vp[(size_t)d * LL + n0 + nn];
        }
        __syncthreads();
        #pragma unroll 8
        for (int n = 0; n < 64; n++) {
            float af[4], bf[4];
            #pragma unroll
            for (int i = 0; i < 4; i++) af[i] = ksT[n][ty * 4 + i];
            #pragma unroll
            for (int j = 0; j < 4; j++) bf[j] = vsT[n][tx * 4 + j];
            #pragma unroll
            for (int i = 0; i < 4; i++)
                #pragma unroll
                for (int j = 0; j < 4; j++)
                    acc[i][j] = fmaf(af[i], bf[j], acc[i][j]);
        }
        __syncthreads();
    }

    float* cbase = ctx + ((size_t)(b * NH + h)) * DH * DH;
    #pragma unroll
    for (int i = 0; i < 4; i++)
        #pragma unroll
        for (int j = 0; j < 4; j++)
            atomicAdd(&cbase[(size_t)(ty * 4 + i) * DH + tx * 4 + j], acc[i][j]);
}

// ---------------- 5) attn_out = SCALE * ctx^T @ q ---------------------------
__global__ __launch_bounds__(256)
void attn_out_kernel(const float* __restrict__ qkv, const float* __restrict__ ctx,
                     float* __restrict__ attn)
{
    const int nt = blockIdx.x;       // 0..31 (tiles of 128 over L)
    const int h = blockIdx.y, b = blockIdx.z;
    const int n0 = nt * 128;

    const float* qp = qkv + (size_t)b * 3 * HID * LL + (size_t)h * DH * LL;  // s=0
    const float* cp = ctx + ((size_t)(b * NH + h)) * DH * DH;

    __shared__ float cs[64][64];     // [d][e]
    __shared__ float qs[64][128];    // [d][n]

    const int tid = threadIdx.x;

    // load ctx (4096 floats) and q tile (64x128)
    #pragma unroll
    for (int i = 0; i < 4; i++) {
        int f = tid + i * 256;                    // float4 index 0..1023
        reinterpret_cast<float4*>(&cs[0][0])[f] =
            reinterpret_cast<const float4*>(cp)[f];
    }
    #pragma unroll
    for (int i = 0; i < 8; i++) {
        int f = tid + i * 256;                    // 0..2047 float4
        int d = f >> 5, c4 = (f & 31) * 4;
        float4 v = *reinterpret_cast<const float4*>(qp + (size_t)d * LL + n0 + c4);
        *reinterpret_cast<float4*>(&qs[d][c4]) = v;
    }
    __syncthreads();

    const int ty = tid >> 5;         // 0..7 -> e group (8 rows)
    const int tx = tid & 31;         // 0..31 -> n group (4 cols)

    float acc[8][4];
    #pragma unroll
    for (int i = 0; i < 8; i++)
        #pragma unroll
        for (int j = 0; j < 4; j++) acc[i][j] = 0.f;

    #pragma unroll 8
    for (int d = 0; d < 64; d++) {
        float qf[4], cf[8];
        #pragma unroll
        for (int j = 0; j < 4; j++) qf[j] = qs[d][tx * 4 + j];
        #pragma unroll
        for (int i = 0; i < 8; i++) cf[i] = cs[d][ty * 8 + i];
        #pragma unroll
        for (int i = 0; i < 8; i++)
            #pragma unroll
            for (int j = 0; j < 4; j++)
                acc[i][j] = fmaf(cf[i], qf[j], acc[i][j]);
    }

    #pragma unroll
    for (int i = 0; i < 8; i++) {
        int e = ty * 8 + i;
        float* op = attn + ((size_t)b * HID + h * DH + e) * LL + n0 + tx * 4;
        float4 v;
        v.x = acc[i][0] * SCALEV; v.y = acc[i][1] * SCALEV;
        v.z = acc[i][2] * SCALEV; v.w = acc[i][3] * SCALEV;
        *reinterpret_cast<float4*>(op) = v;
    }
}

// ---------------- launch ----------------------------------------------------
extern "C" void kernel_launch(void* const* d_in, const int* in_sizes, int n_in,
                              void* d_out, int out_size)
{
    const float* x     = (const float*)d_in[0];
    const float* gamma = (const float*)d_in[1];
    const float* beta  = (const float*)d_in[2];
    const float* w_qkv = (const float*)d_in[3];
    const float* w_out = (const float*)d_in[4];
    const float* b_out = (const float*)d_in[5];
    float* out = (float*)d_out;

    float *xn, *qkv, *ctx, *attn;
    cudaGetSymbolAddress((void**)&xn,   g_xn);
    cudaGetSymbolAddress((void**)&qkv,  g_qkv);
    cudaGetSymbolAddress((void**)&ctx,  g_ctx);
    cudaGetSymbolAddress((void**)&attn, g_attn);

    // 1) LayerNorm
    ln_kernel<<<dim3(LL / 256, BB), 256>>>(x, gamma, beta, xn);

    // 2) QKV GEMM: [1536x512] @ [512x4096] per batch
    sgemm_kernel<false><<<dim3(LL / 128, (3 * HID) / 128, BB), 256>>>(
        w_qkv, xn, qkv, 3 * HID, LL, CC,
        (size_t)CC * LL, (size_t)3 * HID * LL, nullptr, nullptr, 0);

    // 3) softmax over L on k
    softmax_kernel<<<BB * HID, 256>>>(qkv);

    // 4) context = k @ v^T (split-K over 8 chunks, atomic accumulate)
    zero_ctx_kernel<<<(BB * NH * DH * DH) / 256, 256>>>(ctx);
    ctx_kernel<<<dim3(8, NH, BB), 256>>>(qkv, ctx);

    // 5) attn = SCALE * ctx^T @ q
    attn_out_kernel<<<dim3(LL / 128, NH, BB), 256>>>(qkv, ctx, attn);

    // 6) out = w_out @ attn + b_out + xn   (fused epilogue)
    sgemm_kernel<true><<<dim3(LL / 128, HID / 128, BB), 256>>>(
        w_out, attn, out, HID, LL, HID,
        (size_t)HID * LL, (size_t)HID * LL, b_out, xn, (size_t)CC * LL);
}

// round 4
// speedup vs baseline: 1.8928x; 1.8928x over previous
#include <cuda_runtime.h>
#include <cstdint>
#include <cstddef>

// Problem constants
#define BB   8
#define CC   512
#define LL   4096
#define HID  512
#define NH   8
#define DH   64
#define EPSV 1e-5f
#define SCALEV 0.125f

// ---------------- scratch (device globals) ----------------------------------
__device__ float g_xn  [(size_t)BB * CC * LL];        // 64 MB  normalized x (fp32, residual)
__device__ float g_xnT [(size_t)BB * LL * CC];        // 64 MB  xn transposed, tf32-rounded
__device__ float g_qkv [(size_t)BB * 3 * HID * LL];   // 192 MB qkv
__device__ float g_ctx [(size_t)BB * NH * DH * DH];   // 1 MB   context
__device__ float g_attnT[(size_t)BB * LL * HID];      // 64 MB  attn out [L,HID], tf32-rounded
__device__ float g_wq_r[(size_t)3 * HID * CC];        // 3 MB   w_qkv rounded
__device__ float g_wo_r[(size_t)CC * HID];            // 1 MB   w_out rounded

// ---------------- helpers ----------------------------------------------------
__device__ __forceinline__ uint32_t smem_u32(const void* p) {
    uint32_t a;
    asm("{ .reg .u64 t; cvta.to.shared.u64 t, %1; cvt.u32.u64 %0, t; }" : "=r"(a) : "l"(p));
    return a;
}
// tf32 destination is .b32 in PTX — output via integer register constraint.
__device__ __forceinline__ float to_tf32(float x) {
    uint32_t r; asm("cvt.rna.tf32.f32 %0, %1;" : "=r"(r) : "f"(x));
    return __uint_as_float(r);
}
__device__ __forceinline__ void cp_async16(uint32_t saddr, const void* g) {
    asm volatile("cp.async.cg.shared.global [%0], [%1], 16;" :: "r"(saddr), "l"(g));
}
#define CP_COMMIT() asm volatile("cp.async.commit_group;" ::: "memory")
#define CP_WAIT(n)  asm volatile("cp.async.wait_group %0;" :: "n"(n) : "memory")

// m16n8k8 tf32 warp MMA (sm_80+, valid on base sm_100)
__device__ __forceinline__ void mma_tf32(float* c, const uint32_t* a, const uint32_t* b)
{
    asm volatile(
        "mma.sync.aligned.m16n8k8.row.col.f32.tf32.tf32.f32 "
        "{%0,%1,%2,%3}, {%4,%5,%6,%7}, {%8,%9}, {%0,%1,%2,%3};"
        : "+f"(c[0]), "+f"(c[1]), "+f"(c[2]), "+f"(c[3])
        : "r"(a[0]), "r"(a[1]), "r"(a[2]), "r"(a[3]), "r"(b[0]), "r"(b[1]));
}

// ---------------- 1) LayerNorm (writes xn [C,L]) ----------------------------
__global__ void ln_kernel(const float* __restrict__ x,
                          const float* __restrict__ gamma,
                          const float* __restrict__ beta,
                          float* __restrict__ xn)
{
    int l = blockIdx.x * blockDim.x + threadIdx.x;
    int b = blockIdx.y;
    const float* xp = x  + (size_t)b * CC * LL + l;
    float*       op = xn + (size_t)b * CC * LL + l;

    float s = 0.f, ss = 0.f;
    #pragma unroll 8
    for (int c = 0; c < CC; c++) { float v = xp[(size_t)c * LL]; s += v; ss += v * v; }
    float mean = s * (1.0f / CC);
    float var  = ss * (1.0f / CC) - mean * mean;
    float rstd = rsqrtf(var + EPSV);
    #pragma unroll 8
    for (int c = 0; c < CC; c++) {
        float v = xp[(size_t)c * LL];
        op[(size_t)c * LL] = (v - mean) * rstd * gamma[c] + beta[c];
    }
}

// ---------------- 1b) transpose + tf32 round: xn[C,L] -> xnT[L,C] -----------
__global__ void transpose_round_kernel(const float* __restrict__ in, float* __restrict__ out)
{
    __shared__ float t[32][33];
    int b = blockIdx.z;
    int l0 = blockIdx.x * 32, c0 = blockIdx.y * 32;
    const float* ip = in  + (size_t)b * CC * LL;
    float*       op = out + (size_t)b * CC * LL;
    int x = threadIdx.x, y = threadIdx.y;
    #pragma unroll
    for (int i = 0; i < 4; i++) {
        int c = c0 + y + i * 8;
        t[y + i * 8][x] = ip[(size_t)c * LL + l0 + x];
    }
    __syncthreads();
    #pragma unroll
    for (int i = 0; i < 4; i++) {
        int l = l0 + y + i * 8;
        op[(size_t)l * CC + c0 + x] = to_tf32(t[x][y + i * 8]);
    }
}

// ---------------- 1c) round weights to tf32 ---------------------------------
__global__ void round_tf32_kernel(const float* __restrict__ in, float* __restrict__ out, int n)
{
    int i = blockIdx.x * 256 + threadIdx.x;
    if (i < n) out[i] = to_tf32(in[i]);
}

// ---------------- 2,6) tf32 mma.sync GEMM -----------------------------------
// C[M,N] = A[M,512] @ B[N,512]^T.  A row-major K-stride 512, B row-major (K-major).
// CTA tile 128x128, BK=32, 3-stage cp.async, 8 warps x (64x32 warp tile).
#define PITCH 36                     // floats per smem row (conflict-free frag loads)
#define TILE_FLOATS (128 * PITCH)    // 4608 floats per operand per stage
#define GEMM_DYN_SMEM (3 * 2 * TILE_FLOATS * 4)   // 110,592 B

template <bool EPI>
__global__ void __launch_bounds__(256)
gemm_tf32_mma(const float* __restrict__ A, const float* __restrict__ Bmat,
              float* __restrict__ C, size_t strideBz, size_t strideCz,
              const float* __restrict__ bias,
              const float* __restrict__ res, size_t strideRz)
{
    extern __shared__ float smem[];
    float* sA[3]; float* sB[3];
    #pragma unroll
    for (int s = 0; s < 3; s++) {
        sA[s] = smem + s * 2 * TILE_FLOATS;
        sB[s] = sA[s] + TILE_FLOATS;
    }

    const int tid = threadIdx.x;
    const int wid = tid >> 5, lane = tid & 31;
    const int g = lane >> 2, t4 = lane & 3;
    const int warp_m = wid >> 2;          // 0..1  (64 rows each)
    const int warp_n = wid & 3;           // 0..3  (32 cols each)
    const int bx = blockIdx.x, by = blockIdx.y, bz = blockIdx.z;

    const float* Abase = A    + (size_t)by * 128 * 512;
    const float* Bbase = Bmat + (size_t)bz * strideBz + (size_t)bx * 128 * 512;

    const uint32_t sAu = smem_u32(smem);

    auto load_tile = [&](int t) {
        int stage = t % 3;
        uint32_t dA = sAu + (uint32_t)(stage * 2 * TILE_FLOATS) * 4;
        uint32_t dB = dA + TILE_FLOATS * 4;
        int k0 = t * 32;
        #pragma unroll
        for (int i = 0; i < 4; i++) {
            int f = tid + i * 256;        // 0..1023
            int r = f >> 3, j = f & 7;    // row, float4-col
            uint32_t so = (uint32_t)(r * PITCH + j * 4) * 4;
            cp_async16(dA + so, Abase + (size_t)r * 512 + k0 + j * 4);
            cp_async16(dB + so, Bbase + (size_t)r * 512 + k0 + j * 4);
        }
        CP_COMMIT();
    };

    float acc[4][4][4];
    #pragma unroll
    for (int mf = 0; mf < 4; mf++)
        #pragma unroll
        for (int nf = 0; nf < 4; nf++)
            #pragma unroll
            for (int i = 0; i < 4; i++) acc[mf][nf][i] = 0.f;

    load_tile(0); load_tile(1); load_tile(2);

    const int rmb = warp_m * 64;          // warp row base within tile
    const int nbb = warp_n * 32;          // warp col base within tile

    for (int t = 0; t < 16; t++) {
        CP_WAIT(2);
        __syncthreads();
        const float* As = sA[t % 3];
        const float* Bs = sB[t % 3];

        #pragma unroll
        for (int ks = 0; ks < 4; ks++) {
            const int kb = ks * 8;
            uint32_t af[4][4], bf[4][2];
            #pragma unroll
            for (int mf = 0; mf < 4; mf++) {
                int rm = rmb + mf * 16;
                af[mf][0] = __float_as_uint(As[(rm + g)     * PITCH + kb + t4]);
                af[mf][1] = __float_as_uint(As[(rm + g + 8) * PITCH + kb + t4]);
                af[mf][2] = __float_as_uint(As[(rm + g)     * PITCH + kb + t4 + 4]);
                af[mf][3] = __float_as_uint(As[(rm + g + 8) * PITCH + kb + t4 + 4]);
            }
            #pragma unroll
            for (int nf = 0; nf < 4; nf++) {
                int nb = nbb + nf * 8;
                bf[nf][0] = __float_as_uint(Bs[(nb + g) * PITCH + kb + t4]);
                bf[nf][1] = __float_as_uint(Bs[(nb + g) * PITCH + kb + t4 + 4]);
            }
            #pragma unroll
            for (int mf = 0; mf < 4; mf++)
                #pragma unroll
                for (int nf = 0; nf < 4; nf++)
                    mma_tf32(acc[mf][nf], af[mf], bf[nf]);
        }
        __syncthreads();
        if (t + 3 < 16) load_tile(t + 3);
    }

    // epilogue: float2 stores; rows rm+g and rm+g+8, cols nb + 2*t4 (+1)
    #pragma unroll
    for (int mf = 0; mf < 4; mf++) {
        int row0 = by * 128 + rmb + mf * 16 + g;
        #pragma unroll
        for (int half = 0; half < 2; half++) {
            int row = row0 + half * 8;
            float* crow = C + (size_t)bz * strideCz + (size_t)row * LL + bx * 128;
            const float* rrow = EPI ? (res + (size_t)bz * strideRz + (size_t)row * LL + bx * 128)
                                    : nullptr;
            float bval = EPI ? bias[row] : 0.f;
            #pragma unroll
            for (int nf = 0; nf < 4; nf++) {
                int cn = nbb + nf * 8 + 2 * t4;
                float2 v;
                v.x = acc[mf][nf][half * 2 + 0];
                v.y = acc[mf][nf][half * 2 + 1];
                if (EPI) {
                    float2 rr = *reinterpret_cast<const float2*>(rrow + cn);
                    v.x += bval + rr.x; v.y += bval + rr.y;
                }
                *reinterpret_cast<float2*>(crow + cn) = v;
            }
        }
    }
}

// ---------------- 3) softmax over L on the K slice --------------------------
__global__ void softmax_kernel(float* __restrict__ qkv)
{
    int row = blockIdx.x;
    int b = row >> 9, r = row & 511;
    float* p = qkv + ((size_t)b * 3 + 1) * ((size_t)HID * LL) + (size_t)r * LL;

    const int tid = threadIdx.x;
    __shared__ float shp[8];
    __shared__ float bcast;

    float m = -3.4e38f;
    for (int i = tid; i < LL; i += 256) m = fmaxf(m, p[i]);
    #pragma unroll
    for (int o = 16; o; o >>= 1) m = fmaxf(m, __shfl_xor_sync(0xffffffffu, m, o));
    if ((tid & 31) == 0) shp[tid >> 5] = m;
    __syncthreads();
    if (tid < 32) {
        float v = (tid < 8) ? shp[tid] : -3.4e38f;
        #pragma unroll
        for (int o = 4; o; o >>= 1) v = fmaxf(v, __shfl_xor_sync(0xffffffffu, v, o));
        if (tid == 0) bcast = v;
    }
    __syncthreads();
    float M = bcast;
    __syncthreads();

    float s = 0.f;
    for (int i = tid; i < LL; i += 256) s += __expf(p[i] - M);
    #pragma unroll
    for (int o = 16; o; o >>= 1) s += __shfl_xor_sync(0xffffffffu, s, o);
    if ((tid & 31) == 0) shp[tid >> 5] = s;
    __syncthreads();
    if (tid < 32) {
        float v = (tid < 8) ? shp[tid] : 0.f;
        #pragma unroll
        for (int o = 4; o; o >>= 1) v += __shfl_xor_sync(0xffffffffu, v, o);
        if (tid == 0) bcast = v;
    }
    __syncthreads();
    float inv = 1.0f / bcast;
    for (int i = tid; i < LL; i += 256) p[i] = __expf(p[i] - M) * inv;
}

// ---------------- 4) context = k @ v^T --------------------------------------
__global__ void zero_ctx_kernel(float* __restrict__ ctx)
{
    ctx[blockIdx.x * 256 + threadIdx.x] = 0.f;
}

__global__ __launch_bounds__(256)
void ctx_kernel(const float* __restrict__ qkv, float* __restrict__ ctx)
{
    const int chunk = blockIdx.x;
    const int h = blockIdx.y, b = blockIdx.z;

    const float* kp = qkv + ((size_t)b * 3 + 1) * ((size_t)HID * LL) + (size_t)h * DH * LL;
    const float* vp = qkv + ((size_t)b * 3 + 2) * ((size_t)HID * LL) + (size_t)h * DH * LL;

    __shared__ float ksT[64][65];
    __shared__ float vsT[64][65];

    const int tid = threadIdx.x;
    const int ty = tid >> 4, tx = tid & 15;

    float acc[4][4];
    #pragma unroll
    for (int i = 0; i < 4; i++)
        #pragma unroll
        for (int j = 0; j < 4; j++) acc[i][j] = 0.f;

    for (int t = 0; t < 8; t++) {
        int n0 = chunk * 512 + t * 64;
        #pragma unroll
        for (int i = 0; i < 16; i++) {
            int f = tid + i * 256;
            int d = f >> 6, nn = f & 63;
            ksT[nn][d] = kp[(size_t)d * LL + n0 + nn];
            vsT[nn][d] = vp[(size_t)d * LL + n0 + nn];
        }
        __syncthreads();
        #pragma unroll 8
        for (int n = 0; n < 64; n++) {
            float af[4], bf[4];
            #pragma unroll
            for (int i = 0; i < 4; i++) af[i] = ksT[n][ty * 4 + i];
            #pragma unroll
            for (int j = 0; j < 4; j++) bf[j] = vsT[n][tx * 4 + j];
            #pragma unroll
            for (int i = 0; i < 4; i++)
                #pragma unroll
                for (int j = 0; j < 4; j++)
                    acc[i][j] = fmaf(af[i], bf[j], acc[i][j]);
        }
        __syncthreads();
    }

    float* cbase = ctx + ((size_t)(b * NH + h)) * DH * DH;
    #pragma unroll
    for (int i = 0; i < 4; i++)
        #pragma unroll
        for (int j = 0; j < 4; j++)
            atomicAdd(&cbase[(size_t)(ty * 4 + i) * DH + tx * 4 + j], acc[i][j]);
}

// ---------------- 5) attnT[l, hid] = (SCALE * ctx^T @ q)^T, tf32-rounded ----
__global__ __launch_bounds__(256)
void attn_out_kernel(const float* __restrict__ qkv, const float* __restrict__ ctx,
                     float* __restrict__ attnT)
{
    const int nt = blockIdx.x;
    const int h = blockIdx.y, b = blockIdx.z;
    const int n0 = nt * 128;

    const float* qp = qkv + (size_t)b * 3 * HID * LL + (size_t)h * DH * LL;
    const float* cp = ctx + ((size_t)(b * NH + h)) * DH * DH;

    __shared__ union {
        struct { float cs[64][64]; float qs[64][128]; } a;
        float os[128][65];
    } sm;

    const int tid = threadIdx.x;

    #pragma unroll
    for (int i = 0; i < 4; i++) {
        int f = tid + i * 256;
        reinterpret_cast<float4*>(&sm.a.cs[0][0])[f] = reinterpret_cast<const float4*>(cp)[f];
    }
    #pragma unroll
    for (int i = 0; i < 8; i++) {
        int f = tid + i * 256;
        int d = f >> 5, c4 = (f & 31) * 4;
        float4 v = *reinterpret_cast<const float4*>(qp + (size_t)d * LL + n0 + c4);
        *reinterpret_cast<float4*>(&sm.a.qs[d][c4]) = v;
    }
    __syncthreads();

    const int ty = tid >> 5, tx = tid & 31;

    float acc[8][4];
    #pragma unroll
    for (int i = 0; i < 8; i++)
        #pragma unroll
        for (int j = 0; j < 4; j++) acc[i][j] = 0.f;

    #pragma unroll 8
    for (int d = 0; d < 64; d++) {
        float qf[4], cf[8];
        #pragma unroll
        for (int j = 0; j < 4; j++) qf[j] = sm.a.qs[d][tx * 4 + j];
        #pragma unroll
        for (int i = 0; i < 8; i++) cf[i] = sm.a.cs[d][ty * 8 + i];
        #pragma unroll
        for (int i = 0; i < 8; i++)
            #pragma unroll
            for (int j = 0; j < 4; j++)
                acc[i][j] = fmaf(cf[i], qf[j], acc[i][j]);
    }

    __syncthreads();

    #pragma unroll
    for (int i = 0; i < 8; i++)
        #pragma unroll
        for (int j = 0; j < 4; j++)
            sm.os[tx * 4 + j][ty * 8 + i] = acc[i][j] * SCALEV;
    __syncthreads();

    #pragma unroll
    for (int i = 0; i < 8; i++) {
        int f = tid + i * 256;
        int r = f >> 4, c4 = (f & 15) * 4;
        float4 v;
        v.x = to_tf32(sm.os[r][c4 + 0]);
        v.y = to_tf32(sm.os[r][c4 + 1]);
        v.z = to_tf32(sm.os[r][c4 + 2]);
        v.w = to_tf32(sm.os[r][c4 + 3]);
        *reinterpret_cast<float4*>(attnT + ((size_t)b * LL + n0 + r) * HID + h * DH + c4) = v;
    }
}

// ---------------- launch ----------------------------------------------------
extern "C" void kernel_launch(void* const* d_in, const int* in_sizes, int n_in,
                              void* d_out, int out_size)
{
    const float* x     = (const float*)d_in[0];
    const float* gamma = (const float*)d_in[1];
    const float* beta  = (const float*)d_in[2];
    const float* w_qkv = (const float*)d_in[3];
    const float* w_out = (const float*)d_in[4];
    const float* b_out = (const float*)d_in[5];
    float* out = (float*)d_out;

    float *xn, *xnT, *qkv, *ctx, *attnT, *wq_r, *wo_r;
    cudaGetSymbolAddress((void**)&xn,    g_xn);
    cudaGetSymbolAddress((void**)&xnT,   g_xnT);
    cudaGetSymbolAddress((void**)&qkv,   g_qkv);
    cudaGetSymbolAddress((void**)&ctx,   g_ctx);
    cudaGetSymbolAddress((void**)&attnT, g_attnT);
    cudaGetSymbolAddress((void**)&wq_r,  g_wq_r);
    cudaGetSymbolAddress((void**)&wo_r,  g_wo_r);

    cudaFuncSetAttribute(gemm_tf32_mma<false>, cudaFuncAttributeMaxDynamicSharedMemorySize, GEMM_DYN_SMEM);
    cudaFuncSetAttribute(gemm_tf32_mma<true>,  cudaFuncAttributeMaxDynamicSharedMemorySize, GEMM_DYN_SMEM);

    // 1) LayerNorm -> xn
    ln_kernel<<<dim3(LL / 256, BB), 256>>>(x, gamma, beta, xn);

    // 1b) xn -> xnT (tf32-rounded);  1c) round weights
    transpose_round_kernel<<<dim3(LL / 32, CC / 32, BB), dim3(32, 8)>>>(xn, xnT);
    round_tf32_kernel<<<(3 * HID * CC + 255) / 256, 256>>>(w_qkv, wq_r, 3 * HID * CC);
    round_tf32_kernel<<<(CC * HID + 255) / 256, 256>>>(w_out, wo_r, CC * HID);

    // 2) QKV GEMM
    gemm_tf32_mma<false><<<dim3(LL / 128, (3 * HID) / 128, BB), 256, GEMM_DYN_SMEM>>>(
        wq_r, xnT, qkv, (size_t)LL * CC, (size_t)3 * HID * LL, nullptr, nullptr, 0);

    // 3) softmax over L on k
    softmax_kernel<<<BB * HID, 256>>>(qkv);

    // 4) context
    zero_ctx_kernel<<<(BB * NH * DH * DH) / 256, 256>>>(ctx);
    ctx_kernel<<<dim3(8, NH, BB), 256>>>(qkv, ctx);

    // 5) attnT (tf32-rounded, [L, HID])
    attn_out_kernel<<<dim3(LL / 128, NH, BB), 256>>>(qkv, ctx, attnT);

    // 6) out = wo_r @ attn + b_out + xn
    gemm_tf32_mma<true><<<dim3(LL / 128, HID / 128, BB), 256, GEMM_DYN_SMEM>>>(
        wo_r, attnT, out, (size_t)LL * HID, (size_t)HID * LL, b_out, xn, (size_t)CC * LL);
}

// round 6
// speedup vs baseline: 2.2799x; 1.2045x over previous
#include <cuda_runtime.h>
#include <cstdint>
#include <cstddef>

// Problem constants
#define BB   8
#define CC   512
#define LL   4096
#define HID  512
#define NH   8
#define DH   64
#define EPSV 1e-5f
#define SCALEV 0.125f

// ---------------- scratch (device globals) ----------------------------------
__device__ float g_xn  [(size_t)BB * CC * LL];        // 64 MB  normalized x (fp32, residual)
__device__ float g_xnT [(size_t)BB * LL * CC];        // 64 MB  xn transposed, tf32-rounded
__device__ float g_qkv [(size_t)BB * 3 * HID * LL];   // 192 MB qkv
__device__ float g_ctx [(size_t)BB * NH * DH * DH];   // 1 MB   context
__device__ float g_attnT[(size_t)BB * LL * HID];      // 64 MB  attn out [L,HID], tf32-rounded
__device__ float g_wq_r[(size_t)3 * HID * CC];        // 3 MB   w_qkv rounded
__device__ float g_wo_r[(size_t)CC * HID];            // 1 MB   w_out rounded

// ---------------- helpers ----------------------------------------------------
__device__ __forceinline__ uint32_t smem_u32(const void* p) {
    uint32_t a;
    asm("{ .reg .u64 t; cvta.to.shared.u64 t, %1; cvt.u32.u64 %0, t; }" : "=r"(a) : "l"(p));
    return a;
}
__device__ __forceinline__ float to_tf32(float x) {
    uint32_t r; asm("cvt.rna.tf32.f32 %0, %1;" : "=r"(r) : "f"(x));
    return __uint_as_float(r);
}
__device__ __forceinline__ void cp_async16(uint32_t saddr, const void* g) {
    asm volatile("cp.async.cg.shared.global [%0], [%1], 16;" :: "r"(saddr), "l"(g));
}
#define CP_COMMIT() asm volatile("cp.async.commit_group;" ::: "memory")
#define CP_WAIT(n)  asm volatile("cp.async.wait_group %0;" :: "n"(n) : "memory")

// m16n8k8 tf32 warp MMA
__device__ __forceinline__ void mma_tf32(float* c, const uint32_t* a, const uint32_t* b)
{
    asm volatile(
        "mma.sync.aligned.m16n8k8.row.col.f32.tf32.tf32.f32 "
        "{%0,%1,%2,%3}, {%4,%5,%6,%7}, {%8,%9}, {%0,%1,%2,%3};"
        : "+f"(c[0]), "+f"(c[1]), "+f"(c[2]), "+f"(c[3])
        : "r"(a[0]), "r"(a[1]), "r"(a[2]), "r"(a[3]), "r"(b[0]), "r"(b[1]));
}

// ---------------- fused LayerNorm: xn[C,L] + xnT[L,C] (tf32) ----------------
// grid (LL/32, BB), 256 threads, dynamic smem 512*33*4 B.
#define LN_SMEM (512 * 33 * 4)
__global__ void __launch_bounds__(256)
ln_fused_kernel(const float* __restrict__ x,
                const float* __restrict__ gamma,
                const float* __restrict__ beta,
                float* __restrict__ xn, float* __restrict__ xnT)
{
    extern __shared__ float s[];           // [512][33]
    __shared__ float ps[8][32], pss[8][32];
    __shared__ float s_mean[32], s_rstd[32];

    const int tid = threadIdx.x, wid = tid >> 5, lane = tid & 31;
    const int l0 = blockIdx.x * 32, b = blockIdx.y;
    const float* xb = x + (size_t)b * CC * LL;

    // load 512 x 32 tile, coalesced over l
    #pragma unroll 4
    for (int it = 0; it < 64; it++) {
        int c = it * 8 + wid;
        s[c * 33 + lane] = xb[(size_t)c * LL + l0 + lane];
    }
    __syncthreads();

    // per-l stats: 8 partial chunks of 64 channels
    {
        int l = lane, ch = wid;
        float sum = 0.f, ssum = 0.f;
        #pragma unroll 8
        for (int c = ch * 64; c < ch * 64 + 64; c++) {
            float v = s[c * 33 + l];
            sum += v; ssum += v * v;
        }
        ps[ch][l] = sum; pss[ch][l] = ssum;
    }
    __syncthreads();
    if (tid < 32) {
        float sum = 0.f, ssum = 0.f;
        #pragma unroll
        for (int ch = 0; ch < 8; ch++) { sum += ps[ch][tid]; ssum += pss[ch][tid]; }
        float mean = sum * (1.0f / CC);
        float var  = ssum * (1.0f / CC) - mean * mean;
        s_mean[tid] = mean;
        s_rstd[tid] = rsqrtf(var + EPSV);
    }
    __syncthreads();

    // write xn [C,L] (coalesced over l)
    float* xnb = xn + (size_t)b * CC * LL;
    {
        float mean = s_mean[lane], rstd = s_rstd[lane];
        #pragma unroll 4
        for (int it = 0; it < 64; it++) {
            int c = it * 8 + wid;
            float v = (s[c * 33 + lane] - mean) * rstd * __ldg(&gamma[c]) + __ldg(&beta[c]);
            xnb[(size_t)c * LL + l0 + lane] = v;
        }
    }

    // write xnT [L,C] tf32-rounded (coalesced over c)
    float* xTb = xnT + (size_t)b * LL * CC;
    #pragma unroll 4
    for (int i = 0; i < 64; i++) {
        int f = tid + i * 256;           // 0..16383
        int l = f >> 9, c = f & 511;
        float v = (s[c * 33 + l] - s_mean[l]) * s_rstd[l] * __ldg(&gamma[c]) + __ldg(&beta[c]);
        xTb[(size_t)(l0 + l) * CC + c] = to_tf32(v);
    }
}

// ---------------- round weights to tf32 -------------------------------------
__global__ void round_tf32_kernel(const float* __restrict__ in, float* __restrict__ out, int n)
{
    int i = blockIdx.x * 256 + threadIdx.x;
    if (i < n) out[i] = to_tf32(in[i]);
}

// ---------------- tf32 mma.sync GEMM: 128x256 tile ---------------------------
// C[M,N] = A[M,512] @ B[N,512]^T, both K-major.  Warp tile 64x64 (2x4 warps).
#define PITCH 36
#define A_FLOATS (128 * PITCH)       // 4608
#define B_FLOATS (256 * PITCH)       // 9216
#define STG_FLOATS (A_FLOATS + B_FLOATS)
#define GEMM_DYN_SMEM (3 * STG_FLOATS * 4)   // 165,888 B

template <bool EPI>
__global__ void __launch_bounds__(256)
gemm_tf32_mma(const float* __restrict__ A, const float* __restrict__ Bmat,
              float* __restrict__ C, size_t strideBz, size_t strideCz,
              const float* __restrict__ bias,
              const float* __restrict__ res, size_t strideRz)
{
    extern __shared__ float smem[];

    const int tid = threadIdx.x;
    const int wid = tid >> 5, lane = tid & 31;
    const int g = lane >> 2, t4 = lane & 3;
    const int warp_m = wid >> 2;          // 0..1 (64 rows)
    const int warp_n = wid & 3;           // 0..3 (64 cols)
    const int bx = blockIdx.x, by = blockIdx.y, bz = blockIdx.z;

    const float* Abase = A    + (size_t)by * 128 * 512;
    const float* Bbase = Bmat + (size_t)bz * strideBz + (size_t)bx * 256 * 512;

    const uint32_t sAu = smem_u32(smem);

    auto load_tile = [&](int t) {
        int stage = t % 3;
        uint32_t dA = sAu + (uint32_t)(stage * STG_FLOATS) * 4;
        uint32_t dB = dA + A_FLOATS * 4;
        int k0 = t * 32;
        #pragma unroll
        for (int i = 0; i < 4; i++) {     // A: 1024 float4
            int f = tid + i * 256;
            int r = f >> 3, j = f & 7;
            cp_async16(dA + (uint32_t)(r * PITCH + j * 4) * 4,
                       Abase + (size_t)r * 512 + k0 + j * 4);
        }
        #pragma unroll
        for (int i = 0; i < 8; i++) {     // B: 2048 float4
            int f = tid + i * 256;
            int r = f >> 3, j = f & 7;
            cp_async16(dB + (uint32_t)(r * PITCH + j * 4) * 4,
                       Bbase + (size_t)r * 512 + k0 + j * 4);
        }
        CP_COMMIT();
    };

    float acc[4][8][4];
    #pragma unroll
    for (int mf = 0; mf < 4; mf++)
        #pragma unroll
        for (int nf = 0; nf < 8; nf++)
            #pragma unroll
            for (int i = 0; i < 4; i++) acc[mf][nf][i] = 0.f;

    load_tile(0); load_tile(1); load_tile(2);

    const int rmb = warp_m * 64;
    const int nbb = warp_n * 64;

    for (int t = 0; t < 16; t++) {
        CP_WAIT(2);
        __syncthreads();
        const float* As = smem + (t % 3) * STG_FLOATS;
        const float* Bs = As + A_FLOATS;

        #pragma unroll
        for (int ks = 0; ks < 4; ks++) {
            const int kb = ks * 8;
            uint32_t af[4][4], bf[8][2];
            #pragma unroll
            for (int mf = 0; mf < 4; mf++) {
                int rm = rmb + mf * 16;
                af[mf][0] = __float_as_uint(As[(rm + g)     * PITCH + kb + t4]);
                af[mf][1] = __float_as_uint(As[(rm + g + 8) * PITCH + kb + t4]);
                af[mf][2] = __float_as_uint(As[(rm + g)     * PITCH + kb + t4 + 4]);
                af[mf][3] = __float_as_uint(As[(rm + g + 8) * PITCH + kb + t4 + 4]);
            }
            #pragma unroll
            for (int nf = 0; nf < 8; nf++) {
                int nb = nbb + nf * 8;
                bf[nf][0] = __float_as_uint(Bs[(nb + g) * PITCH + kb + t4]);
                bf[nf][1] = __float_as_uint(Bs[(nb + g) * PITCH + kb + t4 + 4]);
            }
            #pragma unroll
            for (int mf = 0; mf < 4; mf++)
                #pragma unroll
                for (int nf = 0; nf < 8; nf++)
                    mma_tf32(acc[mf][nf], af[mf], bf[nf]);
        }
        __syncthreads();
        if (t + 3 < 16) load_tile(t + 3);
    }

    // epilogue
    #pragma unroll
    for (int mf = 0; mf < 4; mf++) {
        int row0 = by * 128 + rmb + mf * 16 + g;
        #pragma unroll
        for (int half = 0; half < 2; half++) {
            int row = row0 + half * 8;
            float* crow = C + (size_t)bz * strideCz + (size_t)row * LL + bx * 256;
            const float* rrow = EPI ? (res + (size_t)bz * strideRz + (size_t)row * LL + bx * 256)
                                    : nullptr;
            float bval = EPI ? bias[row] : 0.f;
            #pragma unroll
            for (int nf = 0; nf < 8; nf++) {
                int cn = nbb + nf * 8 + 2 * t4;
                float2 v;
                v.x = acc[mf][nf][half * 2 + 0];
                v.y = acc[mf][nf][half * 2 + 1];
                if (EPI) {
                    float2 rr = *reinterpret_cast<const float2*>(rrow + cn);
                    v.x += bval + rr.x; v.y += bval + rr.y;
                }
                *reinterpret_cast<float2*>(crow + cn) = v;
            }
        }
    }
}

// ---------------- softmax over L (single pass, register-resident) ------------
__global__ void __launch_bounds__(256)
softmax_kernel(float* __restrict__ qkv)
{
    int row = blockIdx.x;
    int b = row >> 9, r = row & 511;
    float* p = qkv + ((size_t)b * 3 + 1) * ((size_t)HID * LL) + (size_t)r * LL;

    const int tid = threadIdx.x;
    __shared__ float shp[8];
    __shared__ float bcast;

    float4 v[4];
    #pragma unroll
    for (int i = 0; i < 4; i++)
        v[i] = reinterpret_cast<const float4*>(p)[tid + i * 256];

    float m = -3.4e38f;
    #pragma unroll
    for (int i = 0; i < 4; i++) {
        m = fmaxf(m, fmaxf(fmaxf(v[i].x, v[i].y), fmaxf(v[i].z, v[i].w)));
    }
    #pragma unroll
    for (int o = 16; o; o >>= 1) m = fmaxf(m, __shfl_xor_sync(0xffffffffu, m, o));
    if ((tid & 31) == 0) shp[tid >> 5] = m;
    __syncthreads();
    if (tid < 32) {
        float t = (tid < 8) ? shp[tid] : -3.4e38f;
        #pragma unroll
        for (int o = 4; o; o >>= 1) t = fmaxf(t, __shfl_xor_sync(0xffffffffu, t, o));
        if (tid == 0) bcast = t;
    }
    __syncthreads();
    float M = bcast;
    __syncthreads();

    float s = 0.f;
    #pragma unroll
    for (int i = 0; i < 4; i++) {
        v[i].x = __expf(v[i].x - M); v[i].y = __expf(v[i].y - M);
        v[i].z = __expf(v[i].z - M); v[i].w = __expf(v[i].w - M);
        s += v[i].x + v[i].y + v[i].z + v[i].w;
    }
    #pragma unroll
    for (int o = 16; o; o >>= 1) s += __shfl_xor_sync(0xffffffffu, s, o);
    if ((tid & 31) == 0) shp[tid >> 5] = s;
    __syncthreads();
    if (tid < 32) {
        float t = (tid < 8) ? shp[tid] : 0.f;
        #pragma unroll
        for (int o = 4; o; o >>= 1) t += __shfl_xor_sync(0xffffffffu, t, o);
        if (tid == 0) bcast = t;
    }
    __syncthreads();
    float inv = 1.0f / bcast;

    #pragma unroll
    for (int i = 0; i < 4; i++) {
        v[i].x *= inv; v[i].y *= inv; v[i].z *= inv; v[i].w *= inv;
        reinterpret_cast<float4*>(p)[tid + i * 256] = v[i];
    }
}

// ---------------- context = k @ v^T ------------------------------------------
__global__ void zero_ctx_kernel(float* __restrict__ ctx, int off)
{
    ctx[off + blockIdx.x * 256 + threadIdx.x] = 0.f;
}

__global__ void __launch_bounds__(256)
ctx_kernel(const float* __restrict__ qkv, float* __restrict__ ctx)
{
    const int chunk = blockIdx.x;
    const int h = blockIdx.y, b = blockIdx.z;

    const float* kp = qkv + ((size_t)b * 3 + 1) * ((size_t)HID * LL) + (size_t)h * DH * LL;
    const float* vp = qkv + ((size_t)b * 3 + 2) * ((size_t)HID * LL) + (size_t)h * DH * LL;

    __shared__ float ksT[64][65];
    __shared__ float vsT[64][65];

    const int tid = threadIdx.x;
    const int ty = tid >> 4, tx = tid & 15;

    float acc[4][4];
    #pragma unroll
    for (int i = 0; i < 4; i++)
        #pragma unroll
        for (int j = 0; j < 4; j++) acc[i][j] = 0.f;

    for (int t = 0; t < 8; t++) {
        int n0 = chunk * 512 + t * 64;
        #pragma unroll
        for (int i = 0; i < 16; i++) {
            int f = tid + i * 256;
            int d = f >> 6, nn = f & 63;
            ksT[nn][d] = kp[(size_t)d * LL + n0 + nn];
            vsT[nn][d] = vp[(size_t)d * LL + n0 + nn];
        }
        __syncthreads();
        #pragma unroll 8
        for (int n = 0; n < 64; n++) {
            float af[4], bf[4];
            #pragma unroll
            for (int i = 0; i < 4; i++) af[i] = ksT[n][ty * 4 + i];
            #pragma unroll
            for (int j = 0; j < 4; j++) bf[j] = vsT[n][tx * 4 + j];
            #pragma unroll
            for (int i = 0; i < 4; i++)
                #pragma unroll
                for (int j = 0; j < 4; j++)
                    acc[i][j] = fmaf(af[i], bf[j], acc[i][j]);
        }
        __syncthreads();
    }

    float* cbase = ctx + ((size_t)(b * NH + h)) * DH * DH;
    #pragma unroll
    for (int i = 0; i < 4; i++)
        #pragma unroll
        for (int j = 0; j < 4; j++)
            atomicAdd(&cbase[(size_t)(ty * 4 + i) * DH + tx * 4 + j], acc[i][j]);
}

// ---------------- attnT[l, hid] = (SCALE * ctx^T @ q)^T, tf32-rounded --------
__global__ void __launch_bounds__(256)
attn_out_kernel(const float* __restrict__ qkv, const float* __restrict__ ctx,
                float* __restrict__ attnT)
{
    const int nt = blockIdx.x;
    const int h = blockIdx.y, b = blockIdx.z;
    const int n0 = nt * 128;

    const float* qp = qkv + (size_t)b * 3 * HID * LL + (size_t)h * DH * LL;
    const float* cp = ctx + ((size_t)(b * NH + h)) * DH * DH;

    __shared__ union {
        struct { float cs[64][64]; float qs[64][128]; } a;
        float os[128][65];
    } sm;

    const int tid = threadIdx.x;

    #pragma unroll
    for (int i = 0; i < 4; i++) {
        int f = tid + i * 256;
        reinterpret_cast<float4*>(&sm.a.cs[0][0])[f] = reinterpret_cast<const float4*>(cp)[f];
    }
    #pragma unroll
    for (int i = 0; i < 8; i++) {
        int f = tid + i * 256;
        int d = f >> 5, c4 = (f & 31) * 4;
        float4 v = *reinterpret_cast<const float4*>(qp + (size_t)d * LL + n0 + c4);
        *reinterpret_cast<float4*>(&sm.a.qs[d][c4]) = v;
    }
    __syncthreads();

    const int ty = tid >> 5, tx = tid & 31;

    float acc[8][4];
    #pragma unroll
    for (int i = 0; i < 8; i++)
        #pragma unroll
        for (int j = 0; j < 4; j++) acc[i][j] = 0.f;

    #pragma unroll 8
    for (int d = 0; d < 64; d++) {
        float qf[4], cf[8];
        #pragma unroll
        for (int j = 0; j < 4; j++) qf[j] = sm.a.qs[d][tx * 4 + j];
        #pragma unroll
        for (int i = 0; i < 8; i++) cf[i] = sm.a.cs[d][ty * 8 + i];
        #pragma unroll
        for (int i = 0; i < 8; i++)
            #pragma unroll
            for (int j = 0; j < 4; j++)
                acc[i][j] = fmaf(cf[i], qf[j], acc[i][j]);
    }

    __syncthreads();

    #pragma unroll
    for (int i = 0; i < 8; i++)
        #pragma unroll
        for (int j = 0; j < 4; j++)
            sm.os[tx * 4 + j][ty * 8 + i] = acc[i][j] * SCALEV;
    __syncthreads();

    #pragma unroll
    for (int i = 0; i < 8; i++) {
        int f = tid + i * 256;
        int r = f >> 4, c4 = (f & 15) * 4;
        float4 v;
        v.x = to_tf32(sm.os[r][c4 + 0]);
        v.y = to_tf32(sm.os[r][c4 + 1]);
        v.z = to_tf32(sm.os[r][c4 + 2]);
        v.w = to_tf32(sm.os[r][c4 + 3]);
        *reinterpret_cast<float4*>(attnT + ((size_t)b * LL + n0 + r) * HID + h * DH + c4) = v;
    }
}

// ---------------- launch ------------------------------------------------------
extern "C" void kernel_launch(void* const* d_in, const int* in_sizes, int n_in,
                              void* d_out, int out_size)
{
    const float* x     = (const float*)d_in[0];
    const float* gamma = (const float*)d_in[1];
    const float* beta  = (const float*)d_in[2];
    const float* w_qkv = (const float*)d_in[3];
    const float* w_out = (const float*)d_in[4];
    const float* b_out = (const float*)d_in[5];
    float* out = (float*)d_out;

    float *xn, *xnT, *qkv, *ctx, *attnT, *wq_r, *wo_r;
    cudaGetSymbolAddress((void**)&xn,    g_xn);
    cudaGetSymbolAddress((void**)&xnT,   g_xnT);
    cudaGetSymbolAddress((void**)&qkv,   g_qkv);
    cudaGetSymbolAddress((void**)&ctx,   g_ctx);
    cudaGetSymbolAddress((void**)&attnT, g_attnT);
    cudaGetSymbolAddress((void**)&wq_r,  g_wq_r);
    cudaGetSymbolAddress((void**)&wo_r,  g_wo_r);

    cudaFuncSetAttribute(gemm_tf32_mma<false>, cudaFuncAttributeMaxDynamicSharedMemorySize, GEMM_DYN_SMEM);
    cudaFuncSetAttribute(gemm_tf32_mma<true>,  cudaFuncAttributeMaxDynamicSharedMemorySize, GEMM_DYN_SMEM);
    cudaFuncSetAttribute(ln_fused_kernel,      cudaFuncAttributeMaxDynamicSharedMemorySize, LN_SMEM);

    const int CTX_N = BB * NH * DH * DH;   // 262144

    // launches 0-4 (so ncu -s 5 -c 1 lands on the QKV GEMM at index 5)
    round_tf32_kernel<<<(3 * HID * CC + 255) / 256, 256>>>(w_qkv, wq_r, 3 * HID * CC);   // 0
    round_tf32_kernel<<<(CC * HID + 255) / 256, 256>>>(w_out, wo_r, CC * HID);           // 1
    zero_ctx_kernel<<<CTX_N / 512, 256>>>(ctx, 0);                                       // 2
    zero_ctx_kernel<<<CTX_N / 512, 256>>>(ctx, CTX_N / 2);                               // 3
    ln_fused_kernel<<<dim3(LL / 32, BB), 256, LN_SMEM>>>(x, gamma, beta, xn, xnT);       // 4

    // 5) QKV GEMM: [1536 x 4096 x 512] per batch, tile 128x256
    gemm_tf32_mma<false><<<dim3(LL / 256, (3 * HID) / 128, BB), 256, GEMM_DYN_SMEM>>>(
        wq_r, xnT, qkv, (size_t)LL * CC, (size_t)3 * HID * LL, nullptr, nullptr, 0);

    // 6) softmax over L on k
    softmax_kernel<<<BB * HID, 256>>>(qkv);

    // 7) context
    ctx_kernel<<<dim3(8, NH, BB), 256>>>(qkv, ctx);

    // 8) attnT
    attn_out_kernel<<<dim3(LL / 128, NH, BB), 256>>>(qkv, ctx, attnT);

    // 9) out = wo_r @ attn + b_out + xn
    gemm_tf32_mma<true><<<dim3(LL / 256, HID / 128, BB), 256, GEMM_DYN_SMEM>>>(
        wo_r, attnT, out, (size_t)LL * HID, (size_t)HID * LL, b_out, xn, (size_t)CC * LL);
}

// round 7
// speedup vs baseline: 2.9051x; 1.2742x over previous
#include <cuda_runtime.h>
#include <cuda_bf16.h>
#include <cstdint>
#include <cstddef>

// Problem constants
#define BB   8
#define CC   512
#define LL   4096
#define HID  512
#define NH   8
#define DH   64
#define EPSV 1e-5f
#define SCALEV 0.125f

// ---------------- scratch (device globals) ----------------------------------
__device__ float    g_xn   [(size_t)BB * CC * LL];        // 64 MB fp32 residual
__device__ uint32_t g_xnT16[(size_t)BB * LL * (CC/2)];    // 32 MB xn^T bf16 [L, C]
__device__ float    g_qkv  [(size_t)BB * 3 * HID * LL];   // 192 MB qkv fp32
__device__ float    g_ctx  [(size_t)BB * NH * DH * DH];   // 1 MB context
__device__ uint32_t g_attnT16[(size_t)BB * LL * (HID/2)]; // 32 MB attn^T bf16 [L, HID]
__device__ uint32_t g_wq16 [(size_t)3 * HID * CC / 2];    // 1.5 MB w_qkv bf16
__device__ uint32_t g_wo16 [(size_t)CC * HID / 2];        // 0.5 MB w_out bf16

// ---------------- helpers ----------------------------------------------------
__device__ __forceinline__ uint32_t smem_u32(const void* p) {
    uint32_t a;
    asm("{ .reg .u64 t; cvta.to.shared.u64 t, %1; cvt.u32.u64 %0, t; }" : "=r"(a) : "l"(p));
    return a;
}
__device__ __forceinline__ uint32_t pack_bf16x2(float lo, float hi) {
    __nv_bfloat162 h = __floats2bfloat162_rn(lo, hi);   // .x = lo (low 16 bits)
    return *reinterpret_cast<uint32_t*>(&h);
}
__device__ __forceinline__ void cp_async16(uint32_t saddr, const void* g) {
    asm volatile("cp.async.cg.shared.global [%0], [%1], 16;" :: "r"(saddr), "l"(g));
}
#define CP_COMMIT() asm volatile("cp.async.commit_group;" ::: "memory")
#define CP_WAIT(n)  asm volatile("cp.async.wait_group %0;" :: "n"(n) : "memory")

// m16n8k16 bf16 warp MMA (sm_80+)
__device__ __forceinline__ void mma_bf16(float* c, const uint32_t* a, const uint32_t* b)
{
    asm volatile(
        "mma.sync.aligned.m16n8k16.row.col.f32.bf16.bf16.f32 "
        "{%0,%1,%2,%3}, {%4,%5,%6,%7}, {%8,%9}, {%0,%1,%2,%3};"
        : "+f"(c[0]), "+f"(c[1]), "+f"(c[2]), "+f"(c[3])
        : "r"(a[0]), "r"(a[1]), "r"(a[2]), "r"(a[3]), "r"(b[0]), "r"(b[1]));
}

// ---------------- fused LayerNorm: xn[C,L] fp32 + xnT[L,C] bf16 --------------
#define LN_SMEM (512 * 33 * 4)
__global__ void __launch_bounds__(256)
ln_fused_kernel(const float* __restrict__ x,
                const float* __restrict__ gamma,
                const float* __restrict__ beta,
                float* __restrict__ xn, uint32_t* __restrict__ xnT16)
{
    extern __shared__ float s[];           // [512][33]
    __shared__ float ps[8][32], pss[8][32];
    __shared__ float s_mean[32], s_rstd[32];

    const int tid = threadIdx.x, wid = tid >> 5, lane = tid & 31;
    const int l0 = blockIdx.x * 32, b = blockIdx.y;
    const float* xb = x + (size_t)b * CC * LL;

    #pragma unroll 4
    for (int it = 0; it < 64; it++) {
        int c = it * 8 + wid;
        s[c * 33 + lane] = xb[(size_t)c * LL + l0 + lane];
    }
    __syncthreads();

    {
        int l = lane, ch = wid;
        float sum = 0.f, ssum = 0.f;
        #pragma unroll 8
        for (int c = ch * 64; c < ch * 64 + 64; c++) {
            float v = s[c * 33 + l];
            sum += v; ssum += v * v;
        }
        ps[ch][l] = sum; pss[ch][l] = ssum;
    }
    __syncthreads();
    if (tid < 32) {
        float sum = 0.f, ssum = 0.f;
        #pragma unroll
        for (int ch = 0; ch < 8; ch++) { sum += ps[ch][tid]; ssum += pss[ch][tid]; }
        float mean = sum * (1.0f / CC);
        float var  = ssum * (1.0f / CC) - mean * mean;
        s_mean[tid] = mean;
        s_rstd[tid] = rsqrtf(var + EPSV);
    }
    __syncthreads();

    // xn [C,L] fp32 (residual path)
    float* xnb = xn + (size_t)b * CC * LL;
    {
        float mean = s_mean[lane], rstd = s_rstd[lane];
        #pragma unroll 4
        for (int it = 0; it < 64; it++) {
            int c = it * 8 + wid;
            float v = (s[c * 33 + lane] - mean) * rstd * __ldg(&gamma[c]) + __ldg(&beta[c]);
            xnb[(size_t)c * LL + l0 + lane] = v;
        }
    }

    // xnT [L,C] bf16 packed pairs (coalesced over c-pairs)
    uint32_t* xTb = xnT16 + (size_t)b * LL * (CC / 2);
    #pragma unroll 4
    for (int i = 0; i < 32; i++) {
        int f = tid + i * 256;           // 0..8191 = 32 l x 256 pairs
        int l = f >> 8, cp = f & 255;
        int c0 = cp * 2, c1 = c0 + 1;
        float mean = s_mean[l], rstd = s_rstd[l];
        float v0 = (s[c0 * 33 + l] - mean) * rstd * __ldg(&gamma[c0]) + __ldg(&beta[c0]);
        float v1 = (s[c1 * 33 + l] - mean) * rstd * __ldg(&gamma[c1]) + __ldg(&beta[c1]);
        xTb[(size_t)(l0 + l) * (CC / 2) + cp] = pack_bf16x2(v0, v1);
    }
}

// ---------------- pack weights to bf16 ---------------------------------------
__global__ void pack_bf16_kernel(const float* __restrict__ in, uint32_t* __restrict__ out, int n2)
{
    int i = blockIdx.x * 256 + threadIdx.x;
    if (i < n2) out[i] = pack_bf16x2(in[2 * i], in[2 * i + 1]);
}

// ---------------- bf16 mma.sync GEMM: 128x256 tile, BK=32 --------------------
// C[M,N] = A[M,512] @ B[N,512]^T (bf16 K-major operands, fp32 out).
// smem row = 16 u32 data (32 bf16) + 4 pad = pitch 20 u32 (conflict-free).
#define BP 20
#define A_U32 (128 * BP)             // 2560
#define B_U32 (256 * BP)             // 5120
#define STG_U32 (A_U32 + B_U32)      // 7680
#define GEMM_DYN_SMEM (3 * STG_U32 * 4)   // 92,160 B

template <bool EPI>
__global__ void __launch_bounds__(256)
gemm_bf16_mma(const __nv_bfloat16* __restrict__ A, const __nv_bfloat16* __restrict__ Bmat,
              float* __restrict__ C, size_t strideBz, size_t strideCz,
              const float* __restrict__ bias,
              const float* __restrict__ res, size_t strideRz)
{
    extern __shared__ uint32_t smem32[];

    const int tid = threadIdx.x;
    const int wid = tid >> 5, lane = tid & 31;
    const int g = lane >> 2, t4 = lane & 3;
    const int warp_m = wid >> 2;          // 0..1 (64 rows)
    const int warp_n = wid & 3;           // 0..3 (64 cols)
    const int bx = blockIdx.x, by = blockIdx.y, bz = blockIdx.z;

    const __nv_bfloat16* Abase = A    + (size_t)by * 128 * 512;
    const __nv_bfloat16* Bbase = Bmat + (size_t)bz * strideBz + (size_t)bx * 256 * 512;

    const uint32_t sAu = smem_u32(smem32);

    auto load_tile = [&](int t) {
        int stage = t % 3;
        uint32_t dA = sAu + (uint32_t)(stage * STG_U32) * 4;
        uint32_t dB = dA + A_U32 * 4;
        int k0 = t * 32;                  // bf16 element offset
        #pragma unroll
        for (int i = 0; i < 2; i++) {     // A: 512 16B-chunks
            int f = tid + i * 256;
            int r = f >> 2, j = f & 3;
            cp_async16(dA + (uint32_t)(r * BP + j * 4) * 4,
                       Abase + (size_t)r * 512 + k0 + j * 8);
        }
        #pragma unroll
        for (int i = 0; i < 4; i++) {     // B: 1024 16B-chunks
            int f = tid + i * 256;
            int r = f >> 2, j = f & 3;
            cp_async16(dB + (uint32_t)(r * BP + j * 4) * 4,
                       Bbase + (size_t)r * 512 + k0 + j * 8);
        }
        CP_COMMIT();
    };

    float acc[4][8][4];
    #pragma unroll
    for (int mf = 0; mf < 4; mf++)
        #pragma unroll
        for (int nf = 0; nf < 8; nf++)
            #pragma unroll
            for (int i = 0; i < 4; i++) acc[mf][nf][i] = 0.f;

    load_tile(0); load_tile(1); load_tile(2);

    const int rmb = warp_m * 64;
    const int nbb = warp_n * 64;

    for (int t = 0; t < 16; t++) {
        CP_WAIT(2);
        __syncthreads();
        const uint32_t* As = smem32 + (t % 3) * STG_U32;
        const uint32_t* Bs = As + A_U32;

        #pragma unroll
        for (int ks = 0; ks < 2; ks++) {  // two K=16 steps per BK=32
            const int kb = ks * 8;        // u32-pair offset
            uint32_t af[4][4], bf[8][2];
            #pragma unroll
            for (int mf = 0; mf < 4; mf++) {
                int rm = rmb + mf * 16;
                af[mf][0] = As[(rm + g)     * BP + kb + t4];
                af[mf][1] = As[(rm + g + 8) * BP + kb + t4];
                af[mf][2] = As[(rm + g)     * BP + kb + t4 + 4];
                af[mf][3] = As[(rm + g + 8) * BP + kb + t4 + 4];
            }
            #pragma unroll
            for (int nf = 0; nf < 8; nf++) {
                int nb = nbb + nf * 8;
                bf[nf][0] = Bs[(nb + g) * BP + kb + t4];
                bf[nf][1] = Bs[(nb + g) * BP + kb + t4 + 4];
            }
            #pragma unroll
            for (int mf = 0; mf < 4; mf++)
                #pragma unroll
                for (int nf = 0; nf < 8; nf++)
                    mma_bf16(acc[mf][nf], af[mf], bf[nf]);
        }
        __syncthreads();
        if (t + 3 < 16) load_tile(t + 3);
    }

    // epilogue
    #pragma unroll
    for (int mf = 0; mf < 4; mf++) {
        int row0 = by * 128 + rmb + mf * 16 + g;
        #pragma unroll
        for (int half = 0; half < 2; half++) {
            int row = row0 + half * 8;
            float* crow = C + (size_t)bz * strideCz + (size_t)row * LL + bx * 256;
            const float* rrow = EPI ? (res + (size_t)bz * strideRz + (size_t)row * LL + bx * 256)
                                    : nullptr;
            float bval = EPI ? bias[row] : 0.f;
            #pragma unroll
            for (int nf = 0; nf < 8; nf++) {
                int cn = nbb + nf * 8 + 2 * t4;
                float2 v;
                v.x = acc[mf][nf][half * 2 + 0];
                v.y = acc[mf][nf][half * 2 + 1];
                if (EPI) {
                    float2 rr = *reinterpret_cast<const float2*>(rrow + cn);
                    v.x += bval + rr.x; v.y += bval + rr.y;
                }
                *reinterpret_cast<float2*>(crow + cn) = v;
            }
        }
    }
}

// ---------------- softmax over L (single pass, register-resident) ------------
__global__ void __launch_bounds__(256)
softmax_kernel(float* __restrict__ qkv)
{
    int row = blockIdx.x;
    int b = row >> 9, r = row & 511;
    float* p = qkv + ((size_t)b * 3 + 1) * ((size_t)HID * LL) + (size_t)r * LL;

    const int tid = threadIdx.x;
    __shared__ float shp[8];
    __shared__ float bcast;

    float4 v[4];
    #pragma unroll
    for (int i = 0; i < 4; i++)
        v[i] = reinterpret_cast<const float4*>(p)[tid + i * 256];

    float m = -3.4e38f;
    #pragma unroll
    for (int i = 0; i < 4; i++)
        m = fmaxf(m, fmaxf(fmaxf(v[i].x, v[i].y), fmaxf(v[i].z, v[i].w)));
    #pragma unroll
    for (int o = 16; o; o >>= 1) m = fmaxf(m, __shfl_xor_sync(0xffffffffu, m, o));
    if ((tid & 31) == 0) shp[tid >> 5] = m;
    __syncthreads();
    if (tid < 32) {
        float t = (tid < 8) ? shp[tid] : -3.4e38f;
        #pragma unroll
        for (int o = 4; o; o >>= 1) t = fmaxf(t, __shfl_xor_sync(0xffffffffu, t, o));
        if (tid == 0) bcast = t;
    }
    __syncthreads();
    float M = bcast;
    __syncthreads();

    float s = 0.f;
    #pragma unroll
    for (int i = 0; i < 4; i++) {
        v[i].x = __expf(v[i].x - M); v[i].y = __expf(v[i].y - M);
        v[i].z = __expf(v[i].z - M); v[i].w = __expf(v[i].w - M);
        s += v[i].x + v[i].y + v[i].z + v[i].w;
    }
    #pragma unroll
    for (int o = 16; o; o >>= 1) s += __shfl_xor_sync(0xffffffffu, s, o);
    if ((tid & 31) == 0) shp[tid >> 5] = s;
    __syncthreads();
    if (tid < 32) {
        float t = (tid < 8) ? shp[tid] : 0.f;
        #pragma unroll
        for (int o = 4; o; o >>= 1) t += __shfl_xor_sync(0xffffffffu, t, o);
        if (tid == 0) bcast = t;
    }
    __syncthreads();
    float inv = 1.0f / bcast;

    #pragma unroll
    for (int i = 0; i < 4; i++) {
        v[i].x *= inv; v[i].y *= inv; v[i].z *= inv; v[i].w *= inv;
        reinterpret_cast<float4*>(p)[tid + i * 256] = v[i];
    }
}

// ---------------- context = k @ v^T ------------------------------------------
__global__ void zero_ctx_kernel(float* __restrict__ ctx, int off)
{
    ctx[off + blockIdx.x * 256 + threadIdx.x] = 0.f;
}

__global__ void __launch_bounds__(256)
ctx_kernel(const float* __restrict__ qkv, float* __restrict__ ctx)
{
    const int chunk = blockIdx.x;
    const int h = blockIdx.y, b = blockIdx.z;

    const float* kp = qkv + ((size_t)b * 3 + 1) * ((size_t)HID * LL) + (size_t)h * DH * LL;
    const float* vp = qkv + ((size_t)b * 3 + 2) * ((size_t)HID * LL) + (size_t)h * DH * LL;

    __shared__ float ksT[64][65];
    __shared__ float vsT[64][65];

    const int tid = threadIdx.x;
    const int ty = tid >> 4, tx = tid & 15;

    float acc[4][4];
    #pragma unroll
    for (int i = 0; i < 4; i++)
        #pragma unroll
        for (int j = 0; j < 4; j++) acc[i][j] = 0.f;

    for (int t = 0; t < 8; t++) {
        int n0 = chunk * 512 + t * 64;
        #pragma unroll
        for (int i = 0; i < 16; i++) {
            int f = tid + i * 256;
            int d = f >> 6, nn = f & 63;
            ksT[nn][d] = kp[(size_t)d * LL + n0 + nn];
            vsT[nn][d] = vp[(size_t)d * LL + n0 + nn];
        }
        __syncthreads();
        #pragma unroll 8
        for (int n = 0; n < 64; n++) {
            float af[4], bf[4];
            #pragma unroll
            for (int i = 0; i < 4; i++) af[i] = ksT[n][ty * 4 + i];
            #pragma unroll
            for (int j = 0; j < 4; j++) bf[j] = vsT[n][tx * 4 + j];
            #pragma unroll
            for (int i = 0; i < 4; i++)
                #pragma unroll
                for (int j = 0; j < 4; j++)
                    acc[i][j] = fmaf(af[i], bf[j], acc[i][j]);
        }
        __syncthreads();
    }

    float* cbase = ctx + ((size_t)(b * NH + h)) * DH * DH;
    #pragma unroll
    for (int i = 0; i < 4; i++)
        #pragma unroll
        for (int j = 0; j < 4; j++)
            atomicAdd(&cbase[(size_t)(ty * 4 + i) * DH + tx * 4 + j], acc[i][j]);
}

// ---------------- attnT[l, hid] = (SCALE * ctx^T @ q)^T, bf16-packed ---------
__global__ void __launch_bounds__(256)
attn_out_kernel(const float* __restrict__ qkv, const float* __restrict__ ctx,
                uint32_t* __restrict__ attnT16)
{
    const int nt = blockIdx.x;
    const int h = blockIdx.y, b = blockIdx.z;
    const int n0 = nt * 128;

    const float* qp = qkv + (size_t)b * 3 * HID * LL + (size_t)h * DH * LL;
    const float* cp = ctx + ((size_t)(b * NH + h)) * DH * DH;

    __shared__ union {
        struct { float cs[64][64]; float qs[64][128]; } a;
        float os[128][65];
    } sm;

    const int tid = threadIdx.x;

    #pragma unroll
    for (int i = 0; i < 4; i++) {
        int f = tid + i * 256;
        reinterpret_cast<float4*>(&sm.a.cs[0][0])[f] = reinterpret_cast<const float4*>(cp)[f];
    }
    #pragma unroll
    for (int i = 0; i < 8; i++) {
        int f = tid + i * 256;
        int d = f >> 5, c4 = (f & 31) * 4;
        float4 v = *reinterpret_cast<const float4*>(qp + (size_t)d * LL + n0 + c4);
        *reinterpret_cast<float4*>(&sm.a.qs[d][c4]) = v;
    }
    __syncthreads();

    const int ty = tid >> 5, tx = tid & 31;

    float acc[8][4];
    #pragma unroll
    for (int i = 0; i < 8; i++)
        #pragma unroll
        for (int j = 0; j < 4; j++) acc[i][j] = 0.f;

    #pragma unroll 8
    for (int d = 0; d < 64; d++) {
        float qf[4], cf[8];
        #pragma unroll
        for (int j = 0; j < 4; j++) qf[j] = sm.a.qs[d][tx * 4 + j];
        #pragma unroll
        for (int i = 0; i < 8; i++) cf[i] = sm.a.cs[d][ty * 8 + i];
        #pragma unroll
        for (int i = 0; i < 8; i++)
            #pragma unroll
            for (int j = 0; j < 4; j++)
                acc[i][j] = fmaf(cf[i], qf[j], acc[i][j]);
    }

    __syncthreads();

    #pragma unroll
    for (int i = 0; i < 8; i++)
        #pragma unroll
        for (int j = 0; j < 4; j++)
            sm.os[tx * 4 + j][ty * 8 + i] = acc[i][j] * SCALEV;
    __syncthreads();

    // write bf16 pairs: 128 rows x 32 u32 (64 bf16 cols per head)
    #pragma unroll
    for (int i = 0; i < 16; i++) {
        int f = tid + i * 256;
        int r = f >> 5, cpx = f & 31;
        uint32_t u = pack_bf16x2(sm.os[r][cpx * 2], sm.os[r][cpx * 2 + 1]);
        attnT16[((size_t)b * LL + n0 + r) * (HID / 2) + h * (DH / 2) + cpx] = u;
    }
}

// ---------------- launch ------------------------------------------------------
extern "C" void kernel_launch(void* const* d_in, const int* in_sizes, int n_in,
                              void* d_out, int out_size)
{
    const float* x     = (const float*)d_in[0];
    const float* gamma = (const float*)d_in[1];
    const float* beta  = (const float*)d_in[2];
    const float* w_qkv = (const float*)d_in[3];
    const float* w_out = (const float*)d_in[4];
    const float* b_out = (const float*)d_in[5];
    float* out = (float*)d_out;

    float *xn, *qkv, *ctx;
    uint32_t *xnT16, *attnT16, *wq16, *wo16;
    cudaGetSymbolAddress((void**)&xn,      g_xn);
    cudaGetSymbolAddress((void**)&xnT16,   g_xnT16);
    cudaGetSymbolAddress((void**)&qkv,     g_qkv);
    cudaGetSymbolAddress((void**)&ctx,     g_ctx);
    cudaGetSymbolAddress((void**)&attnT16, g_attnT16);
    cudaGetSymbolAddress((void**)&wq16,    g_wq16);
    cudaGetSymbolAddress((void**)&wo16,    g_wo16);

    cudaFuncSetAttribute(gemm_bf16_mma<false>, cudaFuncAttributeMaxDynamicSharedMemorySize, GEMM_DYN_SMEM);
    cudaFuncSetAttribute(gemm_bf16_mma<true>,  cudaFuncAttributeMaxDynamicSharedMemorySize, GEMM_DYN_SMEM);
    cudaFuncSetAttribute(ln_fused_kernel,      cudaFuncAttributeMaxDynamicSharedMemorySize, LN_SMEM);

    const int CTX_N = BB * NH * DH * DH;

    pack_bf16_kernel<<<(3 * HID * CC / 2 + 255) / 256, 256>>>(w_qkv, wq16, 3 * HID * CC / 2);
    pack_bf16_kernel<<<(CC * HID / 2 + 255) / 256, 256>>>(w_out, wo16, CC * HID / 2);
    zero_ctx_kernel<<<CTX_N / 512, 256>>>(ctx, 0);
    zero_ctx_kernel<<<CTX_N / 512, 256>>>(ctx, CTX_N / 2);
    ln_fused_kernel<<<dim3(LL / 32, BB), 256, LN_SMEM>>>(x, gamma, beta, xn, xnT16);

    // QKV GEMM (bf16): [1536 x 4096 x 512] per batch
    gemm_bf16_mma<false><<<dim3(LL / 256, (3 * HID) / 128, BB), 256, GEMM_DYN_SMEM>>>(
        (const __nv_bfloat16*)wq16, (const __nv_bfloat16*)xnT16, qkv,
        (size_t)LL * CC, (size_t)3 * HID * LL, nullptr, nullptr, 0);

    softmax_kernel<<<BB * HID, 256>>>(qkv);
    ctx_kernel<<<dim3(8, NH, BB), 256>>>(qkv, ctx);
    attn_out_kernel<<<dim3(LL / 128, NH, BB), 256>>>(qkv, ctx, attnT16);

    // OUT GEMM (bf16) + bias + residual
    gemm_bf16_mma<true><<<dim3(LL / 256, HID / 128, BB), 256, GEMM_DYN_SMEM>>>(
        (const __nv_bfloat16*)wo16, (const __nv_bfloat16*)attnT16, out,
        (size_t)LL * HID, (size_t)HID * LL, b_out, xn, (size_t)CC * LL);
}

// round 8
// speedup vs baseline: 2.9525x; 1.0163x over previous
#include <cuda_runtime.h>
#include <cuda_bf16.h>
#include <cstdint>
#include <cstddef>

// Problem constants
#define BB   8
#define CC   512
#define LL   4096
#define HID  512
#define NH   8
#define DH   64
#define EPSV 1e-5f
#define SCALEV 0.125f

// ---------------- scratch (device globals) ----------------------------------
__device__ float    g_xn   [(size_t)BB * CC * LL];        // 64 MB fp32 residual
__device__ uint32_t g_xnT16[(size_t)BB * LL * (CC/2)];    // 32 MB xn^T bf16 [L, C]
__device__ float    g_qkv  [(size_t)BB * 3 * HID * LL];   // 192 MB qkv fp32
__device__ float    g_ctx  [(size_t)BB * NH * DH * DH];   // 1 MB context
__device__ uint32_t g_attnT16[(size_t)BB * LL * (HID/2)]; // 32 MB attn^T bf16 [L, HID]
__device__ uint32_t g_wq16 [(size_t)3 * HID * CC / 2];    // 1.5 MB w_qkv bf16
__device__ uint32_t g_wo16 [(size_t)CC * HID / 2];        // 0.5 MB w_out bf16

// ---------------- helpers ----------------------------------------------------
__device__ __forceinline__ uint32_t smem_u32(const void* p) {
    uint32_t a;
    asm("{ .reg .u64 t; cvta.to.shared.u64 t, %1; cvt.u32.u64 %0, t; }" : "=r"(a) : "l"(p));
    return a;
}
__device__ __forceinline__ uint32_t pack_bf16x2(float lo, float hi) {
    __nv_bfloat162 h = __floats2bfloat162_rn(lo, hi);
    return *reinterpret_cast<uint32_t*>(&h);
}
__device__ __forceinline__ void cp_async16(uint32_t saddr, const void* g) {
    asm volatile("cp.async.cg.shared.global [%0], [%1], 16;" :: "r"(saddr), "l"(g));
}
#define CP_COMMIT() asm volatile("cp.async.commit_group;" ::: "memory")
#define CP_WAIT(n)  asm volatile("cp.async.wait_group %0;" :: "n"(n) : "memory")

__device__ __forceinline__ void ldsm_x4(uint32_t& r0, uint32_t& r1, uint32_t& r2, uint32_t& r3,
                                        uint32_t addr)
{
    asm volatile("ldmatrix.sync.aligned.m8n8.x4.shared.b16 {%0,%1,%2,%3}, [%4];"
                 : "=r"(r0), "=r"(r1), "=r"(r2), "=r"(r3) : "r"(addr));
}

// m16n8k16 bf16 warp MMA
__device__ __forceinline__ void mma_bf16(float* c, const uint32_t* a, const uint32_t* b)
{
    asm volatile(
        "mma.sync.aligned.m16n8k16.row.col.f32.bf16.bf16.f32 "
        "{%0,%1,%2,%3}, {%4,%5,%6,%7}, {%8,%9}, {%0,%1,%2,%3};"
        : "+f"(c[0]), "+f"(c[1]), "+f"(c[2]), "+f"(c[3])
        : "r"(a[0]), "r"(a[1]), "r"(a[2]), "r"(a[3]), "r"(b[0]), "r"(b[1]));
}

// ---------------- fused LayerNorm: xn[C,L] fp32 + xnT[L,C] bf16 --------------
#define LN_SMEM (512 * 33 * 4)
__global__ void __launch_bounds__(256)
ln_fused_kernel(const float* __restrict__ x,
                const float* __restrict__ gamma,
                const float* __restrict__ beta,
                float* __restrict__ xn, uint32_t* __restrict__ xnT16)
{
    extern __shared__ float s[];           // [512][33]
    __shared__ float ps[8][32], pss[8][32];
    __shared__ float s_mean[32], s_rstd[32];

    const int tid = threadIdx.x, wid = tid >> 5, lane = tid & 31;
    const int l0 = blockIdx.x * 32, b = blockIdx.y;
    const float* xb = x + (size_t)b * CC * LL;

    #pragma unroll 4
    for (int it = 0; it < 64; it++) {
        int c = it * 8 + wid;
        s[c * 33 + lane] = xb[(size_t)c * LL + l0 + lane];
    }
    __syncthreads();

    {
        int l = lane, ch = wid;
        float sum = 0.f, ssum = 0.f;
        #pragma unroll 8
        for (int c = ch * 64; c < ch * 64 + 64; c++) {
            float v = s[c * 33 + l];
            sum += v; ssum += v * v;
        }
        ps[ch][l] = sum; pss[ch][l] = ssum;
    }
    __syncthreads();
    if (tid < 32) {
        float sum = 0.f, ssum = 0.f;
        #pragma unroll
        for (int ch = 0; ch < 8; ch++) { sum += ps[ch][tid]; ssum += pss[ch][tid]; }
        float mean = sum * (1.0f / CC);
        float var  = ssum * (1.0f / CC) - mean * mean;
        s_mean[tid] = mean;
        s_rstd[tid] = rsqrtf(var + EPSV);
    }
    __syncthreads();

    float* xnb = xn + (size_t)b * CC * LL;
    {
        float mean = s_mean[lane], rstd = s_rstd[lane];
        #pragma unroll 4
        for (int it = 0; it < 64; it++) {
            int c = it * 8 + wid;
            float v = (s[c * 33 + lane] - mean) * rstd * __ldg(&gamma[c]) + __ldg(&beta[c]);
            xnb[(size_t)c * LL + l0 + lane] = v;
        }
    }

    uint32_t* xTb = xnT16 + (size_t)b * LL * (CC / 2);
    #pragma unroll 4
    for (int i = 0; i < 32; i++) {
        int f = tid + i * 256;
        int l = f >> 8, cp = f & 255;
        int c0 = cp * 2, c1 = c0 + 1;
        float mean = s_mean[l], rstd = s_rstd[l];
        float v0 = (s[c0 * 33 + l] - mean) * rstd * __ldg(&gamma[c0]) + __ldg(&beta[c0]);
        float v1 = (s[c1 * 33 + l] - mean) * rstd * __ldg(&gamma[c1]) + __ldg(&beta[c1]);
        xTb[(size_t)(l0 + l) * (CC / 2) + cp] = pack_bf16x2(v0, v1);
    }
}

// ---------------- pack weights to bf16 ---------------------------------------
__global__ void pack_bf16_kernel(const float* __restrict__ in, uint32_t* __restrict__ out, int n2)
{
    int i = blockIdx.x * 256 + threadIdx.x;
    if (i < n2) out[i] = pack_bf16x2(in[2 * i], in[2 * i + 1]);
}

// ---------------- bf16 mma.sync GEMM: 128x256 tile, BK=32, ldmatrix ---------
// smem row = 16 u32 data (32 bf16) + 4 pad = pitch 20 u32 (LDSM conflict-free:
// r*20 mod 32 spans all eight 4-bank groups).
#define BP 20
#define A_U32 (128 * BP)
#define B_U32 (256 * BP)
#define STG_U32 (A_U32 + B_U32)
#define GEMM_DYN_SMEM (3 * STG_U32 * 4)   // 92,160 B

template <bool EPI>
__global__ void __launch_bounds__(256)
gemm_bf16_mma(const __nv_bfloat16* __restrict__ A, const __nv_bfloat16* __restrict__ Bmat,
              float* __restrict__ C, size_t strideBz, size_t strideCz,
              const float* __restrict__ bias,
              const float* __restrict__ res, size_t strideRz)
{
    extern __shared__ uint32_t smem32[];

    const int tid = threadIdx.x;
    const int wid = tid >> 5, lane = tid & 31;
    const int g = lane >> 2, t4 = lane & 3;
    const int sel = lane >> 3, wi = lane & 7;   // ldmatrix lane roles
    const int warp_m = wid >> 2;
    const int warp_n = wid & 3;
    const int bx = blockIdx.x, by = blockIdx.y, bz = blockIdx.z;

    const __nv_bfloat16* Abase = A    + (size_t)by * 128 * 512;
    const __nv_bfloat16* Bbase = Bmat + (size_t)bz * strideBz + (size_t)bx * 256 * 512;

    const uint32_t sAu = smem_u32(smem32);
    const int rmb = warp_m * 64;
    const int nbb = warp_n * 64;

    // per-lane ldmatrix byte offsets within a stage (row*80 + chunk*16)
    // A frag (mf, ks): row = rmb + mf*16 + wi + (sel&1)*8, chunk = ks*2 + (sel>>1)
    // B frag (nf2,ks): row = nbb + nf2*16 + wi + (sel>>1)*8, chunk = ks*2 + (sel&1)
    const uint32_t a_off = (uint32_t)(rmb + wi + (sel & 1) * 8) * 80u + (uint32_t)(sel >> 1) * 16u;
    const uint32_t b_off = (uint32_t)(nbb + wi + (sel >> 1) * 8) * 80u + (uint32_t)(sel & 1) * 16u;

    auto load_tile = [&](int t) {
        int stage = t % 3;
        uint32_t dA = sAu + (uint32_t)(stage * STG_U32) * 4;
        uint32_t dB = dA + A_U32 * 4;
        int k0 = t * 32;
        #pragma unroll
        for (int i = 0; i < 2; i++) {
            int f = tid + i * 256;
            int r = f >> 2, j = f & 3;
            cp_async16(dA + (uint32_t)(r * BP + j * 4) * 4,
                       Abase + (size_t)r * 512 + k0 + j * 8);
        }
        #pragma unroll
        for (int i = 0; i < 4; i++) {
            int f = tid + i * 256;
            int r = f >> 2, j = f & 3;
            cp_async16(dB + (uint32_t)(r * BP + j * 4) * 4,
                       Bbase + (size_t)r * 512 + k0 + j * 8);
        }
        CP_COMMIT();
    };

    float acc[4][8][4];
    #pragma unroll
    for (int mf = 0; mf < 4; mf++)
        #pragma unroll
        for (int nf = 0; nf < 8; nf++)
            #pragma unroll
            for (int i = 0; i < 4; i++) acc[mf][nf][i] = 0.f;

    load_tile(0); load_tile(1); load_tile(2);

    for (int t = 0; t < 16; t++) {
        CP_WAIT(2);
        __syncthreads();
        uint32_t stg = sAu + (uint32_t)((t % 3) * STG_U32) * 4;
        uint32_t aB = stg + a_off;
        uint32_t bB = stg + A_U32 * 4 + b_off;

        #pragma unroll
        for (int ks = 0; ks < 2; ks++) {
            uint32_t kso = (uint32_t)ks * 32u;
            uint32_t af[4][4], bf[8][2];
            #pragma unroll
            for (int mf = 0; mf < 4; mf++)
                ldsm_x4(af[mf][0], af[mf][1], af[mf][2], af[mf][3],
                        aB + (uint32_t)mf * (16u * 80u) + kso);
            #pragma unroll
            for (int nf2 = 0; nf2 < 4; nf2++)
                ldsm_x4(bf[nf2*2][0], bf[nf2*2][1], bf[nf2*2+1][0], bf[nf2*2+1][1],
                        bB + (uint32_t)nf2 * (16u * 80u) + kso);
            #pragma unroll
            for (int mf = 0; mf < 4; mf++)
                #pragma unroll
                for (int nf = 0; nf < 8; nf++)
                    mma_bf16(acc[mf][nf], af[mf], bf[nf]);
        }
        __syncthreads();
        if (t + 3 < 16) load_tile(t + 3);
    }

    // epilogue
    #pragma unroll
    for (int mf = 0; mf < 4; mf++) {
        int row0 = by * 128 + rmb + mf * 16 + g;
        #pragma unroll
        for (int half = 0; half < 2; half++) {
            int row = row0 + half * 8;
            float* crow = C + (size_t)bz * strideCz + (size_t)row * LL + bx * 256;
            const float* rrow = EPI ? (res + (size_t)bz * strideRz + (size_t)row * LL + bx * 256)
                                    : nullptr;
            float bval = EPI ? bias[row] : 0.f;
            #pragma unroll
            for (int nf = 0; nf < 8; nf++) {
                int cn = nbb + nf * 8 + 2 * t4;
                float2 v;
                v.x = acc[mf][nf][half * 2 + 0];
                v.y = acc[mf][nf][half * 2 + 1];
                if (EPI) {
                    float2 rr = *reinterpret_cast<const float2*>(rrow + cn);
                    v.x += bval + rr.x; v.y += bval + rr.y;
                }
                *reinterpret_cast<float2*>(crow + cn) = v;
            }
        }
    }
}

// ---------------- softmax over L ---------------------------------------------
__global__ void __launch_bounds__(256)
softmax_kernel(float* __restrict__ qkv)
{
    int row = blockIdx.x;
    int b = row >> 9, r = row & 511;
    float* p = qkv + ((size_t)b * 3 + 1) * ((size_t)HID * LL) + (size_t)r * LL;

    const int tid = threadIdx.x;
    __shared__ float shp[8];
    __shared__ float bcast;

    float4 v[4];
    #pragma unroll
    for (int i = 0; i < 4; i++)
        v[i] = reinterpret_cast<const float4*>(p)[tid + i * 256];

    float m = -3.4e38f;
    #pragma unroll
    for (int i = 0; i < 4; i++)
        m = fmaxf(m, fmaxf(fmaxf(v[i].x, v[i].y), fmaxf(v[i].z, v[i].w)));
    #pragma unroll
    for (int o = 16; o; o >>= 1) m = fmaxf(m, __shfl_xor_sync(0xffffffffu, m, o));
    if ((tid & 31) == 0) shp[tid >> 5] = m;
    __syncthreads();
    if (tid < 32) {
        float t = (tid < 8) ? shp[tid] : -3.4e38f;
        #pragma unroll
        for (int o = 4; o; o >>= 1) t = fmaxf(t, __shfl_xor_sync(0xffffffffu, t, o));
        if (tid == 0) bcast = t;
    }
    __syncthreads();
    float M = bcast;
    __syncthreads();

    float s = 0.f;
    #pragma unroll
    for (int i = 0; i < 4; i++) {
        v[i].x = __expf(v[i].x - M); v[i].y = __expf(v[i].y - M);
        v[i].z = __expf(v[i].z - M); v[i].w = __expf(v[i].w - M);
        s += v[i].x + v[i].y + v[i].z + v[i].w;
    }
    #pragma unroll
    for (int o = 16; o; o >>= 1) s += __shfl_xor_sync(0xffffffffu, s, o);
    if ((tid & 31) == 0) shp[tid >> 5] = s;
    __syncthreads();
    if (tid < 32) {
        float t = (tid < 8) ? shp[tid] : 0.f;
        #pragma unroll
        for (int o = 4; o; o >>= 1) t += __shfl_xor_sync(0xffffffffu, t, o);
        if (tid == 0) bcast = t;
    }
    __syncthreads();
    float inv = 1.0f / bcast;

    #pragma unroll
    for (int i = 0; i < 4; i++) {
        v[i].x *= inv; v[i].y *= inv; v[i].z *= inv; v[i].w *= inv;
        reinterpret_cast<float4*>(p)[tid + i * 256] = v[i];
    }
}

// ---------------- context = k @ v^T ------------------------------------------
__global__ void zero_ctx_kernel(float* __restrict__ ctx, int off)
{
    ctx[off + blockIdx.x * 256 + threadIdx.x] = 0.f;
}

__global__ void __launch_bounds__(256)
ctx_kernel(const float* __restrict__ qkv, float* __restrict__ ctx)
{
    const int chunk = blockIdx.x;
    const int h = blockIdx.y, b = blockIdx.z;

    const float* kp = qkv + ((size_t)b * 3 + 1) * ((size_t)HID * LL) + (size_t)h * DH * LL;
    const float* vp = qkv + ((size_t)b * 3 + 2) * ((size_t)HID * LL) + (size_t)h * DH * LL;

    __shared__ float ksT[64][65];
    __shared__ float vsT[64][65];

    const int tid = threadIdx.x;
    const int ty = tid >> 4, tx = tid & 15;

    float acc[4][4];
    #pragma unroll
    for (int i = 0; i < 4; i++)
        #pragma unroll
        for (int j = 0; j < 4; j++) acc[i][j] = 0.f;

    for (int t = 0; t < 8; t++) {
        int n0 = chunk * 512 + t * 64;
        #pragma unroll
        for (int i = 0; i < 16; i++) {
            int f = tid + i * 256;
            int d = f >> 6, nn = f & 63;
            ksT[nn][d] = kp[(size_t)d * LL + n0 + nn];
            vsT[nn][d] = vp[(size_t)d * LL + n0 + nn];
        }
        __syncthreads();
        #pragma unroll 8
        for (int n = 0; n < 64; n++) {
            float af[4], bf[4];
            #pragma unroll
            for (int i = 0; i < 4; i++) af[i] = ksT[n][ty * 4 + i];
            #pragma unroll
            for (int j = 0; j < 4; j++) bf[j] = vsT[n][tx * 4 + j];
            #pragma unroll
            for (int i = 0; i < 4; i++)
                #pragma unroll
                for (int j = 0; j < 4; j++)
                    acc[i][j] = fmaf(af[i], bf[j], acc[i][j]);
        }
        __syncthreads();
    }

    float* cbase = ctx + ((size_t)(b * NH + h)) * DH * DH;
    #pragma unroll
    for (int i = 0; i < 4; i++)
        #pragma unroll
        for (int j = 0; j < 4; j++)
            atomicAdd(&cbase[(size_t)(ty * 4 + i) * DH + tx * 4 + j], acc[i][j]);
}

// ---------------- attnT[l, hid] = (SCALE * ctx^T @ q)^T, bf16-packed ---------
__global__ void __launch_bounds__(256)
attn_out_kernel(const float* __restrict__ qkv, const float* __restrict__ ctx,
                uint32_t* __restrict__ attnT16)
{
    const int nt = blockIdx.x;
    const int h = blockIdx.y, b = blockIdx.z;
    const int n0 = nt * 128;

    const float* qp = qkv + (size_t)b * 3 * HID * LL + (size_t)h * DH * LL;
    const float* cp = ctx + ((size_t)(b * NH + h)) * DH * DH;

    __shared__ union {
        struct { float cs[64][64]; float qs[64][128]; } a;
        float os[128][65];
    } sm;

    const int tid = threadIdx.x;

    #pragma unroll
    for (int i = 0; i < 4; i++) {
        int f = tid + i * 256;
        reinterpret_cast<float4*>(&sm.a.cs[0][0])[f] = reinterpret_cast<const float4*>(cp)[f];
    }
    #pragma unroll
    for (int i = 0; i < 8; i++) {
        int f = tid + i * 256;
        int d = f >> 5, c4 = (f & 31) * 4;
        float4 v = *reinterpret_cast<const float4*>(qp + (size_t)d * LL + n0 + c4);
        *reinterpret_cast<float4*>(&sm.a.qs[d][c4]) = v;
    }
    __syncthreads();

    const int ty = tid >> 5, tx = tid & 31;

    float acc[8][4];
    #pragma unroll
    for (int i = 0; i < 8; i++)
        #pragma unroll
        for (int j = 0; j < 4; j++) acc[i][j] = 0.f;

    #pragma unroll 8
    for (int d = 0; d < 64; d++) {
        float qf[4], cf[8];
        #pragma unroll
        for (int j = 0; j < 4; j++) qf[j] = sm.a.qs[d][tx * 4 + j];
        #pragma unroll
        for (int i = 0; i < 8; i++) cf[i] = sm.a.cs[d][ty * 8 + i];
        #pragma unroll
        for (int i = 0; i < 8; i++)
            #pragma unroll
            for (int j = 0; j < 4; j++)
                acc[i][j] = fmaf(cf[i], qf[j], acc[i][j]);
    }

    __syncthreads();

    #pragma unroll
    for (int i = 0; i < 8; i++)
        #pragma unroll
        for (int j = 0; j < 4; j++)
            sm.os[tx * 4 + j][ty * 8 + i] = acc[i][j] * SCALEV;
    __syncthreads();

    #pragma unroll
    for (int i = 0; i < 16; i++) {
        int f = tid + i * 256;
        int r = f >> 5, cpx = f & 31;
        uint32_t u = pack_bf16x2(sm.os[r][cpx * 2], sm.os[r][cpx * 2 + 1]);
        attnT16[((size_t)b * LL + n0 + r) * (HID / 2) + h * (DH / 2) + cpx] = u;
    }
}

// ---------------- launch ------------------------------------------------------
extern "C" void kernel_launch(void* const* d_in, const int* in_sizes, int n_in,
                              void* d_out, int out_size)
{
    const float* x     = (const float*)d_in[0];
    const float* gamma = (const float*)d_in[1];
    const float* beta  = (const float*)d_in[2];
    const float* w_qkv = (const float*)d_in[3];
    const float* w_out = (const float*)d_in[4];
    const float* b_out = (const float*)d_in[5];
    float* out = (float*)d_out;

    float *xn, *qkv, *ctx;
    uint32_t *xnT16, *attnT16, *wq16, *wo16;
    cudaGetSymbolAddress((void**)&xn,      g_xn);
    cudaGetSymbolAddress((void**)&xnT16,   g_xnT16);
    cudaGetSymbolAddress((void**)&qkv,     g_qkv);
    cudaGetSymbolAddress((void**)&ctx,     g_ctx);
    cudaGetSymbolAddress((void**)&attnT16, g_attnT16);
    cudaGetSymbolAddress((void**)&wq16,    g_wq16);
    cudaGetSymbolAddress((void**)&wo16,    g_wo16);

    cudaFuncSetAttribute(gemm_bf16_mma<false>, cudaFuncAttributeMaxDynamicSharedMemorySize, GEMM_DYN_SMEM);
    cudaFuncSetAttribute(gemm_bf16_mma<true>,  cudaFuncAttributeMaxDynamicSharedMemorySize, GEMM_DYN_SMEM);
    cudaFuncSetAttribute(ln_fused_kernel,      cudaFuncAttributeMaxDynamicSharedMemorySize, LN_SMEM);

    const int CTX_N = BB * NH * DH * DH;

    pack_bf16_kernel<<<(3 * HID * CC / 2 + 255) / 256, 256>>>(w_qkv, wq16, 3 * HID * CC / 2);
    pack_bf16_kernel<<<(CC * HID / 2 + 255) / 256, 256>>>(w_out, wo16, CC * HID / 2);
    zero_ctx_kernel<<<CTX_N / 512, 256>>>(ctx, 0);
    zero_ctx_kernel<<<CTX_N / 512, 256>>>(ctx, CTX_N / 2);
    ln_fused_kernel<<<dim3(LL / 32, BB), 256, LN_SMEM>>>(x, gamma, beta, xn, xnT16);

    gemm_bf16_mma<false><<<dim3(LL / 256, (3 * HID) / 128, BB), 256, GEMM_DYN_SMEM>>>(
        (const __nv_bfloat16*)wq16, (const __nv_bfloat16*)xnT16, qkv,
        (size_t)LL * CC, (size_t)3 * HID * LL, nullptr, nullptr, 0);

    softmax_kernel<<<BB * HID, 256>>>(qkv);
    ctx_kernel<<<dim3(8, NH, BB), 256>>>(qkv, ctx);
    attn_out_kernel<<<dim3(LL / 128, NH, BB), 256>>>(qkv, ctx, attnT16);

    gemm_bf16_mma<true><<<dim3(LL / 256, HID / 128, BB), 256, GEMM_DYN_SMEM>>>(
        (const __nv_bfloat16*)wo16, (const __nv_bfloat16*)attnT16, out,
        (size_t)LL * HID, (size_t)HID * LL, b_out, xn, (size_t)CC * LL);
}

// round 9
// speedup vs baseline: 3.3971x; 1.1506x over previous
#include <cuda_runtime.h>
#include <cuda_bf16.h>
#include <cstdint>
#include <cstddef>

// Problem constants
#define BB   8
#define CC   512
#define LL   4096
#define HID  512
#define NH   8
#define DH   64
#define EPSV 1e-5f
#define SCALEV 0.125f

// ---------------- scratch (device globals) ----------------------------------
__device__ float    g_xn   [(size_t)BB * CC * LL];        // 64 MB fp32 residual
__device__ uint32_t g_xnT16[(size_t)BB * LL * (CC/2)];    // 32 MB xn^T bf16 [L,C]
__device__ uint32_t g_qkv16[(size_t)BB * 3 * HID * (LL/2)]; // 96 MB qkv bf16
__device__ float2   g_stats[(size_t)BB * HID];            // k-row softmax stats
__device__ float    g_ctx  [(size_t)BB * NH * DH * DH];   // 1 MB context
__device__ uint32_t g_attnT16[(size_t)BB * LL * (HID/2)]; // 32 MB attn^T bf16
__device__ uint32_t g_wq16 [(size_t)3 * HID * CC / 2];
__device__ uint32_t g_wo16 [(size_t)CC * HID / 2];

// ---------------- helpers ----------------------------------------------------
__device__ __forceinline__ uint32_t smem_u32(const void* p) {
    uint32_t a;
    asm("{ .reg .u64 t; cvta.to.shared.u64 t, %1; cvt.u32.u64 %0, t; }" : "=r"(a) : "l"(p));
    return a;
}
__device__ __forceinline__ uint32_t pack_bf16x2(float lo, float hi) {
    __nv_bfloat162 h = __floats2bfloat162_rn(lo, hi);
    return *reinterpret_cast<uint32_t*>(&h);
}
__device__ __forceinline__ float2 unpack_bf16x2(uint32_t u) {
    __nv_bfloat162 h = *reinterpret_cast<__nv_bfloat162*>(&u);
    return make_float2(__bfloat162float(h.x), __bfloat162float(h.y));
}
__device__ __forceinline__ void cp_async16(uint32_t saddr, const void* g) {
    asm volatile("cp.async.cg.shared.global [%0], [%1], 16;" :: "r"(saddr), "l"(g));
}
#define CP_COMMIT() asm volatile("cp.async.commit_group;" ::: "memory")
#define CP_WAIT(n)  asm volatile("cp.async.wait_group %0;" :: "n"(n) : "memory")

__device__ __forceinline__ void ldsm_x4(uint32_t& r0, uint32_t& r1, uint32_t& r2, uint32_t& r3,
                                        uint32_t addr)
{
    asm volatile("ldmatrix.sync.aligned.m8n8.x4.shared.b16 {%0,%1,%2,%3}, [%4];"
                 : "=r"(r0), "=r"(r1), "=r"(r2), "=r"(r3) : "r"(addr));
}

__device__ __forceinline__ void mma_bf16(float* c, const uint32_t* a, const uint32_t* b)
{
    asm volatile(
        "mma.sync.aligned.m16n8k16.row.col.f32.bf16.bf16.f32 "
        "{%0,%1,%2,%3}, {%4,%5,%6,%7}, {%8,%9}, {%0,%1,%2,%3};"
        : "+f"(c[0]), "+f"(c[1]), "+f"(c[2]), "+f"(c[3])
        : "r"(a[0]), "r"(a[1]), "r"(a[2]), "r"(a[3]), "r"(b[0]), "r"(b[1]));
}

// swizzled byte offset inside an operand region: 64B logical rows, 128B lines,
// 16B chunk XOR'd by line index (conflict-free for ldmatrix + cp.async).
__device__ __forceinline__ uint32_t swz(int r, int j) {
    return (uint32_t)(((r >> 1) * 128) + ((((((r & 1) << 2) | j) ^ ((r >> 1) & 7)) << 4)));
}

// ---------------- fused LayerNorm: xn[C,L] fp32 + xnT[L,C] bf16 --------------
#define LN_SMEM (512 * 33 * 4)
__global__ void __launch_bounds__(256)
ln_fused_kernel(const float* __restrict__ x,
                const float* __restrict__ gamma,
                const float* __restrict__ beta,
                float* __restrict__ xn, uint32_t* __restrict__ xnT16)
{
    extern __shared__ float s[];
    __shared__ float ps[8][32], pss[8][32];
    __shared__ float s_mean[32], s_rstd[32];

    const int tid = threadIdx.x, wid = tid >> 5, lane = tid & 31;
    const int l0 = blockIdx.x * 32, b = blockIdx.y;
    const float* xb = x + (size_t)b * CC * LL;

    #pragma unroll 4
    for (int it = 0; it < 64; it++) {
        int c = it * 8 + wid;
        s[c * 33 + lane] = xb[(size_t)c * LL + l0 + lane];
    }
    __syncthreads();

    {
        int l = lane, ch = wid;
        float sum = 0.f, ssum = 0.f;
        #pragma unroll 8
        for (int c = ch * 64; c < ch * 64 + 64; c++) {
            float v = s[c * 33 + l];
            sum += v; ssum += v * v;
        }
        ps[ch][l] = sum; pss[ch][l] = ssum;
    }
    __syncthreads();
    if (tid < 32) {
        float sum = 0.f, ssum = 0.f;
        #pragma unroll
        for (int ch = 0; ch < 8; ch++) { sum += ps[ch][tid]; ssum += pss[ch][tid]; }
        float mean = sum * (1.0f / CC);
        float var  = ssum * (1.0f / CC) - mean * mean;
        s_mean[tid] = mean;
        s_rstd[tid] = rsqrtf(var + EPSV);
    }
    __syncthreads();

    float* xnb = xn + (size_t)b * CC * LL;
    {
        float mean = s_mean[lane], rstd = s_rstd[lane];
        #pragma unroll 4
        for (int it = 0; it < 64; it++) {
            int c = it * 8 + wid;
            float v = (s[c * 33 + lane] - mean) * rstd * __ldg(&gamma[c]) + __ldg(&beta[c]);
            xnb[(size_t)c * LL + l0 + lane] = v;
        }
    }

    uint32_t* xTb = xnT16 + (size_t)b * LL * (CC / 2);
    #pragma unroll 4
    for (int i = 0; i < 32; i++) {
        int f = tid + i * 256;
        int l = f >> 8, cp = f & 255;
        int c0 = cp * 2, c1 = c0 + 1;
        float mean = s_mean[l], rstd = s_rstd[l];
        float v0 = (s[c0 * 33 + l] - mean) * rstd * __ldg(&gamma[c0]) + __ldg(&beta[c0]);
        float v1 = (s[c1 * 33 + l] - mean) * rstd * __ldg(&gamma[c1]) + __ldg(&beta[c1]);
        xTb[(size_t)(l0 + l) * (CC / 2) + cp] = pack_bf16x2(v0, v1);
    }
}

// ---------------- pack weights to bf16 ---------------------------------------
__global__ void pack_bf16_kernel(const float* __restrict__ in, uint32_t* __restrict__ out, int n2)
{
    int i = blockIdx.x * 256 + threadIdx.x;
    if (i < n2) out[i] = pack_bf16x2(in[2 * i], in[2 * i + 1]);
}

// ---------------- bf16 GEMM: 128x256 tile, BK=32, 4-stage, 1 sync/tile -------
// swizzled smem, stage = (128+256) rows x 64B = 24 KB; 4 stages = 96 KB.
#define STG_BYTES 24576
#define A_BYTES   8192
#define GEMM_DYN_SMEM (4 * STG_BYTES)

template <bool EPI, bool OUT16>
__global__ void __launch_bounds__(256)
gemm_bf16_mma(const __nv_bfloat16* __restrict__ A, const __nv_bfloat16* __restrict__ Bmat,
              void* __restrict__ Cout, size_t strideBz, size_t strideCz,
              const float* __restrict__ bias,
              const float* __restrict__ res, size_t strideRz)
{
    extern __shared__ uint32_t smem32[];

    const int tid = threadIdx.x;
    const int wid = tid >> 5, lane = tid & 31;
    const int g = lane >> 2, t4 = lane & 3;
    const int sel = lane >> 3, wi = lane & 7;
    const int warp_m = wid >> 2;
    const int warp_n = wid & 3;
    const int bx = blockIdx.x, by = blockIdx.y, bz = blockIdx.z;

    const __nv_bfloat16* Abase = A    + (size_t)by * 128 * 512;
    const __nv_bfloat16* Bbase = Bmat + (size_t)bz * strideBz + (size_t)bx * 256 * 512;

    const uint32_t sAu = smem_u32(smem32);
    const int rmb = warp_m * 64;
    const int nbb = warp_n * 64;

    auto load_tile = [&](int t) {
        int stage = t & 3;
        uint32_t dA = sAu + (uint32_t)stage * STG_BYTES;
        uint32_t dB = dA + A_BYTES;
        int k0 = t * 32;
        #pragma unroll
        for (int i = 0; i < 2; i++) {
            int f = tid + i * 256;
            int r = f >> 2, j = f & 3;
            cp_async16(dA + swz(r, j), Abase + (size_t)r * 512 + k0 + j * 8);
        }
        #pragma unroll
        for (int i = 0; i < 4; i++) {
            int f = tid + i * 256;
            int r = f >> 2, j = f & 3;
            cp_async16(dB + swz(r, j), Bbase + (size_t)r * 512 + k0 + j * 8);
        }
        CP_COMMIT();
    };

    float acc[4][8][4];
    #pragma unroll
    for (int mf = 0; mf < 4; mf++)
        #pragma unroll
        for (int nf = 0; nf < 8; nf++)
            #pragma unroll
            for (int i = 0; i < 4; i++) acc[mf][nf][i] = 0.f;

    load_tile(0); load_tile(1); load_tile(2);

    for (int t = 0; t < 16; t++) {
        CP_WAIT(2);
        __syncthreads();           // single barrier per tile (4 distinct buffers)
        uint32_t stg = sAu + (uint32_t)(t & 3) * STG_BYTES;

        #pragma unroll
        for (int ks = 0; ks < 2; ks++) {
            uint32_t af[4][4], bf[8][2];
            #pragma unroll
            for (int mf = 0; mf < 4; mf++) {
                int r = rmb + mf * 16 + wi + (sel & 1) * 8;
                int j = ks * 2 + (sel >> 1);
                ldsm_x4(af[mf][0], af[mf][1], af[mf][2], af[mf][3], stg + swz(r, j));
            }
            #pragma unroll
            for (int nf2 = 0; nf2 < 4; nf2++) {
                int r = nbb + nf2 * 16 + wi + (sel >> 1) * 8;
                int j = ks * 2 + (sel & 1);
                ldsm_x4(bf[nf2*2][0], bf[nf2*2][1], bf[nf2*2+1][0], bf[nf2*2+1][1],
                        stg + A_BYTES + swz(r, j));
            }
            #pragma unroll
            for (int mf = 0; mf < 4; mf++)
                #pragma unroll
                for (int nf = 0; nf < 8; nf++)
                    mma_bf16(acc[mf][nf], af[mf], bf[nf]);
        }
        // issue next load (or empty group so CP_WAIT(2) keeps advancing at tail)
        if (t + 3 < 16) load_tile(t + 3); else CP_COMMIT();
    }

    // epilogue
    #pragma unroll
    for (int mf = 0; mf < 4; mf++) {
        int row0 = by * 128 + rmb + mf * 16 + g;
        #pragma unroll
        for (int half = 0; half < 2; half++) {
            int row = row0 + half * 8;
            #pragma unroll
            for (int nf = 0; nf < 8; nf++) {
                int cn = nbb + nf * 8 + 2 * t4;
                float vx = acc[mf][nf][half * 2 + 0];
                float vy = acc[mf][nf][half * 2 + 1];
                if (EPI) {
                    size_t roff = (size_t)bz * strideRz + (size_t)row * LL + bx * 256 + cn;
                    float bval = bias[row];
                    vx += bval + res[roff];
                    vy += bval + res[roff + 1];
                }
                size_t coff = (size_t)bz * strideCz + (size_t)row * LL + bx * 256 + cn;
                if (OUT16) {
                    ((uint32_t*)Cout)[coff >> 1] = pack_bf16x2(vx, vy);
                } else {
                    float2 v2 = make_float2(vx, vy);
                    *reinterpret_cast<float2*>((float*)Cout + coff) = v2;
                }
            }
        }
    }
}

// ---------------- k-row softmax stats: (max, 1/sumexp) -----------------------
__global__ void __launch_bounds__(256)
kstats_kernel(const uint32_t* __restrict__ qkv16, float2* __restrict__ stats)
{
    int row = blockIdx.x;                 // 0..BB*HID-1
    int b = row >> 9, r = row & 511;
    const uint32_t* p = qkv16 + ((size_t)(b * 3 + 1) * HID + r) * (LL / 2);

    const int tid = threadIdx.x;
    __shared__ float shp[8];
    __shared__ float bcast;

    float2 v[8];
    #pragma unroll
    for (int i = 0; i < 8; i++)
        v[i] = unpack_bf16x2(p[tid + i * 256]);

    float m = -3.4e38f;
    #pragma unroll
    for (int i = 0; i < 8; i++) m = fmaxf(m, fmaxf(v[i].x, v[i].y));
    #pragma unroll
    for (int o = 16; o; o >>= 1) m = fmaxf(m, __shfl_xor_sync(0xffffffffu, m, o));
    if ((tid & 31) == 0) shp[tid >> 5] = m;
    __syncthreads();
    if (tid < 32) {
        float t = (tid < 8) ? shp[tid] : -3.4e38f;
        #pragma unroll
        for (int o = 4; o; o >>= 1) t = fmaxf(t, __shfl_xor_sync(0xffffffffu, t, o));
        if (tid == 0) bcast = t;
    }
    __syncthreads();
    float M = bcast;
    __syncthreads();

    float s = 0.f;
    #pragma unroll
    for (int i = 0; i < 8; i++)
        s += __expf(v[i].x - M) + __expf(v[i].y - M);
    #pragma unroll
    for (int o = 16; o; o >>= 1) s += __shfl_xor_sync(0xffffffffu, s, o);
    if ((tid & 31) == 0) shp[tid >> 5] = s;
    __syncthreads();
    if (tid < 32) {
        float t = (tid < 8) ? shp[tid] : 0.f;
        #pragma unroll
        for (int o = 4; o; o >>= 1) t += __shfl_xor_sync(0xffffffffu, t, o);
        if (tid == 0) bcast = t;
    }
    __syncthreads();
    if (tid == 0) stats[row] = make_float2(M, 1.0f / bcast);
}

// ---------------- context = softmax(k) @ v^T (fused normalize) --------------
__global__ void zero_ctx_kernel(float* __restrict__ ctx, int off)
{
    ctx[off + blockIdx.x * 256 + threadIdx.x] = 0.f;
}

__global__ void __launch_bounds__(256)
ctx_kernel(const uint32_t* __restrict__ qkv16, const float2* __restrict__ stats,
           float* __restrict__ ctx)
{
    const int chunk = blockIdx.x;
    const int h = blockIdx.y, b = blockIdx.z;

    const uint32_t* kp = qkv16 + ((size_t)(b * 3 + 1) * HID + h * DH) * (LL / 2);
    const uint32_t* vp = qkv16 + ((size_t)(b * 3 + 2) * HID + h * DH) * (LL / 2);

    __shared__ float ksT[64][65];
    __shared__ float vsT[64][65];
    __shared__ float2 sst[64];

    const int tid = threadIdx.x;
    const int ty = tid >> 4, tx = tid & 15;

    if (tid < 64) sst[tid] = stats[(size_t)b * HID + h * DH + tid];
    __syncthreads();

    float acc[4][4];
    #pragma unroll
    for (int i = 0; i < 4; i++)
        #pragma unroll
        for (int j = 0; j < 4; j++) acc[i][j] = 0.f;

    for (int t = 0; t < 8; t++) {
        int np = (chunk * 512 + t * 64) / 2;      // u32 pair offset
        #pragma unroll
        for (int i = 0; i < 8; i++) {
            int f = tid + i * 256;                // 0..2047: 64 d x 32 pairs
            int d = f >> 5, pr = f & 31;
            float2 st = sst[d];
            float2 kk = unpack_bf16x2(kp[(size_t)d * (LL / 2) + np + pr]);
            float2 vv = unpack_bf16x2(vp[(size_t)d * (LL / 2) + np + pr]);
            ksT[2 * pr][d]     = __expf(kk.x - st.x) * st.y;
            ksT[2 * pr + 1][d] = __expf(kk.y - st.x) * st.y;
            vsT[2 * pr][d]     = vv.x;
            vsT[2 * pr + 1][d] = vv.y;
        }
        __syncthreads();
        #pragma unroll 8
        for (int n = 0; n < 64; n++) {
            float af[4], bf[4];
            #pragma unroll
            for (int i = 0; i < 4; i++) af[i] = ksT[n][ty * 4 + i];
            #pragma unroll
            for (int j = 0; j < 4; j++) bf[j] = vsT[n][tx * 4 + j];
            #pragma unroll
            for (int i = 0; i < 4; i++)
                #pragma unroll
                for (int j = 0; j < 4; j++)
                    acc[i][j] = fmaf(af[i], bf[j], acc[i][j]);
        }
        __syncthreads();
    }

    float* cbase = ctx + ((size_t)(b * NH + h)) * DH * DH;
    #pragma unroll
    for (int i = 0; i < 4; i++)
        #pragma unroll
        for (int j = 0; j < 4; j++)
            atomicAdd(&cbase[(size_t)(ty * 4 + i) * DH + tx * 4 + j], acc[i][j]);
}

// ---------------- attnT[l,hid] = (SCALE * ctx^T @ q)^T, bf16-packed ----------
__global__ void __launch_bounds__(256)
attn_out_kernel(const uint32_t* __restrict__ qkv16, const float* __restrict__ ctx,
                uint32_t* __restrict__ attnT16)
{
    const int nt = blockIdx.x;
    const int h = blockIdx.y, b = blockIdx.z;
    const int n0 = nt * 128;

    const uint32_t* qp = qkv16 + ((size_t)b * 3 * HID + h * DH) * (LL / 2);
    const float* cp = ctx + ((size_t)(b * NH + h)) * DH * DH;

    __shared__ union {
        struct { float cs[64][64]; float qs[64][128]; } a;
        float os[128][65];
    } sm;

    const int tid = threadIdx.x;

    #pragma unroll
    for (int i = 0; i < 4; i++) {
        int f = tid + i * 256;
        reinterpret_cast<float4*>(&sm.a.cs[0][0])[f] = reinterpret_cast<const float4*>(cp)[f];
    }
    #pragma unroll
    for (int i = 0; i < 16; i++) {
        int f = tid + i * 256;                 // 0..4095: 64 d x 64 pairs
        int d = f >> 6, pr = f & 63;
        float2 q2 = unpack_bf16x2(qp[(size_t)d * (LL / 2) + n0 / 2 + pr]);
        sm.a.qs[d][2 * pr]     = q2.x;
        sm.a.qs[d][2 * pr + 1] = q2.y;
    }
    __syncthreads();

    const int ty = tid >> 5, tx = tid & 31;

    float acc[8][4];
    #pragma unroll
    for (int i = 0; i < 8; i++)
        #pragma unroll
        for (int j = 0; j < 4; j++) acc[i][j] = 0.f;

    #pragma unroll 8
    for (int d = 0; d < 64; d++) {
        float qf[4], cf[8];
        #pragma unroll
        for (int j = 0; j < 4; j++) qf[j] = sm.a.qs[d][tx * 4 + j];
        #pragma unroll
        for (int i = 0; i < 8; i++) cf[i] = sm.a.cs[d][ty * 8 + i];
        #pragma unroll
        for (int i = 0; i < 8; i++)
            #pragma unroll
            for (int j = 0; j < 4; j++)
                acc[i][j] = fmaf(cf[i], qf[j], acc[i][j]);
    }

    __syncthreads();

    #pragma unroll
    for (int i = 0; i < 8; i++)
        #pragma unroll
        for (int j = 0; j < 4; j++)
            sm.os[tx * 4 + j][ty * 8 + i] = acc[i][j] * SCALEV;
    __syncthreads();

    #pragma unroll
    for (int i = 0; i < 16; i++) {
        int f = tid + i * 256;
        int r = f >> 5, cpx = f & 31;
        uint32_t u = pack_bf16x2(sm.os[r][cpx * 2], sm.os[r][cpx * 2 + 1]);
        attnT16[((size_t)b * LL + n0 + r) * (HID / 2) + h * (DH / 2) + cpx] = u;
    }
}

// ---------------- launch ------------------------------------------------------
extern "C" void kernel_launch(void* const* d_in, const int* in_sizes, int n_in,
                              void* d_out, int out_size)
{
    const float* x     = (const float*)d_in[0];
    const float* gamma = (const float*)d_in[1];
    const float* beta  = (const float*)d_in[2];
    const float* w_qkv = (const float*)d_in[3];
    const float* w_out = (const float*)d_in[4];
    const float* b_out = (const float*)d_in[5];
    float* out = (float*)d_out;

    float *xn, *ctx;
    float2* stats;
    uint32_t *xnT16, *qkv16, *attnT16, *wq16, *wo16;
    cudaGetSymbolAddress((void**)&xn,      g_xn);
    cudaGetSymbolAddress((void**)&xnT16,   g_xnT16);
    cudaGetSymbolAddress((void**)&qkv16,   g_qkv16);
    cudaGetSymbolAddress((void**)&stats,   g_stats);
    cudaGetSymbolAddress((void**)&ctx,     g_ctx);
    cudaGetSymbolAddress((void**)&attnT16, g_attnT16);
    cudaGetSymbolAddress((void**)&wq16,    g_wq16);
    cudaGetSymbolAddress((void**)&wo16,    g_wo16);

    cudaFuncSetAttribute((const void*)gemm_bf16_mma<false, true>,
                         cudaFuncAttributeMaxDynamicSharedMemorySize, GEMM_DYN_SMEM);
    cudaFuncSetAttribute((const void*)gemm_bf16_mma<true, false>,
                         cudaFuncAttributeMaxDynamicSharedMemorySize, GEMM_DYN_SMEM);
    cudaFuncSetAttribute((const void*)ln_fused_kernel,
                         cudaFuncAttributeMaxDynamicSharedMemorySize, LN_SMEM);

    const int CTX_N = BB * NH * DH * DH;

    pack_bf16_kernel<<<(3 * HID * CC / 2 + 255) / 256, 256>>>(w_qkv, wq16, 3 * HID * CC / 2);
    pack_bf16_kernel<<<(CC * HID / 2 + 255) / 256, 256>>>(w_out, wo16, CC * HID / 2);
    zero_ctx_kernel<<<CTX_N / 512, 256>>>(ctx, 0);
    zero_ctx_kernel<<<CTX_N / 512, 256>>>(ctx, CTX_N / 2);
    ln_fused_kernel<<<dim3(LL / 32, BB), 256, LN_SMEM>>>(x, gamma, beta, xn, xnT16);

    // QKV GEMM (bf16 in, bf16 out)
    gemm_bf16_mma<false, true><<<dim3(LL / 256, (3 * HID) / 128, BB), 256, GEMM_DYN_SMEM>>>(
        (const __nv_bfloat16*)wq16, (const __nv_bfloat16*)xnT16, qkv16,
        (size_t)LL * CC, (size_t)3 * HID * LL, nullptr, nullptr, 0);

    kstats_kernel<<<BB * HID, 256>>>(qkv16, stats);
    ctx_kernel<<<dim3(8, NH, BB), 256>>>(qkv16, stats, ctx);
    attn_out_kernel<<<dim3(LL / 128, NH, BB), 256>>>(qkv16, ctx, attnT16);

    // OUT GEMM (bf16 in, fp32 out + bias + residual)
    gemm_bf16_mma<true, false><<<dim3(LL / 256, HID / 128, BB), 256, GEMM_DYN_SMEM>>>(
        (const __nv_bfloat16*)wo16, (const __nv_bfloat16*)attnT16, out,
        (size_t)LL * HID, (size_t)HID * LL, b_out, xn, (size_t)CC * LL);
}

// round 12
// speedup vs baseline: 3.5430x; 1.0430x over previous
#include <cuda_runtime.h>
#include <cuda_bf16.h>
#include <cstdint>
#include <cstddef>

// Problem constants
#define BB   8
#define CC   512
#define LL   4096
#define HID  512
#define NH   8
#define DH   64
#define EPSV 1e-5f
#define SCALEV 0.125f

// ---------------- scratch (device globals) ----------------------------------
__device__ float    g_xn   [(size_t)BB * CC * LL];          // 64 MB fp32 residual
__device__ uint32_t g_xnT16[(size_t)BB * LL * (CC/2)];      // 32 MB xn^T bf16 [L,C]
__device__ uint32_t g_qkv16[(size_t)BB * 3 * HID * (LL/2)]; // 96 MB qkv bf16
__device__ float2   g_stats[(size_t)BB * HID];              // k-row softmax stats
__device__ float    g_ctx  [(size_t)BB * NH * DH * DH];     // 1 MB context
__device__ uint32_t g_attnT16[(size_t)BB * LL * (HID/2)];   // 32 MB attn^T bf16
__device__ uint32_t g_wq16 [(size_t)3 * HID * CC / 2];
__device__ uint32_t g_wo16 [(size_t)CC * HID / 2];

// ---------------- helpers ----------------------------------------------------
__device__ __forceinline__ uint32_t smem_u32(const void* p) {
    uint32_t a;
    asm("{ .reg .u64 t; cvta.to.shared.u64 t, %1; cvt.u32.u64 %0, t; }" : "=r"(a) : "l"(p));
    return a;
}
__device__ __forceinline__ uint32_t pack_bf16x2(float lo, float hi) {
    __nv_bfloat162 h = __floats2bfloat162_rn(lo, hi);
    return *reinterpret_cast<uint32_t*>(&h);
}
__device__ __forceinline__ float2 unpack_bf16x2(uint32_t u) {
    __nv_bfloat162 h = *reinterpret_cast<__nv_bfloat162*>(&u);
    return make_float2(__bfloat162float(h.x), __bfloat162float(h.y));
}
__device__ __forceinline__ void cp_async16(uint32_t saddr, const void* g) {
    asm volatile("cp.async.cg.shared.global [%0], [%1], 16;" :: "r"(saddr), "l"(g));
}
#define CP_COMMIT() asm volatile("cp.async.commit_group;" ::: "memory")
#define CP_WAIT(n)  asm volatile("cp.async.wait_group %0;" :: "n"(n) : "memory")

__device__ __forceinline__ void ldsm_x4(uint32_t& r0, uint32_t& r1, uint32_t& r2, uint32_t& r3,
                                        uint32_t addr)
{
    asm volatile("ldmatrix.sync.aligned.m8n8.x4.shared.b16 {%0,%1,%2,%3}, [%4];"
                 : "=r"(r0), "=r"(r1), "=r"(r2), "=r"(r3) : "r"(addr));
}

__device__ __forceinline__ void mma_bf16(float* c, const uint32_t* a, const uint32_t* b)
{
    asm volatile(
        "mma.sync.aligned.m16n8k16.row.col.f32.bf16.bf16.f32 "
        "{%0,%1,%2,%3}, {%4,%5,%6,%7}, {%8,%9}, {%0,%1,%2,%3};"
        : "+f"(c[0]), "+f"(c[1]), "+f"(c[2]), "+f"(c[3])
        : "r"(a[0]), "r"(a[1]), "r"(a[2]), "r"(a[3]), "r"(b[0]), "r"(b[1]));
}

// SW128 swizzle: 128B rows of eight 16B chunks; chunk XOR'd by row&7.
__device__ __forceinline__ uint32_t swz128(int r, int j) {
    return (uint32_t)(r * 128 + ((j ^ (r & 7)) << 4));
}

// ---------------- fused LayerNorm: xn[C,L] fp32 + xnT[L,C] bf16 --------------
#define LN_SMEM (512 * 33 * 4)
__global__ void __launch_bounds__(256)
ln_fused_kernel(const float* __restrict__ x,
                const float* __restrict__ gamma,
                const float* __restrict__ beta,
                float* __restrict__ xn, uint32_t* __restrict__ xnT16)
{
    extern __shared__ float s[];
    __shared__ float ps[8][32], pss[8][32];
    __shared__ float s_mean[32], s_rstd[32];

    const int tid = threadIdx.x, wid = tid >> 5, lane = tid & 31;
    const int l0 = blockIdx.x * 32, b = blockIdx.y;
    const float* xb = x + (size_t)b * CC * LL;

    #pragma unroll 4
    for (int it = 0; it < 64; it++) {
        int c = it * 8 + wid;
        s[c * 33 + lane] = xb[(size_t)c * LL + l0 + lane];
    }
    __syncthreads();

    {
        int l = lane, ch = wid;
        float sum = 0.f, ssum = 0.f;
        #pragma unroll 8
        for (int c = ch * 64; c < ch * 64 + 64; c++) {
            float v = s[c * 33 + l];
            sum += v; ssum += v * v;
        }
        ps[ch][l] = sum; pss[ch][l] = ssum;
    }
    __syncthreads();
    if (tid < 32) {
        float sum = 0.f, ssum = 0.f;
        #pragma unroll
        for (int ch = 0; ch < 8; ch++) { sum += ps[ch][tid]; ssum += pss[ch][tid]; }
        float mean = sum * (1.0f / CC);
        float var  = ssum * (1.0f / CC) - mean * mean;
        s_mean[tid] = mean;
        s_rstd[tid] = rsqrtf(var + EPSV);
    }
    __syncthreads();

    float* xnb = xn + (size_t)b * CC * LL;
    {
        float mean = s_mean[lane], rstd = s_rstd[lane];
        #pragma unroll 4
        for (int it = 0; it < 64; it++) {
            int c = it * 8 + wid;
            float v = (s[c * 33 + lane] - mean) * rstd * __ldg(&gamma[c]) + __ldg(&beta[c]);
            xnb[(size_t)c * LL + l0 + lane] = v;
        }
    }

    uint32_t* xTb = xnT16 + (size_t)b * LL * (CC / 2);
    #pragma unroll 4
    for (int i = 0; i < 32; i++) {
        int f = tid + i * 256;
        int l = f >> 8, cp = f & 255;
        int c0 = cp * 2, c1 = c0 + 1;
        float mean = s_mean[l], rstd = s_rstd[l];
        float v0 = (s[c0 * 33 + l] - mean) * rstd * __ldg(&gamma[c0]) + __ldg(&beta[c0]);
        float v1 = (s[c1 * 33 + l] - mean) * rstd * __ldg(&gamma[c1]) + __ldg(&beta[c1]);
        xTb[(size_t)(l0 + l) * (CC / 2) + cp] = pack_bf16x2(v0, v1);
    }
}

// ---------------- pack weights to bf16 ---------------------------------------
__global__ void pack_bf16_kernel(const float* __restrict__ in, uint32_t* __restrict__ out, int n2)
{
    int i = blockIdx.x * 256 + threadIdx.x;
    if (i < n2) out[i] = pack_bf16x2(in[2 * i], in[2 * i + 1]);
}

// ---------------- bf16 GEMM: 128x256 tile, BK=64, 3-stage, 1 sync/tile -------
// SW128-swizzled smem; stage = (128+256) rows x 128B = 48 KB; 3 stages = 144 KB.
#define STG_BYTES 49152
#define A_BYTES   16384
#define GEMM_DYN_SMEM (3 * STG_BYTES)

template <bool EPI, bool OUT16>
__global__ void __launch_bounds__(256)
gemm_bf16_mma(const __nv_bfloat16* __restrict__ A, const __nv_bfloat16* __restrict__ Bmat,
              void* __restrict__ Cout, size_t strideBz, size_t strideCz,
              const float* __restrict__ bias,
              const float* __restrict__ res, size_t strideRz)
{
    extern __shared__ uint32_t smem32[];

    const int tid = threadIdx.x;
    const int wid = tid >> 5, lane = tid & 31;
    const int g = lane >> 2, t4 = lane & 3;
    const int sel = lane >> 3, wi = lane & 7;
    const int warp_m = wid >> 2;
    const int warp_n = wid & 3;
    const int bx = blockIdx.x, by = blockIdx.y, bz = blockIdx.z;

    const __nv_bfloat16* Abase = A    + (size_t)by * 128 * 512;
    const __nv_bfloat16* Bbase = Bmat + (size_t)bz * strideBz + (size_t)bx * 256 * 512;

    const uint32_t sAu = smem_u32(smem32);
    const int rmb = warp_m * 64;
    const int nbb = warp_n * 64;

    auto load_tile = [&](int t) {
        int stage = t % 3;
        uint32_t dA = sAu + (uint32_t)stage * STG_BYTES;
        uint32_t dB = dA + A_BYTES;
        int k0 = t * 64;
        #pragma unroll
        for (int i = 0; i < 4; i++) {     // A: 1024 chunks
            int f = tid + i * 256;
            int r = f >> 3, j = f & 7;
            cp_async16(dA + swz128(r, j), Abase + (size_t)r * 512 + k0 + j * 8);
        }
        #pragma unroll
        for (int i = 0; i < 8; i++) {     // B: 2048 chunks
            int f = tid + i * 256;
            int r = f >> 3, j = f & 7;
            cp_async16(dB + swz128(r, j), Bbase + (size_t)r * 512 + k0 + j * 8);
        }
        CP_COMMIT();
    };

    float acc[4][8][4];
    #pragma unroll
    for (int mf = 0; mf < 4; mf++)
        #pragma unroll
        for (int nf = 0; nf < 8; nf++)
            #pragma unroll
            for (int i = 0; i < 4; i++) acc[mf][nf][i] = 0.f;

    load_tile(0); load_tile(1);

    for (int t = 0; t < 8; t++) {
        CP_WAIT(1);                       // tile t resident (t+1 may be pending)
        __syncthreads();
        uint32_t stg = sAu + (uint32_t)(t % 3) * STG_BYTES;

        #pragma unroll
        for (int ks = 0; ks < 4; ks++) {
            uint32_t af[4][4], bf[8][2];
            #pragma unroll
            for (int mf = 0; mf < 4; mf++) {
                int r = rmb + mf * 16 + wi + (sel & 1) * 8;
                int j = ks * 2 + (sel >> 1);
                ldsm_x4(af[mf][0], af[mf][1], af[mf][2], af[mf][3], stg + swz128(r, j));
            }
            #pragma unroll
            for (int nf2 = 0; nf2 < 4; nf2++) {
                int r = nbb + nf2 * 16 + wi + (sel >> 1) * 8;
                int j = ks * 2 + (sel & 1);
                ldsm_x4(bf[nf2*2][0], bf[nf2*2][1], bf[nf2*2+1][0], bf[nf2*2+1][1],
                        stg + A_BYTES + swz128(r, j));
            }
            #pragma unroll
            for (int mf = 0; mf < 4; mf++)
                #pragma unroll
                for (int nf = 0; nf < 8; nf++)
                    mma_bf16(acc[mf][nf], af[mf], bf[nf]);
        }
        if (t + 2 < 8) load_tile(t + 2); else CP_COMMIT();  // keep group count advancing
    }

    // epilogue
    #pragma unroll
    for (int mf = 0; mf < 4; mf++) {
        int row0 = by * 128 + rmb + mf * 16 + g;
        #pragma unroll
        for (int half = 0; half < 2; half++) {
            int row = row0 + half * 8;
            #pragma unroll
            for (int nf = 0; nf < 8; nf++) {
                int cn = nbb + nf * 8 + 2 * t4;
                float vx = acc[mf][nf][half * 2 + 0];
                float vy = acc[mf][nf][half * 2 + 1];
                if (EPI) {
                    size_t roff = (size_t)bz * strideRz + (size_t)row * LL + bx * 256 + cn;
                    float bval = bias[row];
                    vx += bval + res[roff];
                    vy += bval + res[roff + 1];
                }
                size_t coff = (size_t)bz * strideCz + (size_t)row * LL + bx * 256 + cn;
                if (OUT16) {
                    ((uint32_t*)Cout)[coff >> 1] = pack_bf16x2(vx, vy);
                } else {
                    float2 v2 = make_float2(vx, vy);
                    *reinterpret_cast<float2*>((float*)Cout + coff) = v2;
                }
            }
        }
    }
}

// ---------------- k-row softmax stats: (max, 1/sumexp) -----------------------
__global__ void __launch_bounds__(256)
kstats_kernel(const uint32_t* __restrict__ qkv16, float2* __restrict__ stats)
{
    int row = blockIdx.x;
    int b = row >> 9, r = row & 511;
    const uint32_t* p = qkv16 + ((size_t)(b * 3 + 1) * HID + r) * (LL / 2);

    const int tid = threadIdx.x;
    __shared__ float shp[8];
    __shared__ float bcast;

    float2 v[8];
    #pragma unroll
    for (int i = 0; i < 8; i++)
        v[i] = unpack_bf16x2(p[tid + i * 256]);

    float m = -3.4e38f;
    #pragma unroll
    for (int i = 0; i < 8; i++) m = fmaxf(m, fmaxf(v[i].x, v[i].y));
    #pragma unroll
    for (int o = 16; o; o >>= 1) m = fmaxf(m, __shfl_xor_sync(0xffffffffu, m, o));
    if ((tid & 31) == 0) shp[tid >> 5] = m;
    __syncthreads();
    if (tid < 32) {
        float t = (tid < 8) ? shp[tid] : -3.4e38f;
        #pragma unroll
        for (int o = 4; o; o >>= 1) t = fmaxf(t, __shfl_xor_sync(0xffffffffu, t, o));
        if (tid == 0) bcast = t;
    }
    __syncthreads();
    float M = bcast;
    __syncthreads();

    float s = 0.f;
    #pragma unroll
    for (int i = 0; i < 8; i++)
        s += __expf(v[i].x - M) + __expf(v[i].y - M);
    #pragma unroll
    for (int o = 16; o; o >>= 1) s += __shfl_xor_sync(0xffffffffu, s, o);
    if ((tid & 31) == 0) shp[tid >> 5] = s;
    __syncthreads();
    if (tid < 32) {
        float t = (tid < 8) ? shp[tid] : 0.f;
        #pragma unroll
        for (int o = 4; o; o >>= 1) t += __shfl_xor_sync(0xffffffffu, t, o);
        if (tid == 0) bcast = t;
    }
    __syncthreads();
    if (tid == 0) stats[row] = make_float2(M, 1.0f / bcast);
}

// ---------------- context = (SCALE * softmax(k)) @ v^T ----------------------
__global__ void zero_ctx_kernel(float* __restrict__ ctx)
{
    ctx[blockIdx.x * 256 + threadIdx.x] = 0.f;
}

__global__ void __launch_bounds__(256)
ctx_kernel(const uint32_t* __restrict__ qkv16, const float2* __restrict__ stats,
           float* __restrict__ ctx)
{
    const int chunk = blockIdx.x;
    const int h = blockIdx.y, b = blockIdx.z;

    const uint32_t* kp = qkv16 + ((size_t)(b * 3 + 1) * HID + h * DH) * (LL / 2);
    const uint32_t* vp = qkv16 + ((size_t)(b * 3 + 2) * HID + h * DH) * (LL / 2);

    __shared__ float ksT[64][65];
    __shared__ float vsT[64][65];
    __shared__ float2 sst[64];

    const int tid = threadIdx.x;
    const int ty = tid >> 4, tx = tid & 15;

    if (tid < 64) {
        float2 st = stats[(size_t)b * HID + h * DH + tid];
        st.y *= SCALEV;            // fold q-scale into ctx (exact pow2)
        sst[tid] = st;
    }
    __syncthreads();

    float acc[4][4];
    #pragma unroll
    for (int i = 0; i < 4; i++)
        #pragma unroll
        for (int j = 0; j < 4; j++) acc[i][j] = 0.f;

    for (int t = 0; t < 8; t++) {
        int np = (chunk * 512 + t * 64) / 2;
        #pragma unroll
        for (int i = 0; i < 8; i++) {
            int f = tid + i * 256;
            int d = f >> 5, pr = f & 31;
            float2 st = sst[d];
            float2 kk = unpack_bf16x2(kp[(size_t)d * (LL / 2) + np + pr]);
            float2 vv = unpack_bf16x2(vp[(size_t)d * (LL / 2) + np + pr]);
            ksT[2 * pr][d]     = __expf(kk.x - st.x) * st.y;
            ksT[2 * pr + 1][d] = __expf(kk.y - st.x) * st.y;
            vsT[2 * pr][d]     = vv.x;
            vsT[2 * pr + 1][d] = vv.y;
        }
        __syncthreads();
        #pragma unroll 8
        for (int n = 0; n < 64; n++) {
            float af[4], bf[4];
            #pragma unroll
            for (int i = 0; i < 4; i++) af[i] = ksT[n][ty * 4 + i];
            #pragma unroll
            for (int j = 0; j < 4; j++) bf[j] = vsT[n][tx * 4 + j];
            #pragma unroll
            for (int i = 0; i < 4; i++)
                #pragma unroll
                for (int j = 0; j < 4; j++)
                    acc[i][j] = fmaf(af[i], bf[j], acc[i][j]);
        }
        __syncthreads();
    }

    float* cbase = ctx + ((size_t)(b * NH + h)) * DH * DH;
    #pragma unroll
    for (int i = 0; i < 4; i++)
        #pragma unroll
        for (int j = 0; j < 4; j++)
            atomicAdd(&cbase[(size_t)(ty * 4 + i) * DH + tx * 4 + j], acc[i][j]);
}

// ---------------- attnT[l,hid] = (ctx^T @ q)^T (SCALE pre-folded) ------------
__global__ void __launch_bounds__(256)
attn_out_kernel(const uint32_t* __restrict__ qkv16, const float* __restrict__ ctx,
                uint32_t* __restrict__ attnT16)
{
    const int nt = blockIdx.x;
    const int h = blockIdx.y, b = blockIdx.z;
    const int n0 = nt * 128;

    const uint32_t* qp = qkv16 + ((size_t)b * 3 * HID + h * DH) * (LL / 2);
    const float* cp = ctx + ((size_t)(b * NH + h)) * DH * DH;

    __shared__ union {
        struct { float cs[64][64]; float qs[64][128]; } a;
        float os[128][65];
    } sm;

    const int tid = threadIdx.x;

    #pragma unroll
    for (int i = 0; i < 4; i++) {
        int f = tid + i * 256;
        reinterpret_cast<float4*>(&sm.a.cs[0][0])[f] = reinterpret_cast<const float4*>(cp)[f];
    }
    #pragma unroll
    for (int i = 0; i < 16; i++) {
        int f = tid + i * 256;
        int d = f >> 6, pr = f & 63;
        float2 q2 = unpack_bf16x2(qp[(size_t)d * (LL / 2) + n0 / 2 + pr]);
        sm.a.qs[d][2 * pr]     = q2.x;
        sm.a.qs[d][2 * pr + 1] = q2.y;
    }
    __syncthreads();

    const int ty = tid >> 5, tx = tid & 31;

    float acc[8][4];
    #pragma unroll
    for (int i = 0; i < 8; i++)
        #pragma unroll
        for (int j = 0; j < 4; j++) acc[i][j] = 0.f;

    #pragma unroll 8
    for (int d = 0; d < 64; d++) {
        float qf[4], cf[8];
        #pragma unroll
        for (int j = 0; j < 4; j++) qf[j] = sm.a.qs[d][tx * 4 + j];
        #pragma unroll
        for (int i = 0; i < 8; i++) cf[i] = sm.a.cs[d][ty * 8 + i];
        #pragma unroll
        for (int i = 0; i < 8; i++)
            #pragma unroll
            for (int j = 0; j < 4; j++)
                acc[i][j] = fmaf(cf[i], qf[j], acc[i][j]);
    }

    __syncthreads();

    #pragma unroll
    for (int i = 0; i < 8; i++)
        #pragma unroll
        for (int j = 0; j < 4; j++)
            sm.os[tx * 4 + j][ty * 8 + i] = acc[i][j];
    __syncthreads();

    #pragma unroll
    for (int i = 0; i < 16; i++) {
        int f = tid + i * 256;
        int r = f >> 5, cpx = f & 31;
        uint32_t u = pack_bf16x2(sm.os[r][cpx * 2], sm.os[r][cpx * 2 + 1]);
        attnT16[((size_t)b * LL + n0 + r) * (HID / 2) + h * (DH / 2) + cpx] = u;
    }
}

// ---------------- launch ------------------------------------------------------
extern "C" void kernel_launch(void* const* d_in, const int* in_sizes, int n_in,
                              void* d_out, int out_size)
{
    const float* x     = (const float*)d_in[0];
    const float* gamma = (const float*)d_in[1];
    const float* beta  = (const float*)d_in[2];
    const float* w_qkv = (const float*)d_in[3];
    const float* w_out = (const float*)d_in[4];
    const float* b_out = (const float*)d_in[5];
    float* out = (float*)d_out;

    float *xn, *ctx;
    float2* stats;
    uint32_t *xnT16, *qkv16, *attnT16, *wq16, *wo16;
    cudaGetSymbolAddress((void**)&xn,      g_xn);
    cudaGetSymbolAddress((void**)&xnT16,   g_xnT16);
    cudaGetSymbolAddress((void**)&qkv16,   g_qkv16);
    cudaGetSymbolAddress((void**)&stats,   g_stats);
    cudaGetSymbolAddress((void**)&ctx,     g_ctx);
    cudaGetSymbolAddress((void**)&attnT16, g_attnT16);
    cudaGetSymbolAddress((void**)&wq16,    g_wq16);
    cudaGetSymbolAddress((void**)&wo16,    g_wo16);

    cudaFuncSetAttribute((const void*)gemm_bf16_mma<false, true>,
                         cudaFuncAttributeMaxDynamicSharedMemorySize, GEMM_DYN_SMEM);
    cudaFuncSetAttribute((const void*)gemm_bf16_mma<true, false>,
                         cudaFuncAttributeMaxDynamicSharedMemorySize, GEMM_DYN_SMEM);
    cudaFuncSetAttribute((const void*)ln_fused_kernel,
                         cudaFuncAttributeMaxDynamicSharedMemorySize, LN_SMEM);

    const int CTX_N = BB * NH * DH * DH;

    pack_bf16_kernel<<<(3 * HID * CC / 2 + 255) / 256, 256>>>(w_qkv, wq16, 3 * HID * CC / 2);
    pack_bf16_kernel<<<(CC * HID / 2 + 255) / 256, 256>>>(w_out, wo16, CC * HID / 2);
    zero_ctx_kernel<<<CTX_N / 256, 256>>>(ctx);
    ln_fused_kernel<<<dim3(LL / 32, BB), 256, LN_SMEM>>>(x, gamma, beta, xn, xnT16);

    // QKV GEMM (bf16 in, bf16 out)
    gemm_bf16_mma<false, true><<<dim3(LL / 256, (3 * HID) / 128, BB), 256, GEMM_DYN_SMEM>>>(
        (const __nv_bfloat16*)wq16, (const __nv_bfloat16*)xnT16, qkv16,
        (size_t)LL * CC, (size_t)3 * HID * LL, nullptr, nullptr, 0);

    kstats_kernel<<<BB * HID, 256>>>(qkv16, stats);
    ctx_kernel<<<dim3(8, NH, BB), 256>>>(qkv16, stats, ctx);
    attn_out_kernel<<<dim3(LL / 128, NH, BB), 256>>>(qkv16, ctx, attnT16);

    // OUT GEMM (bf16 in, fp32 out + bias + residual)
    gemm_bf16_mma<true, false><<<dim3(LL / 256, HID / 128, BB), 256, GEMM_DYN_SMEM>>>(
        (const __nv_bfloat16*)wo16, (const __nv_bfloat16*)attnT16, out,
        (size_t)LL * HID, (size_t)HID * LL, b_out, xn, (size_t)CC * LL);
}

// round 13
// speedup vs baseline: 3.7931x; 1.0706x over previous
#include <cuda_runtime.h>
#include <cuda_bf16.h>
#include <cstdint>
#include <cstddef>

// Problem constants
#define BB   8
#define CC   512
#define LL   4096
#define HID  512
#define NH   8
#define DH   64
#define EPSV 1e-5f
#define SCALEV 0.125f

// ---------------- scratch (device globals) ----------------------------------
__device__ uint32_t g_xnT16[(size_t)BB * LL * (CC/2)];      // 32 MB xn^T bf16 [L,C]
__device__ uint32_t g_qkv16[(size_t)BB * 3 * HID * (LL/2)]; // 96 MB qkv bf16
__device__ float2   g_stats[(size_t)BB * HID];              // k-row softmax stats
__device__ float2   g_lnst [(size_t)BB * LL];               // LN (mean, rstd) per (b,l)
__device__ float    g_ctx  [(size_t)BB * NH * DH * DH];     // 1 MB context
__device__ uint32_t g_attnT16[(size_t)BB * LL * (HID/2)];   // 32 MB attn^T bf16
__device__ uint32_t g_wq16 [(size_t)3 * HID * CC / 2];
__device__ uint32_t g_wo16 [(size_t)CC * HID / 2];

// ---------------- helpers ----------------------------------------------------
__device__ __forceinline__ uint32_t smem_u32(const void* p) {
    uint32_t a;
    asm("{ .reg .u64 t; cvta.to.shared.u64 t, %1; cvt.u32.u64 %0, t; }" : "=r"(a) : "l"(p));
    return a;
}
__device__ __forceinline__ uint32_t pack_bf16x2(float lo, float hi) {
    __nv_bfloat162 h = __floats2bfloat162_rn(lo, hi);
    return *reinterpret_cast<uint32_t*>(&h);
}
__device__ __forceinline__ float2 unpack_bf16x2(uint32_t u) {
    __nv_bfloat162 h = *reinterpret_cast<__nv_bfloat162*>(&u);
    return make_float2(__bfloat162float(h.x), __bfloat162float(h.y));
}
__device__ __forceinline__ void cp_async16(uint32_t saddr, const void* g) {
    asm volatile("cp.async.cg.shared.global [%0], [%1], 16;" :: "r"(saddr), "l"(g));
}
#define CP_COMMIT() asm volatile("cp.async.commit_group;" ::: "memory")
#define CP_WAIT(n)  asm volatile("cp.async.wait_group %0;" :: "n"(n) : "memory")

__device__ __forceinline__ void ldsm_x4(uint32_t& r0, uint32_t& r1, uint32_t& r2, uint32_t& r3,
                                        uint32_t addr)
{
    asm volatile("ldmatrix.sync.aligned.m8n8.x4.shared.b16 {%0,%1,%2,%3}, [%4];"
                 : "=r"(r0), "=r"(r1), "=r"(r2), "=r"(r3) : "r"(addr));
}

__device__ __forceinline__ void mma_bf16(float* c, const uint32_t* a, const uint32_t* b)
{
    asm volatile(
        "mma.sync.aligned.m16n8k16.row.col.f32.bf16.bf16.f32 "
        "{%0,%1,%2,%3}, {%4,%5,%6,%7}, {%8,%9}, {%0,%1,%2,%3};"
        : "+f"(c[0]), "+f"(c[1]), "+f"(c[2]), "+f"(c[3])
        : "r"(a[0]), "r"(a[1]), "r"(a[2]), "r"(a[3]), "r"(b[0]), "r"(b[1]));
}

// SW128 swizzle: 128B rows of eight 16B chunks; chunk XOR'd by row&7.
__device__ __forceinline__ uint32_t swz128(int r, int j) {
    return (uint32_t)(r * 128 + ((j ^ (r & 7)) << 4));
}

// ---------------- LayerNorm: stats + xnT[L,C] bf16 (no fp32 xn write) --------
#define LN_SMEM (512 * 33 * 4)
__global__ void __launch_bounds__(256)
ln_fused_kernel(const float* __restrict__ x,
                const float* __restrict__ gamma,
                const float* __restrict__ beta,
                float2* __restrict__ lnst, uint32_t* __restrict__ xnT16)
{
    extern __shared__ float s[];
    __shared__ float ps[8][32], pss[8][32];
    __shared__ float s_mean[32], s_rstd[32];

    const int tid = threadIdx.x, wid = tid >> 5, lane = tid & 31;
    const int l0 = blockIdx.x * 32, b = blockIdx.y;
    const float* xb = x + (size_t)b * CC * LL;

    #pragma unroll 8
    for (int it = 0; it < 64; it++) {
        int c = it * 8 + wid;
        s[c * 33 + lane] = xb[(size_t)c * LL + l0 + lane];
    }
    __syncthreads();

    {
        int l = lane, ch = wid;
        float sum = 0.f, ssum = 0.f;
        #pragma unroll 8
        for (int c = ch * 64; c < ch * 64 + 64; c++) {
            float v = s[c * 33 + l];
            sum += v; ssum += v * v;
        }
        ps[ch][l] = sum; pss[ch][l] = ssum;
    }
    __syncthreads();
    if (tid < 32) {
        float sum = 0.f, ssum = 0.f;
        #pragma unroll
        for (int ch = 0; ch < 8; ch++) { sum += ps[ch][tid]; ssum += pss[ch][tid]; }
        float mean = sum * (1.0f / CC);
        float var  = ssum * (1.0f / CC) - mean * mean;
        float rstd = rsqrtf(var + EPSV);
        s_mean[tid] = mean;
        s_rstd[tid] = rstd;
        lnst[(size_t)b * LL + l0 + tid] = make_float2(mean, rstd);
    }
    __syncthreads();

    uint32_t* xTb = xnT16 + (size_t)b * LL * (CC / 2);
    #pragma unroll 4
    for (int i = 0; i < 32; i++) {
        int f = tid + i * 256;
        int l = f >> 8, cp = f & 255;
        int c0 = cp * 2, c1 = c0 + 1;
        float mean = s_mean[l], rstd = s_rstd[l];
        float v0 = (s[c0 * 33 + l] - mean) * rstd * __ldg(&gamma[c0]) + __ldg(&beta[c0]);
        float v1 = (s[c1 * 33 + l] - mean) * rstd * __ldg(&gamma[c1]) + __ldg(&beta[c1]);
        xTb[(size_t)(l0 + l) * (CC / 2) + cp] = pack_bf16x2(v0, v1);
    }
}

// ---------------- pack weights to bf16 ---------------------------------------
__global__ void pack_bf16_kernel(const float* __restrict__ in, uint32_t* __restrict__ out, int n2)
{
    int i = blockIdx.x * 256 + threadIdx.x;
    if (i < n2) out[i] = pack_bf16x2(in[2 * i], in[2 * i + 1]);
}

// ---------------- bf16 GEMM: 128x256 tile, BK=64, 3-stage, 1 sync/tile -------
// EPI epilogue recomputes the LayerNorm residual from x + lnst + gamma/beta.
#define STG_BYTES 49152
#define A_BYTES   16384
#define GEMM_DYN_SMEM (3 * STG_BYTES)

template <bool EPI, bool OUT16>
__global__ void __launch_bounds__(256)
gemm_bf16_mma(const __nv_bfloat16* __restrict__ A, const __nv_bfloat16* __restrict__ Bmat,
              void* __restrict__ Cout, size_t strideBz, size_t strideCz,
              const float* __restrict__ bias,
              const float* __restrict__ resx, size_t strideRz,
              const float2* __restrict__ lnst,
              const float* __restrict__ gamma, const float* __restrict__ beta)
{
    extern __shared__ uint32_t smem32[];

    const int tid = threadIdx.x;
    const int wid = tid >> 5, lane = tid & 31;
    const int g = lane >> 2, t4 = lane & 3;
    const int sel = lane >> 3, wi = lane & 7;
    const int warp_m = wid >> 2;
    const int warp_n = wid & 3;
    const int bx = blockIdx.x, by = blockIdx.y, bz = blockIdx.z;

    const __nv_bfloat16* Abase = A    + (size_t)by * 128 * 512;
    const __nv_bfloat16* Bbase = Bmat + (size_t)bz * strideBz + (size_t)bx * 256 * 512;

    const uint32_t sAu = smem_u32(smem32);
    const int rmb = warp_m * 64;
    const int nbb = warp_n * 64;

    auto load_tile = [&](int t) {
        int stage = t % 3;
        uint32_t dA = sAu + (uint32_t)stage * STG_BYTES;
        uint32_t dB = dA + A_BYTES;
        int k0 = t * 64;
        #pragma unroll
        for (int i = 0; i < 4; i++) {
            int f = tid + i * 256;
            int r = f >> 3, j = f & 7;
            cp_async16(dA + swz128(r, j), Abase + (size_t)r * 512 + k0 + j * 8);
        }
        #pragma unroll
        for (int i = 0; i < 8; i++) {
            int f = tid + i * 256;
            int r = f >> 3, j = f & 7;
            cp_async16(dB + swz128(r, j), Bbase + (size_t)r * 512 + k0 + j * 8);
        }
        CP_COMMIT();
    };

    float acc[4][8][4];
    #pragma unroll
    for (int mf = 0; mf < 4; mf++)
        #pragma unroll
        for (int nf = 0; nf < 8; nf++)
            #pragma unroll
            for (int i = 0; i < 4; i++) acc[mf][nf][i] = 0.f;

    load_tile(0); load_tile(1);

    for (int t = 0; t < 8; t++) {
        CP_WAIT(1);
        __syncthreads();
        uint32_t stg = sAu + (uint32_t)(t % 3) * STG_BYTES;

        #pragma unroll
        for (int ks = 0; ks < 4; ks++) {
            uint32_t af[4][4], bf[8][2];
            #pragma unroll
            for (int mf = 0; mf < 4; mf++) {
                int r = rmb + mf * 16 + wi + (sel & 1) * 8;
                int j = ks * 2 + (sel >> 1);
                ldsm_x4(af[mf][0], af[mf][1], af[mf][2], af[mf][3], stg + swz128(r, j));
            }
            #pragma unroll
            for (int nf2 = 0; nf2 < 4; nf2++) {
                int r = nbb + nf2 * 16 + wi + (sel >> 1) * 8;
                int j = ks * 2 + (sel & 1);
                ldsm_x4(bf[nf2*2][0], bf[nf2*2][1], bf[nf2*2+1][0], bf[nf2*2+1][1],
                        stg + A_BYTES + swz128(r, j));
            }
            #pragma unroll
            for (int mf = 0; mf < 4; mf++)
                #pragma unroll
                for (int nf = 0; nf < 8; nf++)
                    mma_bf16(acc[mf][nf], af[mf], bf[nf]);
        }
        if (t + 2 < 8) load_tile(t + 2); else CP_COMMIT();
    }

    // epilogue
    #pragma unroll
    for (int mf = 0; mf < 4; mf++) {
        int row0 = by * 128 + rmb + mf * 16 + g;
        #pragma unroll
        for (int half = 0; half < 2; half++) {
            int row = row0 + half * 8;
            float bval = 0.f, ga = 0.f, be = 0.f;
            if (EPI) { bval = bias[row]; ga = gamma[row]; be = beta[row]; }
            #pragma unroll
            for (int nf = 0; nf < 8; nf++) {
                int cn = nbb + nf * 8 + 2 * t4;
                float vx = acc[mf][nf][half * 2 + 0];
                float vy = acc[mf][nf][half * 2 + 1];
                if (EPI) {
                    int lcol = bx * 256 + cn;
                    size_t roff = (size_t)bz * strideRz + (size_t)row * LL + lcol;
                    float2 x2 = *reinterpret_cast<const float2*>(resx + roff);
                    float2 s0 = lnst[(size_t)bz * LL + lcol];
                    float2 s1 = lnst[(size_t)bz * LL + lcol + 1];
                    vx += bval + ((x2.x - s0.x) * s0.y * ga + be);
                    vy += bval + ((x2.y - s1.x) * s1.y * ga + be);
                }
                size_t coff = (size_t)bz * strideCz + (size_t)row * LL + bx * 256 + cn;
                if (OUT16) {
                    ((uint32_t*)Cout)[coff >> 1] = pack_bf16x2(vx, vy);
                } else {
                    float2 v2 = make_float2(vx, vy);
                    *reinterpret_cast<float2*>((float*)Cout + coff) = v2;
                }
            }
        }
    }
}

// ---------------- k-row softmax stats: (max, 1/sumexp) -----------------------
__global__ void __launch_bounds__(256)
kstats_kernel(const uint32_t* __restrict__ qkv16, float2* __restrict__ stats)
{
    int row = blockIdx.x;
    int b = row >> 9, r = row & 511;
    const uint32_t* p = qkv16 + ((size_t)(b * 3 + 1) * HID + r) * (LL / 2);

    const int tid = threadIdx.x;
    __shared__ float shp[8];
    __shared__ float bcast;

    float2 v[8];
    #pragma unroll
    for (int i = 0; i < 8; i++)
        v[i] = unpack_bf16x2(p[tid + i * 256]);

    float m = -3.4e38f;
    #pragma unroll
    for (int i = 0; i < 8; i++) m = fmaxf(m, fmaxf(v[i].x, v[i].y));
    #pragma unroll
    for (int o = 16; o; o >>= 1) m = fmaxf(m, __shfl_xor_sync(0xffffffffu, m, o));
    if ((tid & 31) == 0) shp[tid >> 5] = m;
    __syncthreads();
    if (tid < 32) {
        float t = (tid < 8) ? shp[tid] : -3.4e38f;
        #pragma unroll
        for (int o = 4; o; o >>= 1) t = fmaxf(t, __shfl_xor_sync(0xffffffffu, t, o));
        if (tid == 0) bcast = t;
    }
    __syncthreads();
    float M = bcast;
    __syncthreads();

    float s = 0.f;
    #pragma unroll
    for (int i = 0; i < 8; i++)
        s += __expf(v[i].x - M) + __expf(v[i].y - M);
    #pragma unroll
    for (int o = 16; o; o >>= 1) s += __shfl_xor_sync(0xffffffffu, s, o);
    if ((tid & 31) == 0) shp[tid >> 5] = s;
    __syncthreads();
    if (tid < 32) {
        float t = (tid < 8) ? shp[tid] : 0.f;
        #pragma unroll
        for (int o = 4; o; o >>= 1) t += __shfl_xor_sync(0xffffffffu, t, o);
        if (tid == 0) bcast = t;
    }
    __syncthreads();
    if (tid == 0) stats[row] = make_float2(M, 1.0f / bcast);
}

// ---------------- context = (SCALE * softmax(k)) @ v^T ----------------------
__global__ void zero_ctx_kernel(float* __restrict__ ctx)
{
    ctx[blockIdx.x * 256 + threadIdx.x] = 0.f;
}

__global__ void __launch_bounds__(256)
ctx_kernel(const uint32_t* __restrict__ qkv16, const float2* __restrict__ stats,
           float* __restrict__ ctx)
{
    const int chunk = blockIdx.x;
    const int h = blockIdx.y, b = blockIdx.z;

    const uint32_t* kp = qkv16 + ((size_t)(b * 3 + 1) * HID + h * DH) * (LL / 2);
    const uint32_t* vp = qkv16 + ((size_t)(b * 3 + 2) * HID + h * DH) * (LL / 2);

    __shared__ float ksT[64][65];
    __shared__ float vsT[64][65];
    __shared__ float2 sst[64];

    const int tid = threadIdx.x;
    const int ty = tid >> 4, tx = tid & 15;

    if (tid < 64) {
        float2 st = stats[(size_t)b * HID + h * DH + tid];
        st.y *= SCALEV;
        sst[tid] = st;
    }
    __syncthreads();

    float acc[4][4];
    #pragma unroll
    for (int i = 0; i < 4; i++)
        #pragma unroll
        for (int j = 0; j < 4; j++) acc[i][j] = 0.f;

    for (int t = 0; t < 8; t++) {
        int np = (chunk * 512 + t * 64) / 2;
        #pragma unroll
        for (int i = 0; i < 8; i++) {
            int f = tid + i * 256;
            int d = f >> 5, pr = f & 31;
            float2 st = sst[d];
            float2 kk = unpack_bf16x2(kp[(size_t)d * (LL / 2) + np + pr]);
            float2 vv = unpack_bf16x2(vp[(size_t)d * (LL / 2) + np + pr]);
            ksT[2 * pr][d]     = __expf(kk.x - st.x) * st.y;
            ksT[2 * pr + 1][d] = __expf(kk.y - st.x) * st.y;
            vsT[2 * pr][d]     = vv.x;
            vsT[2 * pr + 1][d] = vv.y;
        }
        __syncthreads();
        #pragma unroll 8
        for (int n = 0; n < 64; n++) {
            float af[4], bf[4];
            #pragma unroll
            for (int i = 0; i < 4; i++) af[i] = ksT[n][ty * 4 + i];
            #pragma unroll
            for (int j = 0; j < 4; j++) bf[j] = vsT[n][tx * 4 + j];
            #pragma unroll
            for (int i = 0; i < 4; i++)
                #pragma unroll
                for (int j = 0; j < 4; j++)
                    acc[i][j] = fmaf(af[i], bf[j], acc[i][j]);
        }
        __syncthreads();
    }

    float* cbase = ctx + ((size_t)(b * NH + h)) * DH * DH;
    #pragma unroll
    for (int i = 0; i < 4; i++)
        #pragma unroll
        for (int j = 0; j < 4; j++)
            atomicAdd(&cbase[(size_t)(ty * 4 + i) * DH + tx * 4 + j], acc[i][j]);
}

// ---------------- attnT[l,hid] = (ctx^T @ q)^T (SCALE pre-folded) ------------
__global__ void __launch_bounds__(256)
attn_out_kernel(const uint32_t* __restrict__ qkv16, const float* __restrict__ ctx,
                uint32_t* __restrict__ attnT16)
{
    const int nt = blockIdx.x;
    const int h = blockIdx.y, b = blockIdx.z;
    const int n0 = nt * 128;

    const uint32_t* qp = qkv16 + ((size_t)b * 3 * HID + h * DH) * (LL / 2);
    const float* cp = ctx + ((size_t)(b * NH + h)) * DH * DH;

    __shared__ union {
        struct { float cs[64][64]; float qs[64][128]; } a;
        float os[128][65];
    } sm;

    const int tid = threadIdx.x;

    #pragma unroll
    for (int i = 0; i < 4; i++) {
        int f = tid + i * 256;
        reinterpret_cast<float4*>(&sm.a.cs[0][0])[f] = reinterpret_cast<const float4*>(cp)[f];
    }
    #pragma unroll
    for (int i = 0; i < 16; i++) {
        int f = tid + i * 256;
        int d = f >> 6, pr = f & 63;
        float2 q2 = unpack_bf16x2(qp[(size_t)d * (LL / 2) + n0 / 2 + pr]);
        sm.a.qs[d][2 * pr]     = q2.x;
        sm.a.qs[d][2 * pr + 1] = q2.y;
    }
    __syncthreads();

    const int ty = tid >> 5, tx = tid & 31;

    float acc[8][4];
    #pragma unroll
    for (int i = 0; i < 8; i++)
        #pragma unroll
        for (int j = 0; j < 4; j++) acc[i][j] = 0.f;

    #pragma unroll 8
    for (int d = 0; d < 64; d++) {
        float qf[4], cf[8];
        #pragma unroll
        for (int j = 0; j < 4; j++) qf[j] = sm.a.qs[d][tx * 4 + j];
        #pragma unroll
        for (int i = 0; i < 8; i++) cf[i] = sm.a.cs[d][ty * 8 + i];
        #pragma unroll
        for (int i = 0; i < 8; i++)
            #pragma unroll
            for (int j = 0; j < 4; j++)
                acc[i][j] = fmaf(cf[i], qf[j], acc[i][j]);
    }

    __syncthreads();

    #pragma unroll
    for (int i = 0; i < 8; i++)
        #pragma unroll
        for (int j = 0; j < 4; j++)
            sm.os[tx * 4 + j][ty * 8 + i] = acc[i][j];
    __syncthreads();

    #pragma unroll
    for (int i = 0; i < 16; i++) {
        int f = tid + i * 256;
        int r = f >> 5, cpx = f & 31;
        uint32_t u = pack_bf16x2(sm.os[r][cpx * 2], sm.os[r][cpx * 2 + 1]);
        attnT16[((size_t)b * LL + n0 + r) * (HID / 2) + h * (DH / 2) + cpx] = u;
    }
}

// ---------------- launch ------------------------------------------------------
extern "C" void kernel_launch(void* const* d_in, const int* in_sizes, int n_in,
                              void* d_out, int out_size)
{
    const float* x     = (const float*)d_in[0];
    const float* gamma = (const float*)d_in[1];
    const float* beta  = (const float*)d_in[2];
    const float* w_qkv = (const float*)d_in[3];
    const float* w_out = (const float*)d_in[4];
    const float* b_out = (const float*)d_in[5];
    float* out = (float*)d_out;

    float* ctx;
    float2 *stats, *lnst;
    uint32_t *xnT16, *qkv16, *attnT16, *wq16, *wo16;
    cudaGetSymbolAddress((void**)&xnT16,   g_xnT16);
    cudaGetSymbolAddress((void**)&qkv16,   g_qkv16);
    cudaGetSymbolAddress((void**)&stats,   g_stats);
    cudaGetSymbolAddress((void**)&lnst,    g_lnst);
    cudaGetSymbolAddress((void**)&ctx,     g_ctx);
    cudaGetSymbolAddress((void**)&attnT16, g_attnT16);
    cudaGetSymbolAddress((void**)&wq16,    g_wq16);
    cudaGetSymbolAddress((void**)&wo16,    g_wo16);

    cudaFuncSetAttribute((const void*)gemm_bf16_mma<false, true>,
                         cudaFuncAttributeMaxDynamicSharedMemorySize, GEMM_DYN_SMEM);
    cudaFuncSetAttribute((const void*)gemm_bf16_mma<true, false>,
                         cudaFuncAttributeMaxDynamicSharedMemorySize, GEMM_DYN_SMEM);
    cudaFuncSetAttribute((const void*)ln_fused_kernel,
                         cudaFuncAttributeMaxDynamicSharedMemorySize, LN_SMEM);

    const int CTX_N = BB * NH * DH * DH;

    pack_bf16_kernel<<<(3 * HID * CC / 2 + 255) / 256, 256>>>(w_qkv, wq16, 3 * HID * CC / 2);
    pack_bf16_kernel<<<(CC * HID / 2 + 255) / 256, 256>>>(w_out, wo16, CC * HID / 2);
    zero_ctx_kernel<<<CTX_N / 256, 256>>>(ctx);
    ln_fused_kernel<<<dim3(LL / 32, BB), 256, LN_SMEM>>>(x, gamma, beta, lnst, xnT16);

    // QKV GEMM (bf16 in, bf16 out)
    gemm_bf16_mma<false, true><<<dim3(LL / 256, (3 * HID) / 128, BB), 256, GEMM_DYN_SMEM>>>(
        (const __nv_bfloat16*)wq16, (const __nv_bfloat16*)xnT16, qkv16,
        (size_t)LL * CC, (size_t)3 * HID * LL, nullptr, nullptr, 0,
        nullptr, nullptr, nullptr);

    kstats_kernel<<<BB * HID, 256>>>(qkv16, stats);
    ctx_kernel<<<dim3(8, NH, BB), 256>>>(qkv16, stats, ctx);
    attn_out_kernel<<<dim3(LL / 128, NH, BB), 256>>>(qkv16, ctx, attnT16);

    // OUT GEMM (bf16 in, fp32 out + bias + recomputed-LN residual)
    gemm_bf16_mma<true, false><<<dim3(LL / 256, HID / 128, BB), 256, GEMM_DYN_SMEM>>>(
        (const __nv_bfloat16*)wo16, (const __nv_bfloat16*)attnT16, out,
        (size_t)LL * HID, (size_t)HID * LL, b_out, x, (size_t)CC * LL,
        lnst, gamma, beta);
}

// round 15
// speedup vs baseline: 4.9261x; 1.2987x over previous
#include <cuda_runtime.h>
#include <cuda_bf16.h>
#include <cstdint>
#include <cstddef>

// Problem constants
#define BB   8
#define CC   512
#define LL   4096
#define HID  512
#define NH   8
#define DH   64
#define EPSV 1e-5f
#define SCALEV 0.125f

// ---------------- scratch (device globals) ----------------------------------
__device__ uint32_t g_xnT16[(size_t)BB * LL * (CC/2)];      // 32 MB xn^T bf16 [L,C]
__device__ uint32_t g_kv16 [(size_t)BB * 2 * HID * (LL/2)]; // 64 MB k,v bf16
__device__ float2   g_stats[(size_t)BB * HID];              // k-row softmax stats
__device__ float2   g_lnst [(size_t)BB * LL];               // LN (mean, rstd)
__device__ float    g_ctx  [(size_t)BB * NH * DH * DH];     // 1 MB context
__device__ uint32_t g_PT16 [(size_t)BB * CC * (HID/2)];     // 4 MB P^T bf16 [b][c][hid]
__device__ uint32_t g_M16  [(size_t)BB * CC * (CC/2)];      // 4 MB Mfull bf16 [b][r][c]
__device__ uint32_t g_wq16 [(size_t)3 * HID * CC / 2];      // packed w_qkv
__device__ uint32_t g_wo16 [(size_t)CC * HID / 2];          // packed w_out

// ---------------- helpers ----------------------------------------------------
__device__ __forceinline__ uint32_t smem_u32(const void* p) {
    uint32_t a;
    asm("{ .reg .u64 t; cvta.to.shared.u64 t, %1; cvt.u32.u64 %0, t; }" : "=r"(a) : "l"(p));
    return a;
}
__device__ __forceinline__ uint32_t pack_bf16x2(float lo, float hi) {
    __nv_bfloat162 h = __floats2bfloat162_rn(lo, hi);
    return *reinterpret_cast<uint32_t*>(&h);
}
__device__ __forceinline__ float2 unpack_bf16x2(uint32_t u) {
    __nv_bfloat162 h = *reinterpret_cast<__nv_bfloat162*>(&u);
    return make_float2(__bfloat162float(h.x), __bfloat162float(h.y));
}
__device__ __forceinline__ void cp_async16(uint32_t saddr, const void* g) {
    asm volatile("cp.async.cg.shared.global [%0], [%1], 16;" :: "r"(saddr), "l"(g));
}
#define CP_COMMIT() asm volatile("cp.async.commit_group;" ::: "memory")
#define CP_WAIT(n)  asm volatile("cp.async.wait_group %0;" :: "n"(n) : "memory")

__device__ __forceinline__ void ldsm_x4(uint32_t& r0, uint32_t& r1, uint32_t& r2, uint32_t& r3,
                                        uint32_t addr)
{
    asm volatile("ldmatrix.sync.aligned.m8n8.x4.shared.b16 {%0,%1,%2,%3}, [%4];"
                 : "=r"(r0), "=r"(r1), "=r"(r2), "=r"(r3) : "r"(addr));
}

__device__ __forceinline__ void mma_bf16(float* c, const uint32_t* a, const uint32_t* b)
{
    asm volatile(
        "mma.sync.aligned.m16n8k16.row.col.f32.bf16.bf16.f32 "
        "{%0,%1,%2,%3}, {%4,%5,%6,%7}, {%8,%9}, {%0,%1,%2,%3};"
        : "+f"(c[0]), "+f"(c[1]), "+f"(c[2]), "+f"(c[3])
        : "r"(a[0]), "r"(a[1]), "r"(a[2]), "r"(a[3]), "r"(b[0]), "r"(b[1]));
}

// SW128 swizzle: 128B rows of eight 16B chunks; chunk XOR'd by row&7.
__device__ __forceinline__ uint32_t swz128(int r, int j) {
    return (uint32_t)(r * 128 + ((j ^ (r & 7)) << 4));
}

// ---------------- LayerNorm: stats + xnT[L,C] bf16 ---------------------------
#define LN_SMEM (512 * 33 * 4)
__global__ void __launch_bounds__(256)
ln_fused_kernel(const float* __restrict__ x,
                const float* __restrict__ gamma,
                const float* __restrict__ beta,
                float2* __restrict__ lnst, uint32_t* __restrict__ xnT16)
{
    extern __shared__ float s[];
    __shared__ float ps[8][32], pss[8][32];
    __shared__ float s_mean[32], s_rstd[32];

    const int tid = threadIdx.x, wid = tid >> 5, lane = tid & 31;
    const int l0 = blockIdx.x * 32, b = blockIdx.y;
    const float* xb = x + (size_t)b * CC * LL;

    #pragma unroll 8
    for (int it = 0; it < 64; it++) {
        int c = it * 8 + wid;
        s[c * 33 + lane] = xb[(size_t)c * LL + l0 + lane];
    }
    __syncthreads();

    {
        int l = lane, ch = wid;
        float sum = 0.f, ssum = 0.f;
        #pragma unroll 8
        for (int c = ch * 64; c < ch * 64 + 64; c++) {
            float v = s[c * 33 + l];
            sum += v; ssum += v * v;
        }
        ps[ch][l] = sum; pss[ch][l] = ssum;
    }
    __syncthreads();
    if (tid < 32) {
        float sum = 0.f, ssum = 0.f;
        #pragma unroll
        for (int ch = 0; ch < 8; ch++) { sum += ps[ch][tid]; ssum += pss[ch][tid]; }
        float mean = sum * (1.0f / CC);
        float var  = ssum * (1.0f / CC) - mean * mean;
        float rstd = rsqrtf(var + EPSV);
        s_mean[tid] = mean;
        s_rstd[tid] = rstd;
        lnst[(size_t)b * LL + l0 + tid] = make_float2(mean, rstd);
    }
    __syncthreads();

    uint32_t* xTb = xnT16 + (size_t)b * LL * (CC / 2);
    #pragma unroll 4
    for (int i = 0; i < 32; i++) {
        int f = tid + i * 256;
        int l = f >> 8, cp = f & 255;
        int c0 = cp * 2, c1 = c0 + 1;
        float mean = s_mean[l], rstd = s_rstd[l];
        float v0 = (s[c0 * 33 + l] - mean) * rstd * __ldg(&gamma[c0]) + __ldg(&beta[c0]);
        float v1 = (s[c1 * 33 + l] - mean) * rstd * __ldg(&gamma[c1]) + __ldg(&beta[c1]);
        xTb[(size_t)(l0 + l) * (CC / 2) + cp] = pack_bf16x2(v0, v1);
    }
}

// ---------------- pack weights to bf16 ---------------------------------------
__global__ void pack_bf16_kernel(const float* __restrict__ in, uint32_t* __restrict__ out, int n2)
{
    int i = blockIdx.x * 256 + threadIdx.x;
    if (i < n2) out[i] = pack_bf16x2(in[2 * i], in[2 * i + 1]);
}

// ---------------- bf16 GEMM: 128x256 tile, BK=64, 3-stage, 1 sync/tile -------
#define STG_BYTES 49152
#define A_BYTES   16384
#define GEMM_DYN_SMEM (3 * STG_BYTES)

template <bool EPI, bool OUT16>
__global__ void __launch_bounds__(256)
gemm_bf16_mma(const __nv_bfloat16* __restrict__ A, const __nv_bfloat16* __restrict__ Bmat,
              void* __restrict__ Cout,
              size_t strideAz, size_t strideBz, size_t strideCz, int ldc,
              const float* __restrict__ bias,
              const float* __restrict__ resx, size_t strideRz,
              const float2* __restrict__ lnst,
              const float* __restrict__ gamma, const float* __restrict__ beta)
{
    extern __shared__ uint32_t smem32[];

    const int tid = threadIdx.x;
    const int wid = tid >> 5, lane = tid & 31;
    const int g = lane >> 2, t4 = lane & 3;
    const int sel = lane >> 3, wi = lane & 7;
    const int warp_m = wid >> 2;
    const int warp_n = wid & 3;
    const int bx = blockIdx.x, by = blockIdx.y, bz = blockIdx.z;

    const __nv_bfloat16* Abase = A    + bz * strideAz + (size_t)by * 128 * 512;
    const __nv_bfloat16* Bbase = Bmat + bz * strideBz + (size_t)bx * 256 * 512;

    const uint32_t sAu = smem_u32(smem32);
    const int rmb = warp_m * 64;
    const int nbb = warp_n * 64;

    auto load_tile = [&](int t) {
        int stage = t % 3;
        uint32_t dA = sAu + (uint32_t)stage * STG_BYTES;
        uint32_t dB = dA + A_BYTES;
        int k0 = t * 64;
        #pragma unroll
        for (int i = 0; i < 4; i++) {
            int f = tid + i * 256;
            int r = f >> 3, j = f & 7;
            cp_async16(dA + swz128(r, j), Abase + (size_t)r * 512 + k0 + j * 8);
        }
        #pragma unroll
        for (int i = 0; i < 8; i++) {
            int f = tid + i * 256;
            int r = f >> 3, j = f & 7;
            cp_async16(dB + swz128(r, j), Bbase + (size_t)r * 512 + k0 + j * 8);
        }
        CP_COMMIT();
    };

    float acc[4][8][4];
    #pragma unroll
    for (int mf = 0; mf < 4; mf++)
        #pragma unroll
        for (int nf = 0; nf < 8; nf++)
            #pragma unroll
            for (int i = 0; i < 4; i++) acc[mf][nf][i] = 0.f;

    load_tile(0); load_tile(1);

    for (int t = 0; t < 8; t++) {
        CP_WAIT(1);
        __syncthreads();
        uint32_t stg = sAu + (uint32_t)(t % 3) * STG_BYTES;

        #pragma unroll
        for (int ks = 0; ks < 4; ks++) {
            uint32_t af[4][4], bf[8][2];
            #pragma unroll
            for (int mf = 0; mf < 4; mf++) {
                int r = rmb + mf * 16 + wi + (sel & 1) * 8;
                int j = ks * 2 + (sel >> 1);
                ldsm_x4(af[mf][0], af[mf][1], af[mf][2], af[mf][3], stg + swz128(r, j));
            }
            #pragma unroll
            for (int nf2 = 0; nf2 < 4; nf2++) {
                int r = nbb + nf2 * 16 + wi + (sel >> 1) * 8;
                int j = ks * 2 + (sel & 1);
                ldsm_x4(bf[nf2*2][0], bf[nf2*2][1], bf[nf2*2+1][0], bf[nf2*2+1][1],
                        stg + A_BYTES + swz128(r, j));
            }
            #pragma unroll
            for (int mf = 0; mf < 4; mf++)
                #pragma unroll
                for (int nf = 0; nf < 8; nf++)
                    mma_bf16(acc[mf][nf], af[mf], bf[nf]);
        }
        if (t + 2 < 8) load_tile(t + 2); else CP_COMMIT();
    }

    // epilogue
    #pragma unroll
    for (int mf = 0; mf < 4; mf++) {
        int row0 = by * 128 + rmb + mf * 16 + g;
        #pragma unroll
        for (int half = 0; half < 2; half++) {
            int row = row0 + half * 8;
            float bval = 0.f, ga = 0.f, be = 0.f;
            if (EPI) { bval = bias[row]; ga = gamma[row]; be = beta[row]; }
            #pragma unroll
            for (int nf = 0; nf < 8; nf++) {
                int cn = nbb + nf * 8 + 2 * t4;
                float vx = acc[mf][nf][half * 2 + 0];
                float vy = acc[mf][nf][half * 2 + 1];
                if (EPI) {
                    int lcol = bx * 256 + cn;
                    size_t roff = (size_t)bz * strideRz + (size_t)row * ldc + lcol;
                    float2 x2 = *reinterpret_cast<const float2*>(resx + roff);
                    float2 s0 = lnst[(size_t)bz * LL + lcol];
                    float2 s1 = lnst[(size_t)bz * LL + lcol + 1];
                    vx += bval + ((x2.x - s0.x) * s0.y * ga + be);
                    vy += bval + ((x2.y - s1.x) * s1.y * ga + be);
                }
                size_t coff = (size_t)bz * strideCz + (size_t)row * ldc + bx * 256 + cn;
                if (OUT16) {
                    ((uint32_t*)Cout)[coff >> 1] = pack_bf16x2(vx, vy);
                } else {
                    float2 v2 = make_float2(vx, vy);
                    *reinterpret_cast<float2*>((float*)Cout + coff) = v2;
                }
            }
        }
    }
}

// ---------------- k-row softmax stats: (max, 1/sumexp) -----------------------
__global__ void __launch_bounds__(256)
kstats_kernel(const uint32_t* __restrict__ kv16, float2* __restrict__ stats)
{
    int row = blockIdx.x;                // 0..BB*HID-1
    int b = row >> 9, r = row & 511;
    const uint32_t* p = kv16 + ((size_t)b * 2 * HID + r) * (LL / 2);

    const int tid = threadIdx.x;
    __shared__ float shp[8];
    __shared__ float bcast;

    float2 v[8];
    #pragma unroll
    for (int i = 0; i < 8; i++)
        v[i] = unpack_bf16x2(p[tid + i * 256]);

    float m = -3.4e38f;
    #pragma unroll
    for (int i = 0; i < 8; i++) m = fmaxf(m, fmaxf(v[i].x, v[i].y));
    #pragma unroll
    for (int o = 16; o; o >>= 1) m = fmaxf(m, __shfl_xor_sync(0xffffffffu, m, o));
    if ((tid & 31) == 0) shp[tid >> 5] = m;
    __syncthreads();
    if (tid < 32) {
        float t = (tid < 8) ? shp[tid] : -3.4e38f;
        #pragma unroll
        for (int o = 4; o; o >>= 1) t = fmaxf(t, __shfl_xor_sync(0xffffffffu, t, o));
        if (tid == 0) bcast = t;
    }
    __syncthreads();
    float M = bcast;
    __syncthreads();

    float s = 0.f;
    #pragma unroll
    for (int i = 0; i < 8; i++)
        s += __expf(v[i].x - M) + __expf(v[i].y - M);
    #pragma unroll
    for (int o = 16; o; o >>= 1) s += __shfl_xor_sync(0xffffffffu, s, o);
    if ((tid & 31) == 0) shp[tid >> 5] = s;
    __syncthreads();
    if (tid < 32) {
        float t = (tid < 8) ? shp[tid] : 0.f;
        #pragma unroll
        for (int o = 4; o; o >>= 1) t += __shfl_xor_sync(0xffffffffu, t, o);
        if (tid == 0) bcast = t;
    }
    __syncthreads();
    if (tid == 0) stats[row] = make_float2(M, 1.0f / bcast);
}

// ---------------- context = (SCALE * softmax(k)) @ v^T ----------------------
__global__ void zero_ctx_kernel(float* __restrict__ ctx)
{
    ctx[blockIdx.x * 256 + threadIdx.x] = 0.f;
}

__global__ void __launch_bounds__(256)
ctx_kernel(const uint32_t* __restrict__ kv16, const float2* __restrict__ stats,
           float* __restrict__ ctx)
{
    const int chunk = blockIdx.x;
    const int h = blockIdx.y, b = blockIdx.z;

    const uint32_t* kp = kv16 + ((size_t)b * 2 * HID + h * DH) * (LL / 2);
    const uint32_t* vp = kv16 + ((size_t)b * 2 * HID + HID + h * DH) * (LL / 2);

    __shared__ float ksT[64][65];
    __shared__ float vsT[64][65];
    __shared__ float2 sst[64];

    const int tid = threadIdx.x;
    const int ty = tid >> 4, tx = tid & 15;

    if (tid < 64) {
        float2 st = stats[(size_t)b * HID + h * DH + tid];
        st.y *= SCALEV;            // fold q-scale (exact pow2)
        sst[tid] = st;
    }
    __syncthreads();

    float acc[4][4];
    #pragma unroll
    for (int i = 0; i < 4; i++)
        #pragma unroll
        for (int j = 0; j < 4; j++) acc[i][j] = 0.f;

    for (int t = 0; t < 8; t++) {
        int np = (chunk * 512 + t * 64) / 2;
        #pragma unroll
        for (int i = 0; i < 8; i++) {
            int f = tid + i * 256;
            int d = f >> 5, pr = f & 31;
            float2 st = sst[d];
            float2 kk = unpack_bf16x2(kp[(size_t)d * (LL / 2) + np + pr]);
            float2 vv = unpack_bf16x2(vp[(size_t)d * (LL / 2) + np + pr]);
            ksT[2 * pr][d]     = __expf(kk.x - st.x) * st.y;
            ksT[2 * pr + 1][d] = __expf(kk.y - st.x) * st.y;
            vsT[2 * pr][d]     = vv.x;
            vsT[2 * pr + 1][d] = vv.y;
        }
        __syncthreads();
        #pragma unroll 8
        for (int n = 0; n < 64; n++) {
            float af[4], bf[4];
            #pragma unroll
            for (int i = 0; i < 4; i++) af[i] = ksT[n][ty * 4 + i];
            #pragma unroll
            for (int j = 0; j < 4; j++) bf[j] = vsT[n][tx * 4 + j];
            #pragma unroll
            for (int i = 0; i < 4; i++)
                #pragma unroll
                for (int j = 0; j < 4; j++)
                    acc[i][j] = fmaf(af[i], bf[j], acc[i][j]);
        }
        __syncthreads();
    }

    float* cbase = ctx + ((size_t)(b * NH + h)) * DH * DH;
    #pragma unroll
    for (int i = 0; i < 4; i++)
        #pragma unroll
        for (int j = 0; j < 4; j++)
            atomicAdd(&cbase[(size_t)(ty * 4 + i) * DH + tx * 4 + j], acc[i][j]);
}

// ---------------- PT[b][c][hid] = sum_d ctx[b,h,d,e] * Wq[h*64+d, c] ---------
// grid (8 c-tiles, NH, BB), 256 threads. Output bf16-packed pairs over e.
__global__ void __launch_bounds__(256)
ptq_kernel(const float* __restrict__ ctx, const float* __restrict__ w_qkv,
           uint32_t* __restrict__ PT16)
{
    const int ct = blockIdx.x, h = blockIdx.y, b = blockIdx.z;
    const float* cp = ctx + ((size_t)(b * NH + h)) * DH * DH;   // ctx[d][e]
    const float* wq = w_qkv + (size_t)(h * DH) * CC;            // rows h*64+d

    __shared__ float ctxs[64][64];     // [d][e]
    __shared__ float wqs[64][65];      // [d][cc]

    const int tid = threadIdx.x;

    #pragma unroll
    for (int i = 0; i < 16; i++) {
        int f = tid + i * 256;         // 0..4095
        ctxs[f >> 6][f & 63] = cp[f];
        int d = f >> 6, cc = f & 63;
        wqs[d][cc] = wq[(size_t)d * CC + ct * 64 + cc];
    }
    __syncthreads();

    // each thread: 8 (cc, ep) pairs; idx = cc + 64*ep
    #pragma unroll
    for (int i = 0; i < 8; i++) {
        int idx = tid + i * 256;       // 0..2047
        int cc = idx & 63, ep = idx >> 6;   // ep 0..31
        float s0 = 0.f, s1 = 0.f;
        #pragma unroll 8
        for (int d = 0; d < 64; d++) {
            float w = wqs[d][cc];
            s0 = fmaf(ctxs[d][2 * ep],     w, s0);
            s1 = fmaf(ctxs[d][2 * ep + 1], w, s1);
        }
        int c = ct * 64 + cc;
        PT16[((size_t)b * CC + c) * (HID / 2) + h * (DH / 2) + ep] = pack_bf16x2(s0, s1);
    }
}

// ---------------- launch ------------------------------------------------------
extern "C" void kernel_launch(void* const* d_in, const int* in_sizes, int n_in,
                              void* d_out, int out_size)
{
    const float* x     = (const float*)d_in[0];
    const float* gamma = (const float*)d_in[1];
    const float* beta  = (const float*)d_in[2];
    const float* w_qkv = (const float*)d_in[3];
    const float* w_out = (const float*)d_in[4];
    const float* b_out = (const float*)d_in[5];
    float* out = (float*)d_out;

    float* ctx;
    float2 *stats, *lnst;
    uint32_t *xnT16, *kv16, *PT16, *M16, *wq16, *wo16;
    cudaGetSymbolAddress((void**)&xnT16, g_xnT16);
    cudaGetSymbolAddress((void**)&kv16,  g_kv16);
    cudaGetSymbolAddress((void**)&stats, g_stats);
    cudaGetSymbolAddress((void**)&lnst,  g_lnst);
    cudaGetSymbolAddress((void**)&ctx,   g_ctx);
    cudaGetSymbolAddress((void**)&PT16,  g_PT16);
    cudaGetSymbolAddress((void**)&M16,   g_M16);
    cudaGetSymbolAddress((void**)&wq16,  g_wq16);
    cudaGetSymbolAddress((void**)&wo16,  g_wo16);

    cudaFuncSetAttribute((const void*)gemm_bf16_mma<false, true>,
                         cudaFuncAttributeMaxDynamicSharedMemorySize, GEMM_DYN_SMEM);
    cudaFuncSetAttribute((const void*)gemm_bf16_mma<true, false>,
                         cudaFuncAttributeMaxDynamicSharedMemorySize, GEMM_DYN_SMEM);
    cudaFuncSetAttribute((const void*)ln_fused_kernel,
                         cudaFuncAttributeMaxDynamicSharedMemorySize, LN_SMEM);

    const int CTX_N = BB * NH * DH * DH;

    pack_bf16_kernel<<<(3 * HID * CC / 2 + 255) / 256, 256>>>(w_qkv, wq16, 3 * HID * CC / 2);
    pack_bf16_kernel<<<(CC * HID / 2 + 255) / 256, 256>>>(w_out, wo16, CC * HID / 2);
    zero_ctx_kernel<<<CTX_N / 256, 256>>>(ctx);
    ln_fused_kernel<<<dim3(LL / 32, BB), 256, LN_SMEM>>>(x, gamma, beta, lnst, xnT16);

    // KV GEMM: rows 512..1535 of w_qkv (k and v only) -> kv16 [b][2*512][L] bf16
    gemm_bf16_mma<false, true><<<dim3(LL / 256, (2 * HID) / 128, BB), 256, GEMM_DYN_SMEM>>>(
        (const __nv_bfloat16*)wq16 + (size_t)HID * CC, (const __nv_bfloat16*)xnT16, kv16,
        0, (size_t)LL * CC, (size_t)2 * HID * LL, LL,
        nullptr, nullptr, 0, nullptr, nullptr, nullptr);

    kstats_kernel<<<BB * HID, 256>>>(kv16, stats);
    ctx_kernel<<<dim3(8, NH, BB), 256>>>(kv16, stats, ctx);

    // P^T build (fp32 math, bf16 output)
    ptq_kernel<<<dim3(8, NH, BB), 256>>>(ctx, w_qkv, PT16);

    // Mfull[b] = w_out @ P[b]  (bf16 mma; A=wo16 shared, B=PT16[b], C=M16[b])
    gemm_bf16_mma<false, true><<<dim3(CC / 256, CC / 128, BB), 256, GEMM_DYN_SMEM>>>(
        (const __nv_bfloat16*)wo16, (const __nv_bfloat16*)PT16, M16,
        0, (size_t)CC * HID, (size_t)CC * CC, CC,
        nullptr, nullptr, 0, nullptr, nullptr, nullptr);

    // OUT GEMM: out[b] = Mfull[b] @ xn[b] + b_out + xn (exact fp32 residual)
    gemm_bf16_mma<true, false><<<dim3(LL / 256, HID / 128, BB), 256, GEMM_DYN_SMEM>>>(
        (const __nv_bfloat16*)M16, (const __nv_bfloat16*)xnT16, out,
        (size_t)CC * CC, (size_t)LL * CC, (size_t)HID * LL, LL,
        b_out, x, (size_t)CC * LL, lnst, gamma, beta);
}

// round 16
// speedup vs baseline: 6.1285x; 1.2441x over previous
#include <cuda_runtime.h>
#include <cuda_bf16.h>
#include <cstdint>
#include <cstddef>

// Problem constants
#define BB   8
#define CC   512
#define LL   4096
#define HID  512
#define NH   8
#define DH   64
#define EPSV 1e-5f
#define SCALEV 0.125f

// ---------------- scratch (device globals) ----------------------------------
__device__ uint32_t g_xnT16[(size_t)BB * LL * (CC/2)];      // 32 MB xn^T bf16 [L,C]
__device__ uint32_t g_kv16 [(size_t)BB * 2 * HID * (LL/2)]; // 64 MB k,v bf16
__device__ float2   g_stats[(size_t)BB * HID];              // k-row softmax stats
__device__ float2   g_lnst [(size_t)BB * LL];               // LN (mean, rstd)
__device__ float    g_ctx  [(size_t)BB * NH * DH * DH];     // 1 MB context
__device__ uint32_t g_PT16 [(size_t)BB * CC * (HID/2)];     // 4 MB P^T bf16
__device__ uint32_t g_M16  [(size_t)BB * CC * (CC/2)];      // 4 MB Mfull bf16
__device__ uint32_t g_wq16 [(size_t)3 * HID * CC / 2];
__device__ uint32_t g_wo16 [(size_t)CC * HID / 2];

// ---------------- helpers ----------------------------------------------------
__device__ __forceinline__ uint32_t smem_u32(const void* p) {
    uint32_t a;
    asm("{ .reg .u64 t; cvta.to.shared.u64 t, %1; cvt.u32.u64 %0, t; }" : "=r"(a) : "l"(p));
    return a;
}
__device__ __forceinline__ uint32_t pack_bf16x2(float lo, float hi) {
    __nv_bfloat162 h = __floats2bfloat162_rn(lo, hi);
    return *reinterpret_cast<uint32_t*>(&h);
}
__device__ __forceinline__ float2 unpack_bf16x2(uint32_t u) {
    __nv_bfloat162 h = *reinterpret_cast<__nv_bfloat162*>(&u);
    return make_float2(__bfloat162float(h.x), __bfloat162float(h.y));
}
__device__ __forceinline__ void cp_async16(uint32_t saddr, const void* g) {
    asm volatile("cp.async.cg.shared.global [%0], [%1], 16;" :: "r"(saddr), "l"(g));
}
#define CP_COMMIT() asm volatile("cp.async.commit_group;" ::: "memory")
#define CP_WAIT(n)  asm volatile("cp.async.wait_group %0;" :: "n"(n) : "memory")

__device__ __forceinline__ void ldsm_x4(uint32_t& r0, uint32_t& r1, uint32_t& r2, uint32_t& r3,
                                        uint32_t addr)
{
    asm volatile("ldmatrix.sync.aligned.m8n8.x4.shared.b16 {%0,%1,%2,%3}, [%4];"
                 : "=r"(r0), "=r"(r1), "=r"(r2), "=r"(r3) : "r"(addr));
}

__device__ __forceinline__ void mma_bf16(float* c, const uint32_t* a, const uint32_t* b)
{
    asm volatile(
        "mma.sync.aligned.m16n8k16.row.col.f32.bf16.bf16.f32 "
        "{%0,%1,%2,%3}, {%4,%5,%6,%7}, {%8,%9}, {%0,%1,%2,%3};"
        : "+f"(c[0]), "+f"(c[1]), "+f"(c[2]), "+f"(c[3])
        : "r"(a[0]), "r"(a[1]), "r"(a[2]), "r"(a[3]), "r"(b[0]), "r"(b[1]));
}

// SW128 swizzle: 128B rows of eight 16B chunks; chunk XOR'd by row&7.
__device__ __forceinline__ uint32_t swz128(int r, int j) {
    return (uint32_t)(r * 128 + ((j ^ (r & 7)) << 4));
}

// ---------------- LayerNorm: stats + xnT[L,C] bf16 (inline stats) ------------
#define LN_SMEM (512 * 33 * 4)
__global__ void __launch_bounds__(256)
ln_fused_kernel(const float* __restrict__ x,
                const float* __restrict__ gamma,
                const float* __restrict__ beta,
                float2* __restrict__ lnst, uint32_t* __restrict__ xnT16)
{
    extern __shared__ float s[];
    __shared__ float ps[8][32], pss[8][32];
    __shared__ float s_mean[32], s_rstd[32];

    const int tid = threadIdx.x, wid = tid >> 5, lane = tid & 31;
    const int l0 = blockIdx.x * 32, b = blockIdx.y;
    const float* xb = x + (size_t)b * CC * LL;

    // load 512x32 tile AND accumulate per-(wid,lane) partial sums inline:
    // thread covers exactly channels c = it*8+wid (c mod 8 == wid) at l = lane.
    float sum = 0.f, ssum = 0.f;
    #pragma unroll 8
    for (int it = 0; it < 64; it++) {
        int c = it * 8 + wid;
        float v = xb[(size_t)c * LL + l0 + lane];
        s[c * 33 + lane] = v;
        sum += v; ssum += v * v;
    }
    ps[wid][lane] = sum; pss[wid][lane] = ssum;
    __syncthreads();

    if (tid < 32) {
        float su = 0.f, ss2 = 0.f;
        #pragma unroll
        for (int ch = 0; ch < 8; ch++) { su += ps[ch][tid]; ss2 += pss[ch][tid]; }
        float mean = su * (1.0f / CC);
        float var  = ss2 * (1.0f / CC) - mean * mean;
        float rstd = rsqrtf(var + EPSV);
        s_mean[tid] = mean;
        s_rstd[tid] = rstd;
        lnst[(size_t)b * LL + l0 + tid] = make_float2(mean, rstd);
    }
    __syncthreads();

    uint32_t* xTb = xnT16 + (size_t)b * LL * (CC / 2);
    #pragma unroll 4
    for (int i = 0; i < 32; i++) {
        int f = tid + i * 256;
        int l = f >> 8, cp = f & 255;
        int c0 = cp * 2, c1 = c0 + 1;
        float mean = s_mean[l], rstd = s_rstd[l];
        float v0 = (s[c0 * 33 + l] - mean) * rstd * __ldg(&gamma[c0]) + __ldg(&beta[c0]);
        float v1 = (s[c1 * 33 + l] - mean) * rstd * __ldg(&gamma[c1]) + __ldg(&beta[c1]);
        xTb[(size_t)(l0 + l) * (CC / 2) + cp] = pack_bf16x2(v0, v1);
    }
}

// ---------------- pack weights to bf16 ---------------------------------------
__global__ void pack_bf16_kernel(const float* __restrict__ in, uint32_t* __restrict__ out, int n2)
{
    int i = blockIdx.x * 256 + threadIdx.x;
    if (i < n2) out[i] = pack_bf16x2(in[2 * i], in[2 * i + 1]);
}

// ---------------- bf16 GEMM: 128x256 tile, BK=64, 3-stage, 1 sync/tile -------
#define STG_BYTES 49152
#define A_BYTES   16384
#define GEMM_DYN_SMEM (3 * STG_BYTES)

template <bool EPI, bool OUT16>
__global__ void __launch_bounds__(256)
gemm_bf16_mma(const __nv_bfloat16* __restrict__ A, const __nv_bfloat16* __restrict__ Bmat,
              void* __restrict__ Cout,
              size_t strideAz, size_t strideBz, size_t strideCz, int ldc,
              const float* __restrict__ bias,
              const float* __restrict__ resx, size_t strideRz,
              const float2* __restrict__ lnst,
              const float* __restrict__ gamma, const float* __restrict__ beta)
{
    extern __shared__ uint32_t smem32[];

    const int tid = threadIdx.x;
    const int wid = tid >> 5, lane = tid & 31;
    const int g = lane >> 2, t4 = lane & 3;
    const int sel = lane >> 3, wi = lane & 7;
    const int warp_m = wid >> 2;
    const int warp_n = wid & 3;
    const int bx = blockIdx.x, by = blockIdx.y, bz = blockIdx.z;

    const __nv_bfloat16* Abase = A    + bz * strideAz + (size_t)by * 128 * 512;
    const __nv_bfloat16* Bbase = Bmat + bz * strideBz + (size_t)bx * 256 * 512;

    const uint32_t sAu = smem_u32(smem32);
    const int rmb = warp_m * 64;
    const int nbb = warp_n * 64;

    auto load_tile = [&](int t) {
        int stage = t % 3;
        uint32_t dA = sAu + (uint32_t)stage * STG_BYTES;
        uint32_t dB = dA + A_BYTES;
        int k0 = t * 64;
        #pragma unroll
        for (int i = 0; i < 4; i++) {
            int f = tid + i * 256;
            int r = f >> 3, j = f & 7;
            cp_async16(dA + swz128(r, j), Abase + (size_t)r * 512 + k0 + j * 8);
        }
        #pragma unroll
        for (int i = 0; i < 8; i++) {
            int f = tid + i * 256;
            int r = f >> 3, j = f & 7;
            cp_async16(dB + swz128(r, j), Bbase + (size_t)r * 512 + k0 + j * 8);
        }
        CP_COMMIT();
    };

    float acc[4][8][4];
    #pragma unroll
    for (int mf = 0; mf < 4; mf++)
        #pragma unroll
        for (int nf = 0; nf < 8; nf++)
            #pragma unroll
            for (int i = 0; i < 4; i++) acc[mf][nf][i] = 0.f;

    load_tile(0); load_tile(1);

    for (int t = 0; t < 8; t++) {
        CP_WAIT(1);
        __syncthreads();
        uint32_t stg = sAu + (uint32_t)(t % 3) * STG_BYTES;

        #pragma unroll
        for (int ks = 0; ks < 4; ks++) {
            uint32_t af[4][4], bf[8][2];
            #pragma unroll
            for (int mf = 0; mf < 4; mf++) {
                int r = rmb + mf * 16 + wi + (sel & 1) * 8;
                int j = ks * 2 + (sel >> 1);
                ldsm_x4(af[mf][0], af[mf][1], af[mf][2], af[mf][3], stg + swz128(r, j));
            }
            #pragma unroll
            for (int nf2 = 0; nf2 < 4; nf2++) {
                int r = nbb + nf2 * 16 + wi + (sel >> 1) * 8;
                int j = ks * 2 + (sel & 1);
                ldsm_x4(bf[nf2*2][0], bf[nf2*2][1], bf[nf2*2+1][0], bf[nf2*2+1][1],
                        stg + A_BYTES + swz128(r, j));
            }
            #pragma unroll
            for (int mf = 0; mf < 4; mf++)
                #pragma unroll
                for (int nf = 0; nf < 8; nf++)
                    mma_bf16(acc[mf][nf], af[mf], bf[nf]);
        }
        if (t + 2 < 8) load_tile(t + 2); else CP_COMMIT();
    }

    // epilogue
    #pragma unroll
    for (int mf = 0; mf < 4; mf++) {
        int row0 = by * 128 + rmb + mf * 16 + g;
        #pragma unroll
        for (int half = 0; half < 2; half++) {
            int row = row0 + half * 8;
            float bval = 0.f, ga = 0.f, be = 0.f;
            if (EPI) { bval = bias[row]; ga = gamma[row]; be = beta[row]; }
            #pragma unroll
            for (int nf = 0; nf < 8; nf++) {
                int cn = nbb + nf * 8 + 2 * t4;
                float vx = acc[mf][nf][half * 2 + 0];
                float vy = acc[mf][nf][half * 2 + 1];
                if (EPI) {
                    int lcol = bx * 256 + cn;
                    size_t roff = (size_t)bz * strideRz + (size_t)row * ldc + lcol;
                    float2 x2 = *reinterpret_cast<const float2*>(resx + roff);
                    float2 s0 = lnst[(size_t)bz * LL + lcol];
                    float2 s1 = lnst[(size_t)bz * LL + lcol + 1];
                    vx += bval + ((x2.x - s0.x) * s0.y * ga + be);
                    vy += bval + ((x2.y - s1.x) * s1.y * ga + be);
                }
                size_t coff = (size_t)bz * strideCz + (size_t)row * ldc + bx * 256 + cn;
                if (OUT16) {
                    ((uint32_t*)Cout)[coff >> 1] = pack_bf16x2(vx, vy);
                } else {
                    float2 v2 = make_float2(vx, vy);
                    *reinterpret_cast<float2*>((float*)Cout + coff) = v2;
                }
            }
        }
    }
}

// ---------------- k-row softmax stats: (max, 1/sumexp) -----------------------
__global__ void __launch_bounds__(256)
kstats_kernel(const uint32_t* __restrict__ kv16, float2* __restrict__ stats)
{
    int row = blockIdx.x;
    int b = row >> 9, r = row & 511;
    const uint32_t* p = kv16 + ((size_t)b * 2 * HID + r) * (LL / 2);

    const int tid = threadIdx.x;
    __shared__ float shp[8];
    __shared__ float bcast;

    float2 v[8];
    #pragma unroll
    for (int i = 0; i < 8; i++)
        v[i] = unpack_bf16x2(p[tid + i * 256]);

    float m = -3.4e38f;
    #pragma unroll
    for (int i = 0; i < 8; i++) m = fmaxf(m, fmaxf(v[i].x, v[i].y));
    #pragma unroll
    for (int o = 16; o; o >>= 1) m = fmaxf(m, __shfl_xor_sync(0xffffffffu, m, o));
    if ((tid & 31) == 0) shp[tid >> 5] = m;
    __syncthreads();
    if (tid < 32) {
        float t = (tid < 8) ? shp[tid] : -3.4e38f;
        #pragma unroll
        for (int o = 4; o; o >>= 1) t = fmaxf(t, __shfl_xor_sync(0xffffffffu, t, o));
        if (tid == 0) bcast = t;
    }
    __syncthreads();
    float M = bcast;
    __syncthreads();

    float s = 0.f;
    #pragma unroll
    for (int i = 0; i < 8; i++)
        s += __expf(v[i].x - M) + __expf(v[i].y - M);
    #pragma unroll
    for (int o = 16; o; o >>= 1) s += __shfl_xor_sync(0xffffffffu, s, o);
    if ((tid & 31) == 0) shp[tid >> 5] = s;
    __syncthreads();
    if (tid < 32) {
        float t = (tid < 8) ? shp[tid] : 0.f;
        #pragma unroll
        for (int o = 4; o; o >>= 1) t += __shfl_xor_sync(0xffffffffu, t, o);
        if (tid == 0) bcast = t;
    }
    __syncthreads();
    if (tid == 0) stats[row] = make_float2(M, 1.0f / bcast);
}

// ---------------- context via bf16 mma ---------------------------------------
// ctx[b,h] (64x64) += khat[d,n] @ v[e,n]^T over n-chunk of 512.
// khat = exp(k - M_d) * invsum_d * SCALE, computed in-place in smem.
// Double-buffered 64x64 bf16 tiles (8 KB each operand per stage).
#define CTXK_BYTES 8192
#define CTX_STG    (2 * CTXK_BYTES)      // K + V per stage

__global__ void zero_ctx_kernel(float* __restrict__ ctx)
{
    ctx[blockIdx.x * 256 + threadIdx.x] = 0.f;
}

__global__ void __launch_bounds__(256)
ctx_kernel(const uint32_t* __restrict__ kv16, const float2* __restrict__ stats,
           float* __restrict__ ctx)
{
    __shared__ __align__(16) uint8_t smem_raw[2 * CTX_STG];
    __shared__ float2 sst[64];

    const int chunk = blockIdx.x;
    const int h = blockIdx.y, b = blockIdx.z;

    const uint32_t* kp = kv16 + ((size_t)b * 2 * HID + h * DH) * (LL / 2);
    const uint32_t* vp = kv16 + ((size_t)b * 2 * HID + HID + h * DH) * (LL / 2);

    const int tid = threadIdx.x;
    const int wid = tid >> 5, lane = tid & 31;
    const int g = lane >> 2, t4 = lane & 3;
    const int sel = lane >> 3, wi = lane & 7;
    const int warp_m = wid >> 2;        // 0..1 (32 d-rows each)
    const int warp_n = wid & 3;         // 0..3 (16 e-cols each)

    const uint32_t sm = smem_u32(smem_raw);

    if (tid < 64) {
        float2 st = stats[(size_t)b * HID + h * DH + tid];
        st.y *= SCALEV;                 // fold q-scale (exact pow2)
        sst[tid] = st;
    }

    auto load_tile = [&](int t) {
        int stage = t & 1;
        uint32_t dK = sm + (uint32_t)stage * CTX_STG;
        uint32_t dV = dK + CTXK_BYTES;
        int np = (chunk * 512 + t * 64) / 2;   // u32 offset
        #pragma unroll
        for (int i = 0; i < 2; i++) {          // 512 chunks each operand
            int f = tid + i * 256;
            int r = f >> 3, j = f & 7;
            cp_async16(dK + swz128(r, j), kp + (size_t)r * (LL / 2) + np + j * 4);
            cp_async16(dV + swz128(r, j), vp + (size_t)r * (LL / 2) + np + j * 4);
        }
        CP_COMMIT();
    };

    float acc[2][2][4];
    #pragma unroll
    for (int mf = 0; mf < 2; mf++)
        #pragma unroll
        for (int nf = 0; nf < 2; nf++)
            #pragma unroll
            for (int i = 0; i < 4; i++) acc[mf][nf][i] = 0.f;

    load_tile(0); load_tile(1);

    for (int t = 0; t < 8; t++) {
        CP_WAIT(1);
        __syncthreads();
        uint32_t stg = sm + (uint32_t)(t & 1) * CTX_STG;

        // exp-rewrite K tile in place (physical u32 f -> row d = f>>5)
        {
            uint32_t* kk = (uint32_t*)(smem_raw + (t & 1) * CTX_STG);
            #pragma unroll
            for (int i = 0; i < 8; i++) {
                int f = tid + i * 256;          // 0..2047
                float2 st = sst[f >> 5];
                float2 kvv = unpack_bf16x2(kk[f]);
                kk[f] = pack_bf16x2(__expf(kvv.x - st.x) * st.y,
                                    __expf(kvv.y - st.x) * st.y);
            }
        }
        __syncthreads();

        #pragma unroll
        for (int ks = 0; ks < 4; ks++) {
            uint32_t af[2][4], bf[2][2];
            #pragma unroll
            for (int mf = 0; mf < 2; mf++) {
                int r = warp_m * 32 + mf * 16 + wi + (sel & 1) * 8;
                int j = ks * 2 + (sel >> 1);
                ldsm_x4(af[mf][0], af[mf][1], af[mf][2], af[mf][3], stg + swz128(r, j));
            }
            {
                int r = warp_n * 16 + wi + (sel >> 1) * 8;
                int j = ks * 2 + (sel & 1);
                ldsm_x4(bf[0][0], bf[0][1], bf[1][0], bf[1][1],
                        stg + CTXK_BYTES + swz128(r, j));
            }
            #pragma unroll
            for (int mf = 0; mf < 2; mf++)
                #pragma unroll
                for (int nf = 0; nf < 2; nf++)
                    mma_bf16(acc[mf][nf], af[mf], bf[nf]);
        }
        __syncthreads();                // all warps done with stage before reuse
        if (t + 2 < 8) load_tile(t + 2); else CP_COMMIT();
    }

    float* cbase = ctx + ((size_t)(b * NH + h)) * DH * DH;
    #pragma unroll
    for (int mf = 0; mf < 2; mf++)
        #pragma unroll
        for (int nf = 0; nf < 2; nf++)
            #pragma unroll
            for (int half = 0; half < 2; half++) {
                int d = warp_m * 32 + mf * 16 + g + half * 8;
                int e = warp_n * 16 + nf * 8 + 2 * t4;
                atomicAdd(&cbase[(size_t)d * DH + e],     acc[mf][nf][half * 2 + 0]);
                atomicAdd(&cbase[(size_t)d * DH + e + 1], acc[mf][nf][half * 2 + 1]);
            }
}

// ---------------- PT[b][c][hid] = sum_d ctx[b,h,d,e] * Wq[h*64+d, c] ---------
__global__ void __launch_bounds__(256)
ptq_kernel(const float* __restrict__ ctx, const float* __restrict__ w_qkv,
           uint32_t* __restrict__ PT16)
{
    const int ct = blockIdx.x, h = blockIdx.y, b = blockIdx.z;
    const float* cp = ctx + ((size_t)(b * NH + h)) * DH * DH;
    const float* wq = w_qkv + (size_t)(h * DH) * CC;

    __shared__ float ctxs[64][64];
    __shared__ float wqs[64][65];

    const int tid = threadIdx.x;

    #pragma unroll
    for (int i = 0; i < 16; i++) {
        int f = tid + i * 256;
        ctxs[f >> 6][f & 63] = cp[f];
        int d = f >> 6, cc = f & 63;
        wqs[d][cc] = wq[(size_t)d * CC + ct * 64 + cc];
    }
    __syncthreads();

    #pragma unroll
    for (int i = 0; i < 8; i++) {
        int idx = tid + i * 256;
        int cc = idx & 63, ep = idx >> 6;
        float s0 = 0.f, s1 = 0.f;
        #pragma unroll 8
        for (int d = 0; d < 64; d++) {
            float w = wqs[d][cc];
            s0 = fmaf(ctxs[d][2 * ep],     w, s0);
            s1 = fmaf(ctxs[d][2 * ep + 1], w, s1);
        }
        int c = ct * 64 + cc;
        PT16[((size_t)b * CC + c) * (HID / 2) + h * (DH / 2) + ep] = pack_bf16x2(s0, s1);
    }
}

// ---------------- launch ------------------------------------------------------
extern "C" void kernel_launch(void* const* d_in, const int* in_sizes, int n_in,
                              void* d_out, int out_size)
{
    const float* x     = (const float*)d_in[0];
    const float* gamma = (const float*)d_in[1];
    const float* beta  = (const float*)d_in[2];
    const float* w_qkv = (const float*)d_in[3];
    const float* w_out = (const float*)d_in[4];
    const float* b_out = (const float*)d_in[5];
    float* out = (float*)d_out;

    float* ctx;
    float2 *stats, *lnst;
    uint32_t *xnT16, *kv16, *PT16, *M16, *wq16, *wo16;
    cudaGetSymbolAddress((void**)&xnT16, g_xnT16);
    cudaGetSymbolAddress((void**)&kv16,  g_kv16);
    cudaGetSymbolAddress((void**)&stats, g_stats);
    cudaGetSymbolAddress((void**)&lnst,  g_lnst);
    cudaGetSymbolAddress((void**)&ctx,   g_ctx);
    cudaGetSymbolAddress((void**)&PT16,  g_PT16);
    cudaGetSymbolAddress((void**)&M16,   g_M16);
    cudaGetSymbolAddress((void**)&wq16,  g_wq16);
    cudaGetSymbolAddress((void**)&wo16,  g_wo16);

    cudaFuncSetAttribute((const void*)gemm_bf16_mma<false, true>,
                         cudaFuncAttributeMaxDynamicSharedMemorySize, GEMM_DYN_SMEM);
    cudaFuncSetAttribute((const void*)gemm_bf16_mma<true, false>,
                         cudaFuncAttributeMaxDynamicSharedMemorySize, GEMM_DYN_SMEM);
    cudaFuncSetAttribute((const void*)ln_fused_kernel,
                         cudaFuncAttributeMaxDynamicSharedMemorySize, LN_SMEM);

    const int CTX_N = BB * NH * DH * DH;

    pack_bf16_kernel<<<(3 * HID * CC / 2 + 255) / 256, 256>>>(w_qkv, wq16, 3 * HID * CC / 2);
    pack_bf16_kernel<<<(CC * HID / 2 + 255) / 256, 256>>>(w_out, wo16, CC * HID / 2);
    zero_ctx_kernel<<<CTX_N / 256, 256>>>(ctx);
    ln_fused_kernel<<<dim3(LL / 32, BB), 256, LN_SMEM>>>(x, gamma, beta, lnst, xnT16);

    // KV GEMM: rows 512..1535 of w_qkv -> kv16 bf16
    gemm_bf16_mma<false, true><<<dim3(LL / 256, (2 * HID) / 128, BB), 256, GEMM_DYN_SMEM>>>(
        (const __nv_bfloat16*)wq16 + (size_t)HID * CC, (const __nv_bfloat16*)xnT16, kv16,
        0, (size_t)LL * CC, (size_t)2 * HID * LL, LL,
        nullptr, nullptr, 0, nullptr, nullptr, nullptr);

    kstats_kernel<<<BB * HID, 256>>>(kv16, stats);
    ctx_kernel<<<dim3(8, NH, BB), 256>>>(kv16, stats, ctx);

    // P^T build
    ptq_kernel<<<dim3(8, NH, BB), 256>>>(ctx, w_qkv, PT16);

    // Mfull[b] = w_out @ P[b]
    gemm_bf16_mma<false, true><<<dim3(CC / 256, CC / 128, BB), 256, GEMM_DYN_SMEM>>>(
        (const __nv_bfloat16*)wo16, (const __nv_bfloat16*)PT16, M16,
        0, (size_t)CC * HID, (size_t)CC * CC, CC,
        nullptr, nullptr, 0, nullptr, nullptr, nullptr);

    // OUT GEMM: out[b] = Mfull[b] @ xn[b] + b_out + xn (exact fp32 residual)
    gemm_bf16_mma<true, false><<<dim3(LL / 256, HID / 128, BB), 256, GEMM_DYN_SMEM>>>(
        (const __nv_bfloat16*)M16, (const __nv_bfloat16*)xnT16, out,
        (size_t)CC * CC, (size_t)LL * CC, (size_t)HID * LL, LL,
        b_out, x, (size_t)CC * LL, lnst, gamma, beta);
}